// round 1
// baseline (speedup 1.0000x reference)
#include <cuda_runtime.h>

// ---------------- problem constants ----------------
#define Bn 2
#define Sn 2048
#define Dn 1024
#define Vn 32000
#define NHEADS 8
#define DHn 128
#define DFFn 4096
#define Rn (Bn*Sn)   // 4096 total rows

// ---------------- scratch (device globals; bss is zero-initialized) ----------
__device__ float g_Xc[Rn*Dn];        // gathered thought rows (compacted per batch)
__device__ float g_qkv[Rn*3*Dn];
__device__ float g_ctx[Rn*Dn];
__device__ float g_attno[Rn*Dn];
__device__ float g_x1[Rn*Dn];
__device__ float g_hff[Rn*DFFn];
__device__ float g_ff[Rn*Dn];
__device__ float g_x2[Rn*Dn];
__device__ float g_cat[Rn*2*Dn];     // [x | thought_enc]
__device__ float g_mctx[Rn*Dn];
__device__ float g_mixed[Rn*Dn];
__device__ float g_eff[Rn];
__device__ int   g_tidx[Rn];         // per-batch compacted index lists
__device__ int   g_tcnt[Bn];

// ---------------- mask + compaction (1 warp per batch, segmented scan) -------
__global__ void mask_kernel(const int* __restrict__ ids,
                            const int* __restrict__ sotp,
                            const int* __restrict__ eotp)
{
    int b = blockIdx.x;
    int lane = threadIdx.x;
    int sot = *sotp, eot = *eotp;
    const int* row = ids + b * Sn;
    int base = lane * 64;

    // segment aggregate of state machine s' = iso | (s & ~ieo), as (a, bb): s_out = a | (s_in & bb)
    unsigned a = 0u, bb = 1u, anyeot = 0u;
    for (int i = 0; i < 64; ++i) {
        int t = row[base + i];
        unsigned iso = (t == sot) ? 1u : 0u;
        unsigned ieo = (t == eot) ? 1u : 0u;
        a = iso | (a & (1u - ieo));
        bb = bb & (1u - ieo);
        anyeot |= ieo;
    }
    // inclusive scan of (a,bb) composition across lanes
    unsigned ai = a, bi = bb;
    for (int off = 1; off < 32; off <<= 1) {
        unsigned ap = __shfl_up_sync(0xffffffffu, ai, off);
        unsigned bp = __shfl_up_sync(0xffffffffu, bi, off);
        if (lane >= off) { ai = ai | (ap & bi); bi = bi & bp; }
    }
    unsigned s_in = __shfl_up_sync(0xffffffffu, ai, 1);
    if (lane == 0) s_in = 0u;

    // exclusive suffix-OR of anyeot (eot strictly after my segment)
    unsigned sfx = anyeot;
    for (int off = 1; off < 32; off <<= 1) {
        unsigned v = __shfl_down_sync(0xffffffffu, sfx, off);
        if (lane + off < 32) sfx |= v;
    }
    unsigned after = __shfl_down_sync(0xffffffffu, sfx, 1);
    if (lane == 31) after = 0u;

    // forward replay: open bits
    unsigned long long openbits = 0ull;
    unsigned s = s_in;
    for (int i = 0; i < 64; ++i) {
        int t = row[base + i];
        unsigned iso = (t == sot) ? 1u : 0u;
        unsigned ieo = (t == eot) ? 1u : 0u;
        unsigned o = iso | s;
        openbits |= ((unsigned long long)o) << i;
        s = iso | (s & (1u - ieo));
    }
    // backward: closed (eot at pos >= t, inclusive), tmask = open & closed
    unsigned long long tbits = 0ull;
    unsigned seen = after;
    for (int i = 63; i >= 0; --i) {
        int t = row[base + i];
        if (t == eot) seen = 1u;
        if (((openbits >> i) & 1ull) && seen) tbits |= (1ull << i);
    }
    // compaction: exclusive prefix of popcounts
    int c = __popcll(tbits);
    int pre = c;
    for (int off = 1; off < 32; off <<= 1) {
        int v = __shfl_up_sync(0xffffffffu, pre, off);
        if (lane >= off) pre += v;
    }
    int excl = pre - c;
    int total = __shfl_sync(0xffffffffu, pre, 31);
    if (lane == 31) g_tcnt[b] = total;
    int o = excl;
    for (int i = 0; i < 64; ++i) {
        if ((tbits >> i) & 1ull) g_tidx[b * Sn + (o++)] = base + i;
    }
}

// ---------------- gather thought rows ----------------------------------------
__global__ void gather_kernel(const float* __restrict__ x)
{
    int b = blockIdx.y, i = blockIdx.x;
    if (i >= g_tcnt[b]) return;
    int src = b * Sn + g_tidx[b * Sn + i];
    const float4* s4 = (const float4*)(x + (size_t)src * Dn);
    float4* d4 = (float4*)(g_Xc + (size_t)(b * Sn + i) * Dn);
    d4[threadIdx.x] = s4[threadIdx.x];
}

// ---------------- generic GEMM:  C = A @ W^T + bias  (A: MxK, W: NxK) --------
// 128x128 tile, BK=8, 256 threads, 8x8 microtile. Optional compacted-row exit.
template<bool RELU>
__global__ void __launch_bounds__(256) gemm_tn(
    const float* __restrict__ A, const float* __restrict__ W,
    const float* __restrict__ bias, float* __restrict__ C,
    int N, int K, int use_cnt)
{
    int r0 = blockIdx.y * 128;
    int c0 = blockIdx.x * 128;
    if (use_cnt) {
        int b = r0 >> 11;                       // 2048 rows per batch
        if ((r0 & 2047) >= g_tcnt[b]) return;   // whole tile beyond valid rows
    }
    __shared__ float As[8][132];
    __shared__ float Ws[8][132];
    int tid = threadIdx.x;
    int lrow = tid >> 1;
    int lk = (tid & 1) << 2;
    int tx = tid & 15, ty = tid >> 4;
    const float* Ap = A + (size_t)(r0 + lrow) * K + lk;
    const float* Wp = W + (size_t)(c0 + lrow) * K + lk;

    float acc[8][8];
#pragma unroll
    for (int i = 0; i < 8; ++i)
#pragma unroll
        for (int j = 0; j < 8; ++j) acc[i][j] = 0.f;

    for (int k0 = 0; k0 < K; k0 += 8) {
        float4 av = *(const float4*)(Ap + k0);
        float4 wv = *(const float4*)(Wp + k0);
        __syncthreads();
        As[lk+0][lrow] = av.x; As[lk+1][lrow] = av.y;
        As[lk+2][lrow] = av.z; As[lk+3][lrow] = av.w;
        Ws[lk+0][lrow] = wv.x; Ws[lk+1][lrow] = wv.y;
        Ws[lk+2][lrow] = wv.z; Ws[lk+3][lrow] = wv.w;
        __syncthreads();
#pragma unroll
        for (int kk = 0; kk < 8; ++kk) {
            float a[8], bl[8];
            *(float4*)(a)   = *(const float4*)(&As[kk][ty*8]);
            *(float4*)(a+4) = *(const float4*)(&As[kk][ty*8+4]);
            *(float4*)(bl)  = *(const float4*)(&Ws[kk][tx*8]);
            *(float4*)(bl+4)= *(const float4*)(&Ws[kk][tx*8+4]);
#pragma unroll
            for (int i = 0; i < 8; ++i)
#pragma unroll
                for (int j = 0; j < 8; ++j)
                    acc[i][j] += a[i] * bl[j];
        }
    }

    float4 b0 = *(const float4*)(bias + c0 + tx*8);
    float4 b4 = *(const float4*)(bias + c0 + tx*8 + 4);
#pragma unroll
    for (int i = 0; i < 8; ++i) {
        size_t r = (size_t)(r0 + ty*8 + i);
        float* Cr = C + r * (size_t)N + c0 + tx*8;
        float4 o0, o1;
        o0.x = acc[i][0] + b0.x; o0.y = acc[i][1] + b0.y;
        o0.z = acc[i][2] + b0.z; o0.w = acc[i][3] + b0.w;
        o1.x = acc[i][4] + b4.x; o1.y = acc[i][5] + b4.y;
        o1.z = acc[i][6] + b4.z; o1.w = acc[i][7] + b4.w;
        if (RELU) {
            o0.x = fmaxf(o0.x, 0.f); o0.y = fmaxf(o0.y, 0.f);
            o0.z = fmaxf(o0.z, 0.f); o0.w = fmaxf(o0.w, 0.f);
            o1.x = fmaxf(o1.x, 0.f); o1.y = fmaxf(o1.y, 0.f);
            o1.z = fmaxf(o1.z, 0.f); o1.w = fmaxf(o1.w, 0.f);
        }
        *(float4*)(Cr)     = o0;
        *(float4*)(Cr + 4) = o1;
    }
}

// ---------------- attention over compacted thought rows ----------------------
// One warp per query, 8 queries per block, online softmax over key tiles of 32.
__global__ void __launch_bounds__(256) attn_kernel()
{
    int b = blockIdx.z, h = blockIdx.y, qt = blockIdx.x;
    int nT = g_tcnt[b];
    if (qt * 8 >= nT) return;

    __shared__ float Ks[128][33];   // transposed: Ks[d][j]
    __shared__ float Vs[32][128];
    __shared__ float Qs[8][128];

    int tid = threadIdx.x, warp = tid >> 5, lane = tid & 31;
    int q = qt * 8 + warp;
    bool qv = q < nT;
    if (qv) {
        const float* qr = g_qkv + (size_t)(b*Sn + q) * (3*Dn) + h * DHn;
#pragma unroll
        for (int c = 0; c < 4; ++c) Qs[warp][lane + 32*c] = qr[lane + 32*c];
    }

    float m = -1e30f, lsum = 0.f;
    float acc[4] = {0.f, 0.f, 0.f, 0.f};
    const float scale = 0.088388347648318447f;  // 1/sqrt(128)

    for (int j0 = 0; j0 < nT; j0 += 32) {
        int jn = min(32, nT - j0);
        __syncthreads();
        for (int idx = tid; idx < 32*128; idx += 256) {
            int j = idx >> 7, d = idx & 127;
            float kv = 0.f, vv = 0.f;
            if (j < jn) {
                const float* kr = g_qkv + (size_t)(b*Sn + j0 + j)*(3*Dn) + Dn + h*DHn;
                kv = kr[d];
                vv = kr[Dn + d];   // v at +Dn from k
            }
            Ks[d][j] = kv;
            Vs[j][d] = vv;
        }
        __syncthreads();
        if (qv) {
            float s = 0.f;
#pragma unroll 8
            for (int d = 0; d < 128; ++d) s += Qs[warp][d] * Ks[d][lane];
            s *= scale;
            if (lane >= jn) s = -1e30f;
            float smax = s;
#pragma unroll
            for (int off = 16; off; off >>= 1)
                smax = fmaxf(smax, __shfl_xor_sync(0xffffffffu, smax, off));
            float mnew = fmaxf(m, smax);
            float p = (lane < jn) ? __expf(s - mnew) : 0.f;
            float ps = p;
#pragma unroll
            for (int off = 16; off; off >>= 1)
                ps += __shfl_xor_sync(0xffffffffu, ps, off);
            float corr = __expf(m - mnew);
            lsum = lsum * corr + ps;
#pragma unroll
            for (int c = 0; c < 4; ++c) acc[c] *= corr;
            for (int j = 0; j < jn; ++j) {
                float pj = __shfl_sync(0xffffffffu, p, j);
#pragma unroll
                for (int c = 0; c < 4; ++c) acc[c] += pj * Vs[j][lane + 32*c];
            }
            m = mnew;
        }
    }
    if (qv) {
        float inv = 1.f / lsum;
        float* outr = g_ctx + (size_t)(b*Sn + q)*Dn + h*DHn;
#pragma unroll
        for (int c = 0; c < 4; ++c) outr[lane + 32*c] = acc[c] * inv;
    }
}

// ---------------- block reduction helper --------------------------------------
__device__ __forceinline__ float block_sum256(float v, float* red)
{
    int lane = threadIdx.x & 31, warp = threadIdx.x >> 5;
#pragma unroll
    for (int off = 16; off; off >>= 1) v += __shfl_xor_sync(0xffffffffu, v, off);
    if (lane == 0) red[warp] = v;
    __syncthreads();
    if (warp == 0) {
        float t = (lane < 8) ? red[lane] : 0.f;
#pragma unroll
        for (int off = 4; off; off >>= 1) t += __shfl_xor_sync(0xffffffffu, t, off);
        if (lane == 0) red[0] = t;
    }
    __syncthreads();
    float r = red[0];
    __syncthreads();
    return r;
}

// ---------------- fused residual-add + LayerNorm ------------------------------
__global__ void __launch_bounds__(256) add_ln_kernel(
    const float* __restrict__ X, const float* __restrict__ Y,
    const float* __restrict__ g, const float* __restrict__ be,
    float* __restrict__ out, int use_cnt)
{
    int r = blockIdx.x;
    if (use_cnt) { int b = r >> 11; if ((r & 2047) >= g_tcnt[b]) return; }
    __shared__ float red[8];
    int t = threadIdx.x;
    float4 xv = ((const float4*)(X + (size_t)r * Dn))[t];
    float4 yv = ((const float4*)(Y + (size_t)r * Dn))[t];
    float v0 = xv.x + yv.x, v1 = xv.y + yv.y, v2 = xv.z + yv.z, v3 = xv.w + yv.w;
    float mu = block_sum256(v0 + v1 + v2 + v3, red) * (1.0f / Dn);
    float d0 = v0 - mu, d1 = v1 - mu, d2 = v2 - mu, d3 = v3 - mu;
    float var = block_sum256(d0*d0 + d1*d1 + d2*d2 + d3*d3, red) * (1.0f / Dn);
    float inv = rsqrtf(var + 1e-5f);
    float4 gv = ((const float4*)g)[t];
    float4 bv = ((const float4*)be)[t];
    float4 o;
    o.x = d0 * inv * gv.x + bv.x;
    o.y = d1 * inv * gv.y + bv.y;
    o.z = d2 * inv * gv.z + bv.z;
    o.w = d3 * inv * gv.w + bv.w;
    ((float4*)(out + (size_t)r * Dn))[t] = o;
}

// ---------------- cat init: cat = [x | x], eff = 0.1 ---------------------------
__global__ void init_cat_kernel(const float* __restrict__ x)
{
    int r = blockIdx.x, t = threadIdx.x;
    float4 v = ((const float4*)(x + (size_t)r * Dn))[t];
    float4* c4 = (float4*)(g_cat + (size_t)r * 2 * Dn);
    c4[t] = v;
    c4[t + Dn/4] = v;
    if (t == 0) g_eff[r] = 0.1f;
}

// ---------------- scatter x2 into cat[:, D:] + gate ----------------------------
__global__ void __launch_bounds__(256) scatter_kernel(
    const float* __restrict__ Wg, const float* __restrict__ bg)
{
    int b = blockIdx.y, i = blockIdx.x;
    if (i >= g_tcnt[b]) return;
    __shared__ float red[8];
    int dst = b * Sn + g_tidx[b * Sn + i];
    int t = threadIdx.x;
    float4 v = ((const float4*)(g_x2 + (size_t)(b*Sn + i) * Dn))[t];
    ((float4*)(g_cat + (size_t)dst * 2 * Dn + Dn))[t] = v;
    float4 w = ((const float4*)Wg)[t];
    float p = v.x*w.x + v.y*w.y + v.z*w.z + v.w*w.w;
    float tot = block_sum256(p, red);
    if (t == 0) g_eff[dst] = 1.f / (1.f + __expf(-(tot + bg[0])));
}

// ---------------- mix: mixed = (1-eff)*x + eff*mixed_ctx -----------------------
__global__ void mix_kernel(const float* __restrict__ x)
{
    int r = blockIdx.x, t = threadIdx.x;
    float e = g_eff[r];
    float4 xv = ((const float4*)(x + (size_t)r * Dn))[t];
    float4 mc = ((const float4*)(g_mctx + (size_t)r * Dn))[t];
    float4 o;
    o.x = (1.f - e) * xv.x + e * mc.x;
    o.y = (1.f - e) * xv.y + e * mc.y;
    o.z = (1.f - e) * xv.z + e * mc.z;
    o.w = (1.f - e) * xv.w + e * mc.w;
    ((float4*)(g_mixed + (size_t)r * Dn))[t] = o;
}

// ---------------- launch ------------------------------------------------------
extern "C" void kernel_launch(void* const* d_in, const int* in_sizes, int n_in,
                              void* d_out, int out_size)
{
    const float* x    = (const float*)d_in[0];
    const int*   ids  = (const int*)d_in[1];
    const int*   sot  = (const int*)d_in[2];
    const int*   eot  = (const int*)d_in[3];
    const float* Wqkv = (const float*)d_in[4];
    const float* bqkv = (const float*)d_in[5];
    const float* Wo   = (const float*)d_in[6];
    const float* bo   = (const float*)d_in[7];
    const float* ln1g = (const float*)d_in[8];
    const float* ln1b = (const float*)d_in[9];
    const float* W1   = (const float*)d_in[10];
    const float* b1   = (const float*)d_in[11];
    const float* W2   = (const float*)d_in[12];
    const float* b2   = (const float*)d_in[13];
    const float* ln2g = (const float*)d_in[14];
    const float* ln2b = (const float*)d_in[15];
    const float* Wg   = (const float*)d_in[16];
    const float* bg   = (const float*)d_in[17];
    const float* Wm   = (const float*)d_in[18];
    const float* bm   = (const float*)d_in[19];
    const float* Wout = (const float*)d_in[20];
    const float* bout = (const float*)d_in[21];
    float* out = (float*)d_out;

    float *pXc, *pqkv, *pctx, *pattno, *px1, *phff, *pff, *px2, *pcat, *pmctx, *pmixed;
    cudaGetSymbolAddress((void**)&pXc, g_Xc);
    cudaGetSymbolAddress((void**)&pqkv, g_qkv);
    cudaGetSymbolAddress((void**)&pctx, g_ctx);
    cudaGetSymbolAddress((void**)&pattno, g_attno);
    cudaGetSymbolAddress((void**)&px1, g_x1);
    cudaGetSymbolAddress((void**)&phff, g_hff);
    cudaGetSymbolAddress((void**)&pff, g_ff);
    cudaGetSymbolAddress((void**)&px2, g_x2);
    cudaGetSymbolAddress((void**)&pcat, g_cat);
    cudaGetSymbolAddress((void**)&pmctx, g_mctx);
    cudaGetSymbolAddress((void**)&pmixed, g_mixed);

    // 1. thought mask + compaction
    mask_kernel<<<Bn, 32>>>(ids, sot, eot);
    // 2. gather thought rows
    gather_kernel<<<dim3(Sn, Bn), 256>>>(x);
    // 3. QKV on compacted rows
    gemm_tn<false><<<dim3(3*Dn/128, Rn/128), 256>>>(pXc, Wqkv, bqkv, pqkv, 3*Dn, Dn, 1);
    // 4. masked attention == dense attention over compacted keys
    attn_kernel<<<dim3(Sn/8, NHEADS, Bn), 256>>>();
    // 5. output projection of attention
    gemm_tn<false><<<dim3(Dn/128, Rn/128), 256>>>(pctx, Wo, bo, pattno, Dn, Dn, 1);
    // 6. LN1(x + attn)
    add_ln_kernel<<<Rn, 256>>>(pXc, pattno, ln1g, ln1b, px1, 1);
    // 7. FFN up + relu
    gemm_tn<true><<<dim3(DFFn/128, Rn/128), 256>>>(px1, W1, b1, phff, DFFn, Dn, 1);
    // 8. FFN down
    gemm_tn<false><<<dim3(Dn/128, Rn/128), 256>>>(phff, W2, b2, pff, Dn, DFFn, 1);
    // 9. LN2(x1 + ff)
    add_ln_kernel<<<Rn, 256>>>(px1, pff, ln2g, ln2b, px2, 1);
    // 10. cat = [x | x], eff = 0.1 everywhere
    init_cat_kernel<<<Rn, 256>>>(x);
    // 11. scatter x2 into cat[:, D:], gate -> eff at thought rows
    scatter_kernel<<<dim3(Sn, Bn), 256>>>(Wg, bg);
    // 12. mixed_ctx = cat @ Wm^T + bm (dense)
    gemm_tn<false><<<dim3(Dn/128, Rn/128), 256>>>(pcat, Wm, bm, pmctx, Dn, 2*Dn, 0);
    // 13. mixed = (1-eff)x + eff*mixed_ctx
    mix_kernel<<<Rn, 256>>>(x);
    // 14. logits = mixed @ Wout^T + bout (dense, dominant)
    gemm_tn<false><<<dim3(Vn/128, Rn/128), 256>>>(pmixed, Wout, bout, out, Vn, Dn, 0);

    (void)in_sizes; (void)n_in; (void)out_size;
}

// round 3
// speedup vs baseline: 2.4053x; 2.4053x over previous
#include <cuda_runtime.h>
#include <cuda_bf16.h>
#include <cstdint>

// ---------------- problem constants ----------------
#define Bn 2
#define Sn 2048
#define Dn 1024
#define Vn 32000
#define NHEADS 8
#define DHn 128
#define DFFn 4096
#define Rn (Bn*Sn)   // 4096 total rows

// ---------------- fp32 scratch ----------------
__device__ float g_Xc[Rn*Dn];
__device__ float g_qkv[Rn*3*Dn];
__device__ float g_attno[Rn*Dn];
__device__ float g_x1[Rn*Dn];
__device__ float g_ff[Rn*Dn];
__device__ float g_x2[Rn*Dn];
__device__ float g_mctx[Rn*Dn];
__device__ float g_eff[Rn];
__device__ int   g_tidx[Rn];
__device__ int   g_tcnt[Bn];

// ---------------- bf16 hi/lo planes (16B-aligned for cp.async/uint2) ---------
__device__ __align__(16) __nv_bfloat16 g_Xc_h[Rn*Dn],  g_Xc_l[Rn*Dn];
__device__ __align__(16) __nv_bfloat16 g_ctx_h[Rn*Dn], g_ctx_l[Rn*Dn];
__device__ __align__(16) __nv_bfloat16 g_x1_h[Rn*Dn],  g_x1_l[Rn*Dn];
__device__ __align__(16) __nv_bfloat16 g_hff_h[Rn*DFFn], g_hff_l[Rn*DFFn];
__device__ __align__(16) __nv_bfloat16 g_cat_h[Rn*2*Dn], g_cat_l[Rn*2*Dn];
__device__ __align__(16) __nv_bfloat16 g_mix_h[Rn*Dn], g_mix_l[Rn*Dn];
__device__ __align__(16) __nv_bfloat16 g_Wqkv_h[3*Dn*Dn], g_Wqkv_l[3*Dn*Dn];
__device__ __align__(16) __nv_bfloat16 g_Wo_h[Dn*Dn],   g_Wo_l[Dn*Dn];
__device__ __align__(16) __nv_bfloat16 g_W1_h[DFFn*Dn], g_W1_l[DFFn*Dn];
__device__ __align__(16) __nv_bfloat16 g_W2_h[Dn*DFFn], g_W2_l[Dn*DFFn];
__device__ __align__(16) __nv_bfloat16 g_Wm_h[Dn*2*Dn], g_Wm_l[Dn*2*Dn];
__device__ __align__(16) __nv_bfloat16 g_Wout_h[Vn*Dn], g_Wout_l[Vn*Dn];

// ---------------- helpers -------------------------------------------------------
__device__ __forceinline__ uint32_t smem_u32(const void* p) {
    uint32_t a;
    asm("{ .reg .u64 t; cvta.to.shared.u64 t, %1; cvt.u32.u64 %0, t; }" : "=r"(a) : "l"(p));
    return a;
}
__device__ __forceinline__ uint32_t pk2(__nv_bfloat16 a, __nv_bfloat16 b) {
    return ((uint32_t)__bfloat16_as_ushort(b) << 16) | (uint32_t)__bfloat16_as_ushort(a);
}
__device__ __forceinline__ void split4(float4 v, uint2& h, uint2& l) {
    __nv_bfloat16 hx = __float2bfloat16(v.x);
    __nv_bfloat16 hy = __float2bfloat16(v.y);
    __nv_bfloat16 hz = __float2bfloat16(v.z);
    __nv_bfloat16 hw = __float2bfloat16(v.w);
    h.x = pk2(hx, hy); h.y = pk2(hz, hw);
    l.x = pk2(__float2bfloat16(v.x - __bfloat162float(hx)),
              __float2bfloat16(v.y - __bfloat162float(hy)));
    l.y = pk2(__float2bfloat16(v.z - __bfloat162float(hz)),
              __float2bfloat16(v.w - __bfloat162float(hw)));
}
__device__ __forceinline__ void cpa16(uint32_t dst, const void* src) {
    asm volatile("cp.async.cg.shared.global [%0], [%1], 16;" :: "r"(dst), "l"(src));
}
__device__ __forceinline__ void cp_commit() {
    asm volatile("cp.async.commit_group;" ::: "memory");
}
template<int N>
__device__ __forceinline__ void cp_wait() {
    asm volatile("cp.async.wait_group %0;" :: "n"(N) : "memory");
}
__device__ __forceinline__ void ldm4(uint32_t addr, uint32_t* r) {
    asm volatile("ldmatrix.sync.aligned.m8n8.x4.shared.b16 {%0,%1,%2,%3}, [%4];"
                 : "=r"(r[0]), "=r"(r[1]), "=r"(r[2]), "=r"(r[3]) : "r"(addr));
}
__device__ __forceinline__ void mma_bf(float* d, const uint32_t* a, const uint32_t* b) {
    asm volatile("mma.sync.aligned.m16n8k16.row.col.f32.bf16.bf16.f32 "
                 "{%0,%1,%2,%3}, {%4,%5,%6,%7}, {%8,%9}, {%0,%1,%2,%3};"
                 : "+f"(d[0]), "+f"(d[1]), "+f"(d[2]), "+f"(d[3])
                 : "r"(a[0]), "r"(a[1]), "r"(a[2]), "r"(a[3]), "r"(b[0]), "r"(b[1]));
}

// ---------------- split kernel (fp32 -> bf16 hi/lo) ------------------------------
__global__ void split_kernel(const float4* __restrict__ in,
                             uint2* __restrict__ hi, uint2* __restrict__ lo, int n4)
{
    for (int i = blockIdx.x * 256 + threadIdx.x; i < n4; i += gridDim.x * 256) {
        uint2 h, l;
        split4(in[i], h, l);
        hi[i] = h; lo[i] = l;
    }
}

// ---------------- bf16-split GEMM: C = A @ W^T + bias ----------------------------
// A = Ah+Al [M,K], W = Wh+Wl [N,K]. BM=128,BN=128,BK=32. 256 thr, 8 warps (4x2).
#define TILEB 10240          // 128 rows * 80B padded stride
#define BUFB  (4*TILEB)      // Ah | Al | Wh | Wl
#define GSMEM (2*BUFB)       // 81920

template<bool RELU, bool SPLITOUT>
__global__ void __launch_bounds__(256, 1)
gemm_bs(const __nv_bfloat16* __restrict__ Ah, const __nv_bfloat16* __restrict__ Al,
        const __nv_bfloat16* __restrict__ Wh, const __nv_bfloat16* __restrict__ Wl,
        const float* __restrict__ bias, float* __restrict__ C,
        __nv_bfloat16* __restrict__ Ch, __nv_bfloat16* __restrict__ Cl,
        int N, int K, int use_cnt)
{
    int bid = blockIdx.x;
    int m0 = (bid & 31) << 7;
    int n0 = (bid >> 5) << 7;
    if (use_cnt) {
        int b = m0 >> 11;
        if ((m0 & 2047) >= g_tcnt[b]) return;
    }

    extern __shared__ char smraw[];
    uint32_t sb = smem_u32(smraw);
    int tid = threadIdx.x, lane = tid & 31, wid = tid >> 5;
    int mw = (wid & 3) << 5;   // warp m-origin in tile
    int nw = (wid >> 2) << 6;  // warp n-origin in tile

    // cp.async slots: 8 per thread (4 tiles x 2 rows)
    int lr = tid >> 2, seg = tid & 3;
    const __nv_bfloat16* src[8];
    uint32_t dsto[8];
    src[0] = Ah + (size_t)(m0 + lr) * K + seg * 8;        dsto[0] = 0*TILEB + lr*80 + seg*16;
    src[1] = Ah + (size_t)(m0 + lr + 64) * K + seg * 8;   dsto[1] = 0*TILEB + (lr+64)*80 + seg*16;
    src[2] = Al + (size_t)(m0 + lr) * K + seg * 8;        dsto[2] = 1*TILEB + lr*80 + seg*16;
    src[3] = Al + (size_t)(m0 + lr + 64) * K + seg * 8;   dsto[3] = 1*TILEB + (lr+64)*80 + seg*16;
    src[4] = Wh + (size_t)(n0 + lr) * K + seg * 8;        dsto[4] = 2*TILEB + lr*80 + seg*16;
    src[5] = Wh + (size_t)(n0 + lr + 64) * K + seg * 8;   dsto[5] = 2*TILEB + (lr+64)*80 + seg*16;
    src[6] = Wl + (size_t)(n0 + lr) * K + seg * 8;        dsto[6] = 3*TILEB + lr*80 + seg*16;
    src[7] = Wl + (size_t)(n0 + lr + 64) * K + seg * 8;   dsto[7] = 3*TILEB + (lr+64)*80 + seg*16;

    // ldmatrix per-lane offsets
    int am = lane >> 3;
    int arow = ((am & 1) << 3) | (lane & 7);
    int akc = am >> 1;
    uint32_t offA[2][2];
    #pragma unroll
    for (int mt = 0; mt < 2; ++mt)
        #pragma unroll
        for (int ks = 0; ks < 2; ++ks)
            offA[mt][ks] = (uint32_t)((mw + mt*16 + arow) * 80 + (ks*2 + akc) * 16);
    int brow = ((am >> 1) << 3) | (lane & 7);
    int bkc = am & 1;
    uint32_t offB[4][2];
    #pragma unroll
    for (int jp = 0; jp < 4; ++jp)
        #pragma unroll
        for (int ks = 0; ks < 2; ++ks)
            offB[jp][ks] = (uint32_t)((nw + jp*16 + brow) * 80 + (ks*2 + bkc) * 16);

    float acc[2][8][4];
    #pragma unroll
    for (int mt = 0; mt < 2; ++mt)
        #pragma unroll
        for (int nt = 0; nt < 8; ++nt)
            #pragma unroll
            for (int i = 0; i < 4; ++i) acc[mt][nt][i] = 0.f;

    int NC = K >> 5;

    // prefetch chunk 0
    #pragma unroll
    for (int j = 0; j < 8; ++j) cpa16(sb + dsto[j], src[j]);
    cp_commit();

    for (int c = 0; c < NC; ++c) {
        uint32_t cb = sb + (uint32_t)(c & 1) * BUFB;
        if (c + 1 < NC) {
            uint32_t nb = sb + (uint32_t)((c + 1) & 1) * BUFB;
            const int ko = (c + 1) * 32;
            #pragma unroll
            for (int j = 0; j < 8; ++j) cpa16(nb + dsto[j], src[j] + ko);
            cp_commit();
            cp_wait<1>();
        } else {
            cp_wait<0>();
        }
        __syncthreads();

        #pragma unroll
        for (int ks = 0; ks < 2; ++ks) {
            uint32_t ah[2][4], al_[2][4], wh[4][4], wl[4][4];
            ldm4(cb + offA[0][ks], ah[0]);
            ldm4(cb + offA[1][ks], ah[1]);
            ldm4(cb + TILEB + offA[0][ks], al_[0]);
            ldm4(cb + TILEB + offA[1][ks], al_[1]);
            #pragma unroll
            for (int jp = 0; jp < 4; ++jp) {
                ldm4(cb + 2*TILEB + offB[jp][ks], wh[jp]);
                ldm4(cb + 3*TILEB + offB[jp][ks], wl[jp]);
            }
            #pragma unroll
            for (int mt = 0; mt < 2; ++mt)
                #pragma unroll
                for (int nt = 0; nt < 8; ++nt) {
                    const uint32_t* bh = &wh[nt >> 1][(nt & 1) * 2];
                    const uint32_t* bl = &wl[nt >> 1][(nt & 1) * 2];
                    mma_bf(acc[mt][nt], ah[mt], bh);
                    mma_bf(acc[mt][nt], al_[mt], bh);
                    mma_bf(acc[mt][nt], ah[mt], bl);
                }
        }
        __syncthreads();
    }

    // epilogue: direct stores (quad of 4 threads covers 32B contiguous)
    #pragma unroll
    for (int mt = 0; mt < 2; ++mt)
        #pragma unroll
        for (int nt = 0; nt < 8; ++nt) {
            float* a = acc[mt][nt];
            int col = n0 + nw + nt * 8 + (lane & 3) * 2;
            int r0  = m0 + mw + mt * 16 + (lane >> 2);
            float2 bv = *(const float2*)(bias + col);
            float x0 = a[0] + bv.x, y0 = a[1] + bv.y;
            float x1 = a[2] + bv.x, y1 = a[3] + bv.y;
            if (RELU) {
                x0 = fmaxf(x0, 0.f); y0 = fmaxf(y0, 0.f);
                x1 = fmaxf(x1, 0.f); y1 = fmaxf(y1, 0.f);
            }
            if (!SPLITOUT) {
                float2 v0 = {x0, y0}, v1 = {x1, y1};
                *(float2*)(C + (size_t)r0 * N + col) = v0;
                *(float2*)(C + (size_t)(r0 + 8) * N + col) = v1;
            } else {
                __nv_bfloat16 h0 = __float2bfloat16(x0), h1 = __float2bfloat16(y0);
                __nv_bfloat16 h2 = __float2bfloat16(x1), h3 = __float2bfloat16(y1);
                *(uint32_t*)(Ch + (size_t)r0 * N + col) = pk2(h0, h1);
                *(uint32_t*)(Ch + (size_t)(r0 + 8) * N + col) = pk2(h2, h3);
                *(uint32_t*)(Cl + (size_t)r0 * N + col) =
                    pk2(__float2bfloat16(x0 - __bfloat162float(h0)),
                        __float2bfloat16(y0 - __bfloat162float(h1)));
                *(uint32_t*)(Cl + (size_t)(r0 + 8) * N + col) =
                    pk2(__float2bfloat16(x1 - __bfloat162float(h2)),
                        __float2bfloat16(y1 - __bfloat162float(h3)));
            }
        }
}

// ---------------- mask + compaction (1 warp per batch) ---------------------------
__global__ void mask_kernel(const int* __restrict__ ids,
                            const int* __restrict__ sotp,
                            const int* __restrict__ eotp)
{
    int b = blockIdx.x;
    int lane = threadIdx.x;
    int sot = *sotp, eot = *eotp;
    const int* row = ids + b * Sn;
    int base = lane * 64;

    unsigned a = 0u, bb = 1u, anyeot = 0u;
    for (int i = 0; i < 64; ++i) {
        int t = row[base + i];
        unsigned iso = (t == sot) ? 1u : 0u;
        unsigned ieo = (t == eot) ? 1u : 0u;
        a = iso | (a & (1u - ieo));
        bb = bb & (1u - ieo);
        anyeot |= ieo;
    }
    unsigned ai = a, bi = bb;
    for (int off = 1; off < 32; off <<= 1) {
        unsigned ap = __shfl_up_sync(0xffffffffu, ai, off);
        unsigned bp = __shfl_up_sync(0xffffffffu, bi, off);
        if (lane >= off) { ai = ai | (ap & bi); bi = bi & bp; }
    }
    unsigned s_in = __shfl_up_sync(0xffffffffu, ai, 1);
    if (lane == 0) s_in = 0u;

    unsigned sfx = anyeot;
    for (int off = 1; off < 32; off <<= 1) {
        unsigned v = __shfl_down_sync(0xffffffffu, sfx, off);
        if (lane + off < 32) sfx |= v;
    }
    unsigned after = __shfl_down_sync(0xffffffffu, sfx, 1);
    if (lane == 31) after = 0u;

    unsigned long long openbits = 0ull;
    unsigned s = s_in;
    for (int i = 0; i < 64; ++i) {
        int t = row[base + i];
        unsigned iso = (t == sot) ? 1u : 0u;
        unsigned ieo = (t == eot) ? 1u : 0u;
        unsigned o = iso | s;
        openbits |= ((unsigned long long)o) << i;
        s = iso | (s & (1u - ieo));
    }
    unsigned long long tbits = 0ull;
    unsigned seen = after;
    for (int i = 63; i >= 0; --i) {
        int t = row[base + i];
        if (t == eot) seen = 1u;
        if (((openbits >> i) & 1ull) && seen) tbits |= (1ull << i);
    }
    int c = __popcll(tbits);
    int pre = c;
    for (int off = 1; off < 32; off <<= 1) {
        int v = __shfl_up_sync(0xffffffffu, pre, off);
        if (lane >= off) pre += v;
    }
    int excl = pre - c;
    int total = __shfl_sync(0xffffffffu, pre, 31);
    if (lane == 31) g_tcnt[b] = total;
    int o = excl;
    for (int i = 0; i < 64; ++i) {
        if ((tbits >> i) & 1ull) g_tidx[b * Sn + (o++)] = base + i;
    }
}

// ---------------- gather thought rows: fp32 + hi/lo ------------------------------
__global__ void gather_kernel(const float* __restrict__ x)
{
    int b = blockIdx.y, i = blockIdx.x;
    if (i >= g_tcnt[b]) return;
    int src = b * Sn + g_tidx[b * Sn + i];
    int t = threadIdx.x;
    float4 v = ((const float4*)(x + (size_t)src * Dn))[t];
    size_t rb = (size_t)(b * Sn + i) * Dn;
    ((float4*)(g_Xc + rb))[t] = v;
    uint2 h, l;
    split4(v, h, l);
    ((uint2*)(g_Xc_h + rb))[t] = h;
    ((uint2*)(g_Xc_l + rb))[t] = l;
}

// ---------------- attention over compacted thought rows --------------------------
__global__ void __launch_bounds__(256) attn_kernel()
{
    int b = blockIdx.z, h = blockIdx.y, qt = blockIdx.x;
    int nT = g_tcnt[b];
    if (qt * 8 >= nT) return;

    __shared__ float Ks[128][33];
    __shared__ float Vs[32][128];
    __shared__ float Qs[8][128];

    int tid = threadIdx.x, warp = tid >> 5, lane = tid & 31;
    int q = qt * 8 + warp;
    bool qv = q < nT;
    if (qv) {
        const float* qr = g_qkv + (size_t)(b*Sn + q) * (3*Dn) + h * DHn;
#pragma unroll
        for (int c = 0; c < 4; ++c) Qs[warp][lane + 32*c] = qr[lane + 32*c];
    }

    float m = -1e30f, lsum = 0.f;
    float acc[4] = {0.f, 0.f, 0.f, 0.f};
    const float scale = 0.088388347648318447f;

    for (int j0 = 0; j0 < nT; j0 += 32) {
        int jn = min(32, nT - j0);
        __syncthreads();
        for (int idx = tid; idx < 32*128; idx += 256) {
            int j = idx >> 7, d = idx & 127;
            float kv = 0.f, vv = 0.f;
            if (j < jn) {
                const float* kr = g_qkv + (size_t)(b*Sn + j0 + j)*(3*Dn) + Dn + h*DHn;
                kv = kr[d];
                vv = kr[Dn + d];
            }
            Ks[d][j] = kv;
            Vs[j][d] = vv;
        }
        __syncthreads();
        if (qv) {
            float s = 0.f;
#pragma unroll 8
            for (int d = 0; d < 128; ++d) s += Qs[warp][d] * Ks[d][lane];
            s *= scale;
            if (lane >= jn) s = -1e30f;
            float smax = s;
#pragma unroll
            for (int off = 16; off; off >>= 1)
                smax = fmaxf(smax, __shfl_xor_sync(0xffffffffu, smax, off));
            float mnew = fmaxf(m, smax);
            float p = (lane < jn) ? __expf(s - mnew) : 0.f;
            float ps = p;
#pragma unroll
            for (int off = 16; off; off >>= 1)
                ps += __shfl_xor_sync(0xffffffffu, ps, off);
            float corr = __expf(m - mnew);
            lsum = lsum * corr + ps;
#pragma unroll
            for (int c = 0; c < 4; ++c) acc[c] *= corr;
            for (int j = 0; j < jn; ++j) {
                float pj = __shfl_sync(0xffffffffu, p, j);
#pragma unroll
                for (int c = 0; c < 4; ++c) acc[c] += pj * Vs[j][lane + 32*c];
            }
            m = mnew;
        }
    }
    if (qv) {
        float inv = 1.f / lsum;
        size_t rb = (size_t)(b*Sn + q) * Dn + h * DHn;
#pragma unroll
        for (int c = 0; c < 4; ++c) {
            float v = acc[c] * inv;
            __nv_bfloat16 hv = __float2bfloat16(v);
            g_ctx_h[rb + lane + 32*c] = hv;
            g_ctx_l[rb + lane + 32*c] = __float2bfloat16(v - __bfloat162float(hv));
        }
    }
}

// ---------------- block reduction helper ------------------------------------------
__device__ __forceinline__ float block_sum256(float v, float* red)
{
    int lane = threadIdx.x & 31, warp = threadIdx.x >> 5;
#pragma unroll
    for (int off = 16; off; off >>= 1) v += __shfl_xor_sync(0xffffffffu, v, off);
    if (lane == 0) red[warp] = v;
    __syncthreads();
    if (warp == 0) {
        float t = (lane < 8) ? red[lane] : 0.f;
#pragma unroll
        for (int off = 4; off; off >>= 1) t += __shfl_xor_sync(0xffffffffu, t, off);
        if (lane == 0) red[0] = t;
    }
    __syncthreads();
    float r = red[0];
    __syncthreads();
    return r;
}

// ---------------- fused residual-add + LayerNorm (+ optional hi/lo out) ----------
__global__ void __launch_bounds__(256) add_ln_kernel(
    const float* __restrict__ X, const float* __restrict__ Y,
    const float* __restrict__ g, const float* __restrict__ be,
    float* __restrict__ out, __nv_bfloat16* __restrict__ oh,
    __nv_bfloat16* __restrict__ ol, int use_cnt)
{
    int r = blockIdx.x;
    if (use_cnt) { int b = r >> 11; if ((r & 2047) >= g_tcnt[b]) return; }
    __shared__ float red[8];
    int t = threadIdx.x;
    float4 xv = ((const float4*)(X + (size_t)r * Dn))[t];
    float4 yv = ((const float4*)(Y + (size_t)r * Dn))[t];
    float v0 = xv.x + yv.x, v1 = xv.y + yv.y, v2 = xv.z + yv.z, v3 = xv.w + yv.w;
    float mu = block_sum256(v0 + v1 + v2 + v3, red) * (1.0f / Dn);
    float d0 = v0 - mu, d1 = v1 - mu, d2 = v2 - mu, d3 = v3 - mu;
    float var = block_sum256(d0*d0 + d1*d1 + d2*d2 + d3*d3, red) * (1.0f / Dn);
    float inv = rsqrtf(var + 1e-5f);
    float4 gv = ((const float4*)g)[t];
    float4 bv = ((const float4*)be)[t];
    float4 o;
    o.x = d0 * inv * gv.x + bv.x;
    o.y = d1 * inv * gv.y + bv.y;
    o.z = d2 * inv * gv.z + bv.z;
    o.w = d3 * inv * gv.w + bv.w;
    ((float4*)(out + (size_t)r * Dn))[t] = o;
    if (oh) {
        uint2 h, l;
        split4(o, h, l);
        ((uint2*)(oh + (size_t)r * Dn))[t] = h;
        ((uint2*)(ol + (size_t)r * Dn))[t] = l;
    }
}

// ---------------- cat init: cat = [x | x] (hi/lo), eff = 0.1 ----------------------
__global__ void init_cat_kernel(const float* __restrict__ x)
{
    int r = blockIdx.x, t = threadIdx.x;
    float4 v = ((const float4*)(x + (size_t)r * Dn))[t];
    uint2 h, l;
    split4(v, h, l);
    uint2* ch = (uint2*)(g_cat_h + (size_t)r * 2 * Dn);
    uint2* cl = (uint2*)(g_cat_l + (size_t)r * 2 * Dn);
    ch[t] = h; ch[t + 256] = h;
    cl[t] = l; cl[t + 256] = l;
    if (t == 0) g_eff[r] = 0.1f;
}

// ---------------- scatter x2 into cat[:, D:] (hi/lo) + gate -----------------------
__global__ void __launch_bounds__(256) scatter_kernel(
    const float* __restrict__ Wg, const float* __restrict__ bg)
{
    int b = blockIdx.y, i = blockIdx.x;
    if (i >= g_tcnt[b]) return;
    __shared__ float red[8];
    int dst = b * Sn + g_tidx[b * Sn + i];
    int t = threadIdx.x;
    float4 v = ((const float4*)(g_x2 + (size_t)(b*Sn + i) * Dn))[t];
    uint2 h, l;
    split4(v, h, l);
    ((uint2*)(g_cat_h + (size_t)dst * 2 * Dn + Dn))[t] = h;
    ((uint2*)(g_cat_l + (size_t)dst * 2 * Dn + Dn))[t] = l;
    float4 w = ((const float4*)Wg)[t];
    float p = v.x*w.x + v.y*w.y + v.z*w.z + v.w*w.w;
    float tot = block_sum256(p, red);
    if (t == 0) g_eff[dst] = 1.f / (1.f + __expf(-(tot + bg[0])));
}

// ---------------- mix: mixed = (1-eff)*x + eff*mixed_ctx (hi/lo out) --------------
__global__ void mix_kernel(const float* __restrict__ x)
{
    int r = blockIdx.x, t = threadIdx.x;
    float e = g_eff[r];
    float4 xv = ((const float4*)(x + (size_t)r * Dn))[t];
    float4 mc = ((const float4*)(g_mctx + (size_t)r * Dn))[t];
    float4 o;
    o.x = (1.f - e) * xv.x + e * mc.x;
    o.y = (1.f - e) * xv.y + e * mc.y;
    o.z = (1.f - e) * xv.z + e * mc.z;
    o.w = (1.f - e) * xv.w + e * mc.w;
    uint2 h, l;
    split4(o, h, l);
    ((uint2*)(g_mix_h + (size_t)r * Dn))[t] = h;
    ((uint2*)(g_mix_l + (size_t)r * Dn))[t] = l;
}

// ---------------- launch ------------------------------------------------------------
#define SYM(p, s) cudaGetSymbolAddress((void**)&p, s)

extern "C" void kernel_launch(void* const* d_in, const int* in_sizes, int n_in,
                              void* d_out, int out_size)
{
    const float* x    = (const float*)d_in[0];
    const int*   ids  = (const int*)d_in[1];
    const int*   sot  = (const int*)d_in[2];
    const int*   eot  = (const int*)d_in[3];
    const float* Wqkv = (const float*)d_in[4];
    const float* bqkv = (const float*)d_in[5];
    const float* Wo   = (const float*)d_in[6];
    const float* bo   = (const float*)d_in[7];
    const float* ln1g = (const float*)d_in[8];
    const float* ln1b = (const float*)d_in[9];
    const float* W1   = (const float*)d_in[10];
    const float* b1   = (const float*)d_in[11];
    const float* W2   = (const float*)d_in[12];
    const float* b2   = (const float*)d_in[13];
    const float* ln2g = (const float*)d_in[14];
    const float* ln2b = (const float*)d_in[15];
    const float* Wg   = (const float*)d_in[16];
    const float* bg   = (const float*)d_in[17];
    const float* Wm   = (const float*)d_in[18];
    const float* bm   = (const float*)d_in[19];
    const float* Wout = (const float*)d_in[20];
    const float* bout = (const float*)d_in[21];
    float* out = (float*)d_out;

    float *pXc, *pqkv, *pattno, *px1, *pff, *px2, *pmctx;
    __nv_bfloat16 *pXch, *pXcl, *pctxh, *pctxl, *px1h, *px1l, *phffh, *phffl;
    __nv_bfloat16 *pcath, *pcatl, *pmixh, *pmixl;
    __nv_bfloat16 *pWqkvh, *pWqkvl, *pWoh, *pWol, *pW1h, *pW1l, *pW2h, *pW2l;
    __nv_bfloat16 *pWmh, *pWml, *pWouth, *pWoutl;
    SYM(pXc, g_Xc); SYM(pqkv, g_qkv); SYM(pattno, g_attno); SYM(px1, g_x1);
    SYM(pff, g_ff); SYM(px2, g_x2); SYM(pmctx, g_mctx);
    SYM(pXch, g_Xc_h); SYM(pXcl, g_Xc_l); SYM(pctxh, g_ctx_h); SYM(pctxl, g_ctx_l);
    SYM(px1h, g_x1_h); SYM(px1l, g_x1_l); SYM(phffh, g_hff_h); SYM(phffl, g_hff_l);
    SYM(pcath, g_cat_h); SYM(pcatl, g_cat_l); SYM(pmixh, g_mix_h); SYM(pmixl, g_mix_l);
    SYM(pWqkvh, g_Wqkv_h); SYM(pWqkvl, g_Wqkv_l); SYM(pWoh, g_Wo_h); SYM(pWol, g_Wo_l);
    SYM(pW1h, g_W1_h); SYM(pW1l, g_W1_l); SYM(pW2h, g_W2_h); SYM(pW2l, g_W2_l);
    SYM(pWmh, g_Wm_h); SYM(pWml, g_Wm_l); SYM(pWouth, g_Wout_h); SYM(pWoutl, g_Wout_l);

    cudaFuncSetAttribute(gemm_bs<false,false>, cudaFuncAttributeMaxDynamicSharedMemorySize, GSMEM);
    cudaFuncSetAttribute(gemm_bs<true,true>,   cudaFuncAttributeMaxDynamicSharedMemorySize, GSMEM);

    // 1. thought mask + compaction
    mask_kernel<<<Bn, 32>>>(ids, sot, eot);
    // 2. split weights into bf16 hi/lo (pure bandwidth, ~60us total)
    split_kernel<<<512, 256>>>((const float4*)Wqkv, (uint2*)pWqkvh, (uint2*)pWqkvl, 3*Dn*Dn/4);
    split_kernel<<<256, 256>>>((const float4*)Wo,   (uint2*)pWoh,   (uint2*)pWol,   Dn*Dn/4);
    split_kernel<<<512, 256>>>((const float4*)W1,   (uint2*)pW1h,   (uint2*)pW1l,   DFFn*Dn/4);
    split_kernel<<<512, 256>>>((const float4*)W2,   (uint2*)pW2h,   (uint2*)pW2l,   Dn*DFFn/4);
    split_kernel<<<512, 256>>>((const float4*)Wm,   (uint2*)pWmh,   (uint2*)pWml,   Dn*2*Dn/4);
    split_kernel<<<2048, 256>>>((const float4*)Wout,(uint2*)pWouth, (uint2*)pWoutl, Vn*Dn/4);
    // 3. gather thought rows (fp32 + hi/lo)
    gather_kernel<<<dim3(Sn, Bn), 256>>>(x);
    // 4. QKV on compacted rows (N=3072, K=1024)
    gemm_bs<false,false><<<32*24, 256, GSMEM>>>(pXch, pXcl, pWqkvh, pWqkvl, bqkv, pqkv, nullptr, nullptr, 3*Dn, Dn, 1);
    // 5. masked attention == dense attention over compacted keys -> ctx hi/lo
    attn_kernel<<<dim3(Sn/8, NHEADS, Bn), 256>>>();
    // 6. attention output projection
    gemm_bs<false,false><<<32*8, 256, GSMEM>>>(pctxh, pctxl, pWoh, pWol, bo, pattno, nullptr, nullptr, Dn, Dn, 1);
    // 7. LN1(x + attn) -> x1 fp32 + hi/lo
    add_ln_kernel<<<Rn, 256>>>(pXc, pattno, ln1g, ln1b, px1, px1h, px1l, 1);
    // 8. FFN up + relu -> hff hi/lo directly (N=4096, K=1024)
    gemm_bs<true,true><<<32*32, 256, GSMEM>>>(px1h, px1l, pW1h, pW1l, b1, nullptr, phffh, phffl, DFFn, Dn, 1);
    // 9. FFN down (N=1024, K=4096)
    gemm_bs<false,false><<<32*8, 256, GSMEM>>>(phffh, phffl, pW2h, pW2l, b2, pff, nullptr, nullptr, Dn, DFFn, 1);
    // 10. LN2(x1 + ff) -> x2 fp32
    add_ln_kernel<<<Rn, 256>>>(px1, pff, ln2g, ln2b, px2, nullptr, nullptr, 1);
    // 11. cat = [x | x] hi/lo, eff = 0.1
    init_cat_kernel<<<Rn, 256>>>(x);
    // 12. scatter x2 into cat[:, D:] + gate
    scatter_kernel<<<dim3(Sn, Bn), 256>>>(Wg, bg);
    // 13. mixed_ctx = cat @ Wm^T + bm (dense, N=1024, K=2048)
    gemm_bs<false,false><<<32*8, 256, GSMEM>>>(pcath, pcatl, pWmh, pWml, bm, pmctx, nullptr, nullptr, Dn, 2*Dn, 0);
    // 14. mixed (hi/lo)
    mix_kernel<<<Rn, 256>>>(x);
    // 15. logits = mixed @ Wout^T + bout (dominant: N=32000, K=1024)
    gemm_bs<false,false><<<32*250, 256, GSMEM>>>(pmixh, pmixl, pWouth, pWoutl, bout, out, nullptr, nullptr, Vn, Dn, 0);

    (void)in_sizes; (void)n_in; (void)out_size;
}

// round 4
// speedup vs baseline: 3.1798x; 1.3220x over previous
#include <cuda_runtime.h>
#include <cuda_fp16.h>
#include <cstdint>

// ---------------- problem constants ----------------
#define Bn 2
#define Sn 2048
#define Dn 1024
#define Vn 32000
#define NHEADS 8
#define DHn 128
#define DFFn 4096
#define Rn (Bn*Sn)   // 4096 total rows

// ---------------- fp32 scratch ----------------
__device__ float g_Xc[Rn*Dn];
__device__ float g_qkv[Rn*3*Dn];
__device__ float g_attno[Rn*Dn];
__device__ float g_x1[Rn*Dn];
__device__ float g_ff[Rn*Dn];
__device__ float g_x2[Rn*Dn];
__device__ float g_mctx[Rn*Dn];
__device__ float g_eff[Rn];
__device__ int   g_tidx[Rn];
__device__ int   g_tcnt[Bn];

// ---------------- fp16 planes: activations hi/lo, weights single --------------
__device__ __align__(16) __half g_Xc_h[Rn*Dn],  g_Xc_l[Rn*Dn];
__device__ __align__(16) __half g_ctx_h[Rn*Dn], g_ctx_l[Rn*Dn];
__device__ __align__(16) __half g_x1_h[Rn*Dn],  g_x1_l[Rn*Dn];
__device__ __align__(16) __half g_hff_h[Rn*DFFn], g_hff_l[Rn*DFFn];
__device__ __align__(16) __half g_cat_h[Rn*2*Dn], g_cat_l[Rn*2*Dn];
__device__ __align__(16) __half g_mix_h[Rn*Dn], g_mix_l[Rn*Dn];
__device__ __align__(16) __half g_Wqkv_h[3*Dn*Dn];
__device__ __align__(16) __half g_Wo_h[Dn*Dn];
__device__ __align__(16) __half g_W1_h[DFFn*Dn];
__device__ __align__(16) __half g_W2_h[Dn*DFFn];
__device__ __align__(16) __half g_Wm_h[Dn*2*Dn];
__device__ __align__(16) __half g_Wout_h[Vn*Dn];

// ---------------- helpers -------------------------------------------------------
__device__ __forceinline__ uint32_t smem_u32(const void* p) {
    uint32_t a;
    asm("{ .reg .u64 t; cvta.to.shared.u64 t, %1; cvt.u32.u64 %0, t; }" : "=r"(a) : "l"(p));
    return a;
}
__device__ __forceinline__ uint32_t pk2h(__half a, __half b) {
    return ((uint32_t)__half_as_ushort(b) << 16) | (uint32_t)__half_as_ushort(a);
}
__device__ __forceinline__ void split4h(float4 v, uint2& h, uint2& l) {
    __half hx = __float2half_rn(v.x);
    __half hy = __float2half_rn(v.y);
    __half hz = __float2half_rn(v.z);
    __half hw = __float2half_rn(v.w);
    h.x = pk2h(hx, hy); h.y = pk2h(hz, hw);
    l.x = pk2h(__float2half_rn(v.x - __half2float(hx)),
               __float2half_rn(v.y - __half2float(hy)));
    l.y = pk2h(__float2half_rn(v.z - __half2float(hz)),
               __float2half_rn(v.w - __half2float(hw)));
}
__device__ __forceinline__ void cpa16(uint32_t dst, const void* src) {
    asm volatile("cp.async.cg.shared.global [%0], [%1], 16;" :: "r"(dst), "l"(src));
}
__device__ __forceinline__ void cp_commit() {
    asm volatile("cp.async.commit_group;" ::: "memory");
}
template<int N>
__device__ __forceinline__ void cp_wait() {
    asm volatile("cp.async.wait_group %0;" :: "n"(N) : "memory");
}
__device__ __forceinline__ void ldm4(uint32_t addr, uint32_t* r) {
    asm volatile("ldmatrix.sync.aligned.m8n8.x4.shared.b16 {%0,%1,%2,%3}, [%4];"
                 : "=r"(r[0]), "=r"(r[1]), "=r"(r[2]), "=r"(r[3]) : "r"(addr));
}
__device__ __forceinline__ void mma_hf(float* d, const uint32_t* a, const uint32_t* b) {
    asm volatile("mma.sync.aligned.m16n8k16.row.col.f32.f16.f16.f32 "
                 "{%0,%1,%2,%3}, {%4,%5,%6,%7}, {%8,%9}, {%0,%1,%2,%3};"
                 : "+f"(d[0]), "+f"(d[1]), "+f"(d[2]), "+f"(d[3])
                 : "r"(a[0]), "r"(a[1]), "r"(a[2]), "r"(a[3]), "r"(b[0]), "r"(b[1]));
}

// ---------------- weight convert kernel (fp32 -> fp16 single plane) ----------------
__global__ void conv_kernel(const float4* __restrict__ in, uint2* __restrict__ out, int n4)
{
    for (int i = blockIdx.x * 256 + threadIdx.x; i < n4; i += gridDim.x * 256) {
        float4 v = in[i];
        uint2 o;
        o.x = pk2h(__float2half_rn(v.x), __float2half_rn(v.y));
        o.y = pk2h(__float2half_rn(v.z), __float2half_rn(v.w));
        out[i] = o;
    }
}

// ---------------- fp16 2-term GEMM: C = (Ah+Al) @ W^T + bias ----------------------
// A hi/lo fp16 [M,K], W fp16 [N,K]. BM=128,BN=128,BK=32. 256 thr, 8 warps (4x2).
#define TILEB 10240          // 128 rows * 80B padded stride
#define BUFB  (3*TILEB)      // Ah | Al | W
#define GSMEM (2*BUFB)       // 61440

template<bool RELU, bool SPLITOUT>
__global__ void __launch_bounds__(256, 1)
gemm_hs(const __half* __restrict__ Ah, const __half* __restrict__ Al,
        const __half* __restrict__ W,
        const float* __restrict__ bias, float* __restrict__ C,
        __half* __restrict__ Ch, __half* __restrict__ Cl,
        int N, int K, int use_cnt)
{
    int bid = blockIdx.x;
    int m0 = (bid & 31) << 7;
    int n0 = (bid >> 5) << 7;
    if (use_cnt) {
        int b = m0 >> 11;
        if ((m0 & 2047) >= g_tcnt[b]) return;
    }

    extern __shared__ char smraw[];
    uint32_t sb = smem_u32(smraw);
    int tid = threadIdx.x, lane = tid & 31, wid = tid >> 5;
    int mw = (wid & 3) << 5;   // warp m-origin in tile
    int nw = (wid >> 2) << 6;  // warp n-origin in tile

    // cp.async slots: 6 per thread (3 tiles x 2 rows)
    int lr = tid >> 2, seg = tid & 3;
    const __half* src[6];
    uint32_t dsto[6];
    src[0] = Ah + (size_t)(m0 + lr) * K + seg * 8;        dsto[0] = 0*TILEB + lr*80 + seg*16;
    src[1] = Ah + (size_t)(m0 + lr + 64) * K + seg * 8;   dsto[1] = 0*TILEB + (lr+64)*80 + seg*16;
    src[2] = Al + (size_t)(m0 + lr) * K + seg * 8;        dsto[2] = 1*TILEB + lr*80 + seg*16;
    src[3] = Al + (size_t)(m0 + lr + 64) * K + seg * 8;   dsto[3] = 1*TILEB + (lr+64)*80 + seg*16;
    src[4] = W  + (size_t)(n0 + lr) * K + seg * 8;        dsto[4] = 2*TILEB + lr*80 + seg*16;
    src[5] = W  + (size_t)(n0 + lr + 64) * K + seg * 8;   dsto[5] = 2*TILEB + (lr+64)*80 + seg*16;

    // ldmatrix per-lane offsets
    int am = lane >> 3;
    int arow = ((am & 1) << 3) | (lane & 7);
    int akc = am >> 1;
    uint32_t offA[2][2];
    #pragma unroll
    for (int mt = 0; mt < 2; ++mt)
        #pragma unroll
        for (int ks = 0; ks < 2; ++ks)
            offA[mt][ks] = (uint32_t)((mw + mt*16 + arow) * 80 + (ks*2 + akc) * 16);
    int brow = ((am >> 1) << 3) | (lane & 7);
    int bkc = am & 1;
    uint32_t offB[4][2];
    #pragma unroll
    for (int jp = 0; jp < 4; ++jp)
        #pragma unroll
        for (int ks = 0; ks < 2; ++ks)
            offB[jp][ks] = (uint32_t)((nw + jp*16 + brow) * 80 + (ks*2 + bkc) * 16);

    float acc[2][8][4];
    #pragma unroll
    for (int mt = 0; mt < 2; ++mt)
        #pragma unroll
        for (int nt = 0; nt < 8; ++nt)
            #pragma unroll
            for (int i = 0; i < 4; ++i) acc[mt][nt][i] = 0.f;

    int NC = K >> 5;

    // prefetch chunk 0
    #pragma unroll
    for (int j = 0; j < 6; ++j) cpa16(sb + dsto[j], src[j]);
    cp_commit();

    for (int c = 0; c < NC; ++c) {
        uint32_t cb = sb + (uint32_t)(c & 1) * BUFB;
        if (c + 1 < NC) {
            uint32_t nb = sb + (uint32_t)((c + 1) & 1) * BUFB;
            const int ko = (c + 1) * 32;
            #pragma unroll
            for (int j = 0; j < 6; ++j) cpa16(nb + dsto[j], src[j] + ko);
            cp_commit();
            cp_wait<1>();
        } else {
            cp_wait<0>();
        }
        __syncthreads();

        #pragma unroll
        for (int ks = 0; ks < 2; ++ks) {
            uint32_t ah[2][4], al_[2][4], w[4][4];
            ldm4(cb + offA[0][ks], ah[0]);
            ldm4(cb + offA[1][ks], ah[1]);
            ldm4(cb + TILEB + offA[0][ks], al_[0]);
            ldm4(cb + TILEB + offA[1][ks], al_[1]);
            #pragma unroll
            for (int jp = 0; jp < 4; ++jp)
                ldm4(cb + 2*TILEB + offB[jp][ks], w[jp]);
            #pragma unroll
            for (int mt = 0; mt < 2; ++mt)
                #pragma unroll
                for (int nt = 0; nt < 8; ++nt) {
                    const uint32_t* bw = &w[nt >> 1][(nt & 1) * 2];
                    mma_hf(acc[mt][nt], ah[mt], bw);
                    mma_hf(acc[mt][nt], al_[mt], bw);
                }
        }
        __syncthreads();
    }

    // epilogue: direct stores (quad of 4 threads covers 32B contiguous)
    #pragma unroll
    for (int mt = 0; mt < 2; ++mt)
        #pragma unroll
        for (int nt = 0; nt < 8; ++nt) {
            float* a = acc[mt][nt];
            int col = n0 + nw + nt * 8 + (lane & 3) * 2;
            int r0  = m0 + mw + mt * 16 + (lane >> 2);
            float2 bv = *(const float2*)(bias + col);
            float x0 = a[0] + bv.x, y0 = a[1] + bv.y;
            float x1 = a[2] + bv.x, y1 = a[3] + bv.y;
            if (RELU) {
                x0 = fmaxf(x0, 0.f); y0 = fmaxf(y0, 0.f);
                x1 = fmaxf(x1, 0.f); y1 = fmaxf(y1, 0.f);
            }
            if (!SPLITOUT) {
                float2 v0 = {x0, y0}, v1 = {x1, y1};
                *(float2*)(C + (size_t)r0 * N + col) = v0;
                *(float2*)(C + (size_t)(r0 + 8) * N + col) = v1;
            } else {
                __half h0 = __float2half_rn(x0), h1 = __float2half_rn(y0);
                __half h2 = __float2half_rn(x1), h3 = __float2half_rn(y1);
                *(uint32_t*)(Ch + (size_t)r0 * N + col) = pk2h(h0, h1);
                *(uint32_t*)(Ch + (size_t)(r0 + 8) * N + col) = pk2h(h2, h3);
                *(uint32_t*)(Cl + (size_t)r0 * N + col) =
                    pk2h(__float2half_rn(x0 - __half2float(h0)),
                         __float2half_rn(y0 - __half2float(h1)));
                *(uint32_t*)(Cl + (size_t)(r0 + 8) * N + col) =
                    pk2h(__float2half_rn(x1 - __half2float(h2)),
                         __float2half_rn(y1 - __half2float(h3)));
            }
        }
}

// ---------------- mask + compaction (1 warp per batch) ---------------------------
__global__ void mask_kernel(const int* __restrict__ ids,
                            const int* __restrict__ sotp,
                            const int* __restrict__ eotp)
{
    int b = blockIdx.x;
    int lane = threadIdx.x;
    int sot = *sotp, eot = *eotp;
    const int* row = ids + b * Sn;
    int base = lane * 64;

    unsigned a = 0u, bb = 1u, anyeot = 0u;
    for (int i = 0; i < 64; ++i) {
        int t = row[base + i];
        unsigned iso = (t == sot) ? 1u : 0u;
        unsigned ieo = (t == eot) ? 1u : 0u;
        a = iso | (a & (1u - ieo));
        bb = bb & (1u - ieo);
        anyeot |= ieo;
    }
    unsigned ai = a, bi = bb;
    for (int off = 1; off < 32; off <<= 1) {
        unsigned ap = __shfl_up_sync(0xffffffffu, ai, off);
        unsigned bp = __shfl_up_sync(0xffffffffu, bi, off);
        if (lane >= off) { ai = ai | (ap & bi); bi = bi & bp; }
    }
    unsigned s_in = __shfl_up_sync(0xffffffffu, ai, 1);
    if (lane == 0) s_in = 0u;

    unsigned sfx = anyeot;
    for (int off = 1; off < 32; off <<= 1) {
        unsigned v = __shfl_down_sync(0xffffffffu, sfx, off);
        if (lane + off < 32) sfx |= v;
    }
    unsigned after = __shfl_down_sync(0xffffffffu, sfx, 1);
    if (lane == 31) after = 0u;

    unsigned long long openbits = 0ull;
    unsigned s = s_in;
    for (int i = 0; i < 64; ++i) {
        int t = row[base + i];
        unsigned iso = (t == sot) ? 1u : 0u;
        unsigned ieo = (t == eot) ? 1u : 0u;
        unsigned o = iso | s;
        openbits |= ((unsigned long long)o) << i;
        s = iso | (s & (1u - ieo));
    }
    unsigned long long tbits = 0ull;
    unsigned seen = after;
    for (int i = 63; i >= 0; --i) {
        int t = row[base + i];
        if (t == eot) seen = 1u;
        if (((openbits >> i) & 1ull) && seen) tbits |= (1ull << i);
    }
    int c = __popcll(tbits);
    int pre = c;
    for (int off = 1; off < 32; off <<= 1) {
        int v = __shfl_up_sync(0xffffffffu, pre, off);
        if (lane >= off) pre += v;
    }
    int excl = pre - c;
    int total = __shfl_sync(0xffffffffu, pre, 31);
    if (lane == 31) g_tcnt[b] = total;
    int o = excl;
    for (int i = 0; i < 64; ++i) {
        if ((tbits >> i) & 1ull) g_tidx[b * Sn + (o++)] = base + i;
    }
}

// ---------------- gather thought rows: fp32 + hi/lo ------------------------------
__global__ void gather_kernel(const float* __restrict__ x)
{
    int b = blockIdx.y, i = blockIdx.x;
    if (i >= g_tcnt[b]) return;
    int src = b * Sn + g_tidx[b * Sn + i];
    int t = threadIdx.x;
    float4 v = ((const float4*)(x + (size_t)src * Dn))[t];
    size_t rb = (size_t)(b * Sn + i) * Dn;
    ((float4*)(g_Xc + rb))[t] = v;
    uint2 h, l;
    split4h(v, h, l);
    ((uint2*)(g_Xc_h + rb))[t] = h;
    ((uint2*)(g_Xc_l + rb))[t] = l;
}

// ---------------- attention over compacted thought rows --------------------------
__global__ void __launch_bounds__(256) attn_kernel()
{
    int b = blockIdx.z, h = blockIdx.y, qt = blockIdx.x;
    int nT = g_tcnt[b];
    if (qt * 8 >= nT) return;

    __shared__ float Ks[128][33];
    __shared__ float Vs[32][128];
    __shared__ float Qs[8][128];

    int tid = threadIdx.x, warp = tid >> 5, lane = tid & 31;
    int q = qt * 8 + warp;
    bool qv = q < nT;
    if (qv) {
        const float* qr = g_qkv + (size_t)(b*Sn + q) * (3*Dn) + h * DHn;
#pragma unroll
        for (int c = 0; c < 4; ++c) Qs[warp][lane + 32*c] = qr[lane + 32*c];
    }

    float m = -1e30f, lsum = 0.f;
    float acc[4] = {0.f, 0.f, 0.f, 0.f};
    const float scale = 0.088388347648318447f;

    for (int j0 = 0; j0 < nT; j0 += 32) {
        int jn = min(32, nT - j0);
        __syncthreads();
        for (int idx = tid; idx < 32*128; idx += 256) {
            int j = idx >> 7, d = idx & 127;
            float kv = 0.f, vv = 0.f;
            if (j < jn) {
                const float* kr = g_qkv + (size_t)(b*Sn + j0 + j)*(3*Dn) + Dn + h*DHn;
                kv = kr[d];
                vv = kr[Dn + d];
            }
            Ks[d][j] = kv;
            Vs[j][d] = vv;
        }
        __syncthreads();
        if (qv) {
            float s = 0.f;
#pragma unroll 8
            for (int d = 0; d < 128; ++d) s += Qs[warp][d] * Ks[d][lane];
            s *= scale;
            if (lane >= jn) s = -1e30f;
            float smax = s;
#pragma unroll
            for (int off = 16; off; off >>= 1)
                smax = fmaxf(smax, __shfl_xor_sync(0xffffffffu, smax, off));
            float mnew = fmaxf(m, smax);
            float p = (lane < jn) ? __expf(s - mnew) : 0.f;
            float ps = p;
#pragma unroll
            for (int off = 16; off; off >>= 1)
                ps += __shfl_xor_sync(0xffffffffu, ps, off);
            float corr = __expf(m - mnew);
            lsum = lsum * corr + ps;
#pragma unroll
            for (int c = 0; c < 4; ++c) acc[c] *= corr;
            for (int j = 0; j < jn; ++j) {
                float pj = __shfl_sync(0xffffffffu, p, j);
#pragma unroll
                for (int c = 0; c < 4; ++c) acc[c] += pj * Vs[j][lane + 32*c];
            }
            m = mnew;
        }
    }
    if (qv) {
        float inv = 1.f / lsum;
        size_t rb = (size_t)(b*Sn + q) * Dn + h * DHn;
#pragma unroll
        for (int c = 0; c < 4; ++c) {
            float v = acc[c] * inv;
            __half hv = __float2half_rn(v);
            g_ctx_h[rb + lane + 32*c] = hv;
            g_ctx_l[rb + lane + 32*c] = __float2half_rn(v - __half2float(hv));
        }
    }
}

// ---------------- block reduction helper ------------------------------------------
__device__ __forceinline__ float block_sum256(float v, float* red)
{
    int lane = threadIdx.x & 31, warp = threadIdx.x >> 5;
#pragma unroll
    for (int off = 16; off; off >>= 1) v += __shfl_xor_sync(0xffffffffu, v, off);
    if (lane == 0) red[warp] = v;
    __syncthreads();
    if (warp == 0) {
        float t = (lane < 8) ? red[lane] : 0.f;
#pragma unroll
        for (int off = 4; off; off >>= 1) t += __shfl_xor_sync(0xffffffffu, t, off);
        if (lane == 0) red[0] = t;
    }
    __syncthreads();
    float r = red[0];
    __syncthreads();
    return r;
}

// ---------------- fused residual-add + LayerNorm (+ optional hi/lo out) ----------
__global__ void __launch_bounds__(256) add_ln_kernel(
    const float* __restrict__ X, const float* __restrict__ Y,
    const float* __restrict__ g, const float* __restrict__ be,
    float* __restrict__ out, __half* __restrict__ oh,
    __half* __restrict__ ol, int use_cnt)
{
    int r = blockIdx.x;
    if (use_cnt) { int b = r >> 11; if ((r & 2047) >= g_tcnt[b]) return; }
    __shared__ float red[8];
    int t = threadIdx.x;
    float4 xv = ((const float4*)(X + (size_t)r * Dn))[t];
    float4 yv = ((const float4*)(Y + (size_t)r * Dn))[t];
    float v0 = xv.x + yv.x, v1 = xv.y + yv.y, v2 = xv.z + yv.z, v3 = xv.w + yv.w;
    float mu = block_sum256(v0 + v1 + v2 + v3, red) * (1.0f / Dn);
    float d0 = v0 - mu, d1 = v1 - mu, d2 = v2 - mu, d3 = v3 - mu;
    float var = block_sum256(d0*d0 + d1*d1 + d2*d2 + d3*d3, red) * (1.0f / Dn);
    float inv = rsqrtf(var + 1e-5f);
    float4 gv = ((const float4*)g)[t];
    float4 bv = ((const float4*)be)[t];
    float4 o;
    o.x = d0 * inv * gv.x + bv.x;
    o.y = d1 * inv * gv.y + bv.y;
    o.z = d2 * inv * gv.z + bv.z;
    o.w = d3 * inv * gv.w + bv.w;
    ((float4*)(out + (size_t)r * Dn))[t] = o;
    if (oh) {
        uint2 h, l;
        split4h(o, h, l);
        ((uint2*)(oh + (size_t)r * Dn))[t] = h;
        ((uint2*)(ol + (size_t)r * Dn))[t] = l;
    }
}

// ---------------- cat init: cat = [x | x] (hi/lo), eff = 0.1 ----------------------
__global__ void init_cat_kernel(const float* __restrict__ x)
{
    int r = blockIdx.x, t = threadIdx.x;
    float4 v = ((const float4*)(x + (size_t)r * Dn))[t];
    uint2 h, l;
    split4h(v, h, l);
    uint2* ch = (uint2*)(g_cat_h + (size_t)r * 2 * Dn);
    uint2* cl = (uint2*)(g_cat_l + (size_t)r * 2 * Dn);
    ch[t] = h; ch[t + 256] = h;
    cl[t] = l; cl[t + 256] = l;
    if (t == 0) g_eff[r] = 0.1f;
}

// ---------------- scatter x2 into cat[:, D:] (hi/lo) + gate -----------------------
__global__ void __launch_bounds__(256) scatter_kernel(
    const float* __restrict__ Wg, const float* __restrict__ bg)
{
    int b = blockIdx.y, i = blockIdx.x;
    if (i >= g_tcnt[b]) return;
    __shared__ float red[8];
    int dst = b * Sn + g_tidx[b * Sn + i];
    int t = threadIdx.x;
    float4 v = ((const float4*)(g_x2 + (size_t)(b*Sn + i) * Dn))[t];
    uint2 h, l;
    split4h(v, h, l);
    ((uint2*)(g_cat_h + (size_t)dst * 2 * Dn + Dn))[t] = h;
    ((uint2*)(g_cat_l + (size_t)dst * 2 * Dn + Dn))[t] = l;
    float4 w = ((const float4*)Wg)[t];
    float p = v.x*w.x + v.y*w.y + v.z*w.z + v.w*w.w;
    float tot = block_sum256(p, red);
    if (t == 0) g_eff[dst] = 1.f / (1.f + __expf(-(tot + bg[0])));
}

// ---------------- mix: mixed = (1-eff)*x + eff*mixed_ctx (hi/lo out) --------------
__global__ void mix_kernel(const float* __restrict__ x)
{
    int r = blockIdx.x, t = threadIdx.x;
    float e = g_eff[r];
    float4 xv = ((const float4*)(x + (size_t)r * Dn))[t];
    float4 mc = ((const float4*)(g_mctx + (size_t)r * Dn))[t];
    float4 o;
    o.x = (1.f - e) * xv.x + e * mc.x;
    o.y = (1.f - e) * xv.y + e * mc.y;
    o.z = (1.f - e) * xv.z + e * mc.z;
    o.w = (1.f - e) * xv.w + e * mc.w;
    uint2 h, l;
    split4h(o, h, l);
    ((uint2*)(g_mix_h + (size_t)r * Dn))[t] = h;
    ((uint2*)(g_mix_l + (size_t)r * Dn))[t] = l;
}

// ---------------- launch ------------------------------------------------------------
#define SYM(p, s) cudaGetSymbolAddress((void**)&p, s)

extern "C" void kernel_launch(void* const* d_in, const int* in_sizes, int n_in,
                              void* d_out, int out_size)
{
    const float* x    = (const float*)d_in[0];
    const int*   ids  = (const int*)d_in[1];
    const int*   sot  = (const int*)d_in[2];
    const int*   eot  = (const int*)d_in[3];
    const float* Wqkv = (const float*)d_in[4];
    const float* bqkv = (const float*)d_in[5];
    const float* Wo   = (const float*)d_in[6];
    const float* bo   = (const float*)d_in[7];
    const float* ln1g = (const float*)d_in[8];
    const float* ln1b = (const float*)d_in[9];
    const float* W1   = (const float*)d_in[10];
    const float* b1   = (const float*)d_in[11];
    const float* W2   = (const float*)d_in[12];
    const float* b2   = (const float*)d_in[13];
    const float* ln2g = (const float*)d_in[14];
    const float* ln2b = (const float*)d_in[15];
    const float* Wg   = (const float*)d_in[16];
    const float* bg   = (const float*)d_in[17];
    const float* Wm   = (const float*)d_in[18];
    const float* bm   = (const float*)d_in[19];
    const float* Wout = (const float*)d_in[20];
    const float* bout = (const float*)d_in[21];
    float* out = (float*)d_out;

    float *pXc, *pqkv, *pattno, *px1, *pff, *px2, *pmctx;
    __half *pXch, *pXcl, *pctxh, *pctxl, *px1h, *px1l, *phffh, *phffl;
    __half *pcath, *pcatl, *pmixh, *pmixl;
    __half *pWqkvh, *pWoh, *pW1h, *pW2h, *pWmh, *pWouth;
    SYM(pXc, g_Xc); SYM(pqkv, g_qkv); SYM(pattno, g_attno); SYM(px1, g_x1);
    SYM(pff, g_ff); SYM(px2, g_x2); SYM(pmctx, g_mctx);
    SYM(pXch, g_Xc_h); SYM(pXcl, g_Xc_l); SYM(pctxh, g_ctx_h); SYM(pctxl, g_ctx_l);
    SYM(px1h, g_x1_h); SYM(px1l, g_x1_l); SYM(phffh, g_hff_h); SYM(phffl, g_hff_l);
    SYM(pcath, g_cat_h); SYM(pcatl, g_cat_l); SYM(pmixh, g_mix_h); SYM(pmixl, g_mix_l);
    SYM(pWqkvh, g_Wqkv_h); SYM(pWoh, g_Wo_h); SYM(pW1h, g_W1_h); SYM(pW2h, g_W2_h);
    SYM(pWmh, g_Wm_h); SYM(pWouth, g_Wout_h);

    cudaFuncSetAttribute(gemm_hs<false,false>, cudaFuncAttributeMaxDynamicSharedMemorySize, GSMEM);
    cudaFuncSetAttribute(gemm_hs<true,true>,   cudaFuncAttributeMaxDynamicSharedMemorySize, GSMEM);

    // 1. thought mask + compaction
    mask_kernel<<<Bn, 32>>>(ids, sot, eot);
    // 2. convert weights to fp16 (single plane)
    conv_kernel<<<512, 256>>>((const float4*)Wqkv, (uint2*)pWqkvh, 3*Dn*Dn/4);
    conv_kernel<<<256, 256>>>((const float4*)Wo,   (uint2*)pWoh,   Dn*Dn/4);
    conv_kernel<<<512, 256>>>((const float4*)W1,   (uint2*)pW1h,   DFFn*Dn/4);
    conv_kernel<<<512, 256>>>((const float4*)W2,   (uint2*)pW2h,   Dn*DFFn/4);
    conv_kernel<<<512, 256>>>((const float4*)Wm,   (uint2*)pWmh,   Dn*2*Dn/4);
    conv_kernel<<<2048, 256>>>((const float4*)Wout,(uint2*)pWouth, Vn*Dn/4);
    // 3. gather thought rows (fp32 + hi/lo)
    gather_kernel<<<dim3(Sn, Bn), 256>>>(x);
    // 4. QKV on compacted rows (N=3072, K=1024)
    gemm_hs<false,false><<<32*24, 256, GSMEM>>>(pXch, pXcl, pWqkvh, bqkv, pqkv, nullptr, nullptr, 3*Dn, Dn, 1);
    // 5. masked attention == dense attention over compacted keys -> ctx hi/lo
    attn_kernel<<<dim3(Sn/8, NHEADS, Bn), 256>>>();
    // 6. attention output projection
    gemm_hs<false,false><<<32*8, 256, GSMEM>>>(pctxh, pctxl, pWoh, bo, pattno, nullptr, nullptr, Dn, Dn, 1);
    // 7. LN1(x + attn) -> x1 fp32 + hi/lo
    add_ln_kernel<<<Rn, 256>>>(pXc, pattno, ln1g, ln1b, px1, px1h, px1l, 1);
    // 8. FFN up + relu -> hff hi/lo directly (N=4096, K=1024)
    gemm_hs<true,true><<<32*32, 256, GSMEM>>>(px1h, px1l, pW1h, b1, nullptr, phffh, phffl, DFFn, Dn, 1);
    // 9. FFN down (N=1024, K=4096)
    gemm_hs<false,false><<<32*8, 256, GSMEM>>>(phffh, phffl, pW2h, b2, pff, nullptr, nullptr, Dn, DFFn, 1);
    // 10. LN2(x1 + ff) -> x2 fp32
    add_ln_kernel<<<Rn, 256>>>(px1, pff, ln2g, ln2b, px2, nullptr, nullptr, 1);
    // 11. cat = [x | x] hi/lo, eff = 0.1
    init_cat_kernel<<<Rn, 256>>>(x);
    // 12. scatter x2 into cat[:, D:] + gate
    scatter_kernel<<<dim3(Sn, Bn), 256>>>(Wg, bg);
    // 13. mixed_ctx = cat @ Wm^T + bm (dense, N=1024, K=2048)
    gemm_hs<false,false><<<32*8, 256, GSMEM>>>(pcath, pcatl, pWmh, bm, pmctx, nullptr, nullptr, Dn, 2*Dn, 0);
    // 14. mixed (hi/lo)
    mix_kernel<<<Rn, 256>>>(x);
    // 15. logits = mixed @ Wout^T + bout (dominant: N=32000, K=1024)
    gemm_hs<false,false><<<32*250, 256, GSMEM>>>(pmixh, pmixl, pWouth, bout, out, nullptr, nullptr, Vn, Dn, 0);

    (void)in_sizes; (void)n_in; (void)out_size;
}

// round 5
// speedup vs baseline: 4.4628x; 1.4035x over previous
#include <cuda_runtime.h>
#include <cuda_fp16.h>
#include <cstdint>

// ---------------- problem constants ----------------
#define Bn 2
#define Sn 2048
#define Dn 1024
#define Vn 32000
#define NHEADS 8
#define DHn 128
#define DFFn 4096
#define Rn (Bn*Sn)   // 4096 total rows

// ---------------- fp32 scratch ----------------
__device__ float g_Xc[Rn*Dn];
__device__ float g_qkv[Rn*3*Dn];
__device__ float g_attno[Rn*Dn];
__device__ float g_x1[Rn*Dn];
__device__ float g_ff[Rn*Dn];
__device__ float g_x2[Rn*Dn];
__device__ float g_mctx[Rn*Dn];
__device__ float g_eff[Rn];
__device__ int   g_tidx[Rn];
__device__ int   g_tcnt[Bn];

// ---------------- fp16 planes (single, no lo) ---------------------------------
__device__ __align__(16) __half g_Xc_h[Rn*Dn];
__device__ __align__(16) __half g_ctx_h[Rn*Dn];
__device__ __align__(16) __half g_x1_h[Rn*Dn];
__device__ __align__(16) __half g_hff_h[Rn*DFFn];
__device__ __align__(16) __half g_cat_h[Rn*2*Dn];
__device__ __align__(16) __half g_mix_h[Rn*Dn];
__device__ __align__(16) __half g_Wqkv_h[3*Dn*Dn];
__device__ __align__(16) __half g_Wo_h[Dn*Dn];
__device__ __align__(16) __half g_W1_h[DFFn*Dn];
__device__ __align__(16) __half g_W2_h[Dn*DFFn];
__device__ __align__(16) __half g_Wm_h[Dn*2*Dn];
__device__ __align__(16) __half g_Wout_h[Vn*Dn];

// ---------------- helpers -------------------------------------------------------
__device__ __forceinline__ uint32_t smem_u32(const void* p) {
    uint32_t a;
    asm("{ .reg .u64 t; cvta.to.shared.u64 t, %1; cvt.u32.u64 %0, t; }" : "=r"(a) : "l"(p));
    return a;
}
__device__ __forceinline__ uint32_t pk2h(__half a, __half b) {
    return ((uint32_t)__half_as_ushort(b) << 16) | (uint32_t)__half_as_ushort(a);
}
__device__ __forceinline__ uint2 cvt4h(float4 v) {
    uint2 h;
    h.x = pk2h(__float2half_rn(v.x), __float2half_rn(v.y));
    h.y = pk2h(__float2half_rn(v.z), __float2half_rn(v.w));
    return h;
}
__device__ __forceinline__ void cpa16(uint32_t dst, const void* src) {
    asm volatile("cp.async.cg.shared.global [%0], [%1], 16;" :: "r"(dst), "l"(src));
}
__device__ __forceinline__ void cp_commit() {
    asm volatile("cp.async.commit_group;" ::: "memory");
}
template<int N>
__device__ __forceinline__ void cp_wait() {
    asm volatile("cp.async.wait_group %0;" :: "n"(N) : "memory");
}
__device__ __forceinline__ void ldm4(uint32_t addr, uint32_t* r) {
    asm volatile("ldmatrix.sync.aligned.m8n8.x4.shared.b16 {%0,%1,%2,%3}, [%4];"
                 : "=r"(r[0]), "=r"(r[1]), "=r"(r[2]), "=r"(r[3]) : "r"(addr));
}
__device__ __forceinline__ void mma_hf(float* d, const uint32_t* a, const uint32_t* b) {
    asm volatile("mma.sync.aligned.m16n8k16.row.col.f32.f16.f16.f32 "
                 "{%0,%1,%2,%3}, {%4,%5,%6,%7}, {%8,%9}, {%0,%1,%2,%3};"
                 : "+f"(d[0]), "+f"(d[1]), "+f"(d[2]), "+f"(d[3])
                 : "r"(a[0]), "r"(a[1]), "r"(a[2]), "r"(a[3]), "r"(b[0]), "r"(b[1]));
}

// ---------------- weight convert kernel (fp32 -> fp16) ----------------------------
__global__ void conv_kernel(const float4* __restrict__ in, uint2* __restrict__ out, int n4)
{
    for (int i = blockIdx.x * 256 + threadIdx.x; i < n4; i += gridDim.x * 256) {
        out[i] = cvt4h(in[i]);
    }
}

// ---------------- fp16 GEMM: C = A @ W^T + bias -----------------------------------
// A fp16 [M,K], W fp16 [N,K]. BM=128,BN=128,BK=32. 256 thr, 8 warps (4x2).
#define TILEB 10240          // 128 rows * 80B padded stride
#define BUFB  (2*TILEB)      // A | W
#define GSMEM (2*BUFB)       // 40960

template<bool RELU, bool SPLITOUT>
__global__ void __launch_bounds__(256, 1)
gemm_hs(const __half* __restrict__ A, const __half* __restrict__ W,
        const float* __restrict__ bias, float* __restrict__ C,
        __half* __restrict__ Ch,
        int N, int K, int use_cnt)
{
    int bid = blockIdx.x;
    int m0 = (bid & 31) << 7;
    int n0 = (bid >> 5) << 7;
    if (use_cnt) {
        int b = m0 >> 11;
        if ((m0 & 2047) >= g_tcnt[b]) return;
    }

    extern __shared__ char smraw[];
    uint32_t sb = smem_u32(smraw);
    int tid = threadIdx.x, lane = tid & 31, wid = tid >> 5;
    int mw = (wid & 3) << 5;   // warp m-origin in tile
    int nw = (wid >> 2) << 6;  // warp n-origin in tile

    // cp.async slots: 4 per thread (2 tiles x 2 rows)
    int lr = tid >> 2, seg = tid & 3;
    const __half* src[4];
    uint32_t dsto[4];
    src[0] = A + (size_t)(m0 + lr) * K + seg * 8;        dsto[0] = 0*TILEB + lr*80 + seg*16;
    src[1] = A + (size_t)(m0 + lr + 64) * K + seg * 8;   dsto[1] = 0*TILEB + (lr+64)*80 + seg*16;
    src[2] = W + (size_t)(n0 + lr) * K + seg * 8;        dsto[2] = 1*TILEB + lr*80 + seg*16;
    src[3] = W + (size_t)(n0 + lr + 64) * K + seg * 8;   dsto[3] = 1*TILEB + (lr+64)*80 + seg*16;

    // ldmatrix per-lane offsets
    int am = lane >> 3;
    int arow = ((am & 1) << 3) | (lane & 7);
    int akc = am >> 1;
    uint32_t offA[2][2];
    #pragma unroll
    for (int mt = 0; mt < 2; ++mt)
        #pragma unroll
        for (int ks = 0; ks < 2; ++ks)
            offA[mt][ks] = (uint32_t)((mw + mt*16 + arow) * 80 + (ks*2 + akc) * 16);
    int brow = ((am >> 1) << 3) | (lane & 7);
    int bkc = am & 1;
    uint32_t offB[4][2];
    #pragma unroll
    for (int jp = 0; jp < 4; ++jp)
        #pragma unroll
        for (int ks = 0; ks < 2; ++ks)
            offB[jp][ks] = (uint32_t)((nw + jp*16 + brow) * 80 + (ks*2 + bkc) * 16);

    float acc[2][8][4];
    #pragma unroll
    for (int mt = 0; mt < 2; ++mt)
        #pragma unroll
        for (int nt = 0; nt < 8; ++nt)
            #pragma unroll
            for (int i = 0; i < 4; ++i) acc[mt][nt][i] = 0.f;

    int NC = K >> 5;

    // prefetch chunk 0
    #pragma unroll
    for (int j = 0; j < 4; ++j) cpa16(sb + dsto[j], src[j]);
    cp_commit();

    for (int c = 0; c < NC; ++c) {
        uint32_t cb = sb + (uint32_t)(c & 1) * BUFB;
        if (c + 1 < NC) {
            uint32_t nb = sb + (uint32_t)((c + 1) & 1) * BUFB;
            const int ko = (c + 1) * 32;
            #pragma unroll
            for (int j = 0; j < 4; ++j) cpa16(nb + dsto[j], src[j] + ko);
            cp_commit();
            cp_wait<1>();
        } else {
            cp_wait<0>();
        }
        __syncthreads();

        #pragma unroll
        for (int ks = 0; ks < 2; ++ks) {
            uint32_t ah[2][4], w[4][4];
            ldm4(cb + offA[0][ks], ah[0]);
            ldm4(cb + offA[1][ks], ah[1]);
            #pragma unroll
            for (int jp = 0; jp < 4; ++jp)
                ldm4(cb + TILEB + offB[jp][ks], w[jp]);
            #pragma unroll
            for (int mt = 0; mt < 2; ++mt)
                #pragma unroll
                for (int nt = 0; nt < 8; ++nt) {
                    const uint32_t* bw = &w[nt >> 1][(nt & 1) * 2];
                    mma_hf(acc[mt][nt], ah[mt], bw);
                }
        }
        __syncthreads();
    }

    // epilogue: direct stores (quad of 4 threads covers 32B contiguous)
    #pragma unroll
    for (int mt = 0; mt < 2; ++mt)
        #pragma unroll
        for (int nt = 0; nt < 8; ++nt) {
            float* a = acc[mt][nt];
            int col = n0 + nw + nt * 8 + (lane & 3) * 2;
            int r0  = m0 + mw + mt * 16 + (lane >> 2);
            float2 bv = *(const float2*)(bias + col);
            float x0 = a[0] + bv.x, y0 = a[1] + bv.y;
            float x1 = a[2] + bv.x, y1 = a[3] + bv.y;
            if (RELU) {
                x0 = fmaxf(x0, 0.f); y0 = fmaxf(y0, 0.f);
                x1 = fmaxf(x1, 0.f); y1 = fmaxf(y1, 0.f);
            }
            if (!SPLITOUT) {
                float2 v0 = {x0, y0}, v1 = {x1, y1};
                *(float2*)(C + (size_t)r0 * N + col) = v0;
                *(float2*)(C + (size_t)(r0 + 8) * N + col) = v1;
            } else {
                *(uint32_t*)(Ch + (size_t)r0 * N + col) =
                    pk2h(__float2half_rn(x0), __float2half_rn(y0));
                *(uint32_t*)(Ch + (size_t)(r0 + 8) * N + col) =
                    pk2h(__float2half_rn(x1), __float2half_rn(y1));
            }
        }
}

// ---------------- mask + compaction (1 warp per batch) ---------------------------
__global__ void mask_kernel(const int* __restrict__ ids,
                            const int* __restrict__ sotp,
                            const int* __restrict__ eotp)
{
    int b = blockIdx.x;
    int lane = threadIdx.x;
    int sot = *sotp, eot = *eotp;
    const int* row = ids + b * Sn;
    int base = lane * 64;

    unsigned a = 0u, bb = 1u, anyeot = 0u;
    for (int i = 0; i < 64; ++i) {
        int t = row[base + i];
        unsigned iso = (t == sot) ? 1u : 0u;
        unsigned ieo = (t == eot) ? 1u : 0u;
        a = iso | (a & (1u - ieo));
        bb = bb & (1u - ieo);
        anyeot |= ieo;
    }
    unsigned ai = a, bi = bb;
    for (int off = 1; off < 32; off <<= 1) {
        unsigned ap = __shfl_up_sync(0xffffffffu, ai, off);
        unsigned bp = __shfl_up_sync(0xffffffffu, bi, off);
        if (lane >= off) { ai = ai | (ap & bi); bi = bi & bp; }
    }
    unsigned s_in = __shfl_up_sync(0xffffffffu, ai, 1);
    if (lane == 0) s_in = 0u;

    unsigned sfx = anyeot;
    for (int off = 1; off < 32; off <<= 1) {
        unsigned v = __shfl_down_sync(0xffffffffu, sfx, off);
        if (lane + off < 32) sfx |= v;
    }
    unsigned after = __shfl_down_sync(0xffffffffu, sfx, 1);
    if (lane == 31) after = 0u;

    unsigned long long openbits = 0ull;
    unsigned s = s_in;
    for (int i = 0; i < 64; ++i) {
        int t = row[base + i];
        unsigned iso = (t == sot) ? 1u : 0u;
        unsigned ieo = (t == eot) ? 1u : 0u;
        unsigned o = iso | s;
        openbits |= ((unsigned long long)o) << i;
        s = iso | (s & (1u - ieo));
    }
    unsigned long long tbits = 0ull;
    unsigned seen = after;
    for (int i = 63; i >= 0; --i) {
        int t = row[base + i];
        if (t == eot) seen = 1u;
        if (((openbits >> i) & 1ull) && seen) tbits |= (1ull << i);
    }
    int c = __popcll(tbits);
    int pre = c;
    for (int off = 1; off < 32; off <<= 1) {
        int v = __shfl_up_sync(0xffffffffu, pre, off);
        if (lane >= off) pre += v;
    }
    int excl = pre - c;
    int total = __shfl_sync(0xffffffffu, pre, 31);
    if (lane == 31) g_tcnt[b] = total;
    int o = excl;
    for (int i = 0; i < 64; ++i) {
        if ((tbits >> i) & 1ull) g_tidx[b * Sn + (o++)] = base + i;
    }
}

// ---------------- gather thought rows: fp32 + fp16 --------------------------------
__global__ void gather_kernel(const float* __restrict__ x)
{
    int b = blockIdx.y, i = blockIdx.x;
    if (i >= g_tcnt[b]) return;
    int src = b * Sn + g_tidx[b * Sn + i];
    int t = threadIdx.x;
    float4 v = ((const float4*)(x + (size_t)src * Dn))[t];
    size_t rb = (size_t)(b * Sn + i) * Dn;
    ((float4*)(g_Xc + rb))[t] = v;
    ((uint2*)(g_Xc_h + rb))[t] = cvt4h(v);
}

// ---------------- attention over compacted thought rows ---------------------------
__global__ void __launch_bounds__(256) attn_kernel()
{
    int b = blockIdx.z, h = blockIdx.y, qt = blockIdx.x;
    int nT = g_tcnt[b];
    if (qt * 8 >= nT) return;

    __shared__ float Ks[128][33];
    __shared__ float Vs[32][128];
    __shared__ float Qs[8][128];

    int tid = threadIdx.x, warp = tid >> 5, lane = tid & 31;
    int q = qt * 8 + warp;
    bool qv = q < nT;
    if (qv) {
        const float* qr = g_qkv + (size_t)(b*Sn + q) * (3*Dn) + h * DHn;
#pragma unroll
        for (int c = 0; c < 4; ++c) Qs[warp][lane + 32*c] = qr[lane + 32*c];
    }

    float m = -1e30f, lsum = 0.f;
    float acc[4] = {0.f, 0.f, 0.f, 0.f};
    const float scale = 0.088388347648318447f;

    for (int j0 = 0; j0 < nT; j0 += 32) {
        int jn = min(32, nT - j0);
        __syncthreads();
        for (int idx = tid; idx < 32*128; idx += 256) {
            int j = idx >> 7, d = idx & 127;
            float kv = 0.f, vv = 0.f;
            if (j < jn) {
                const float* kr = g_qkv + (size_t)(b*Sn + j0 + j)*(3*Dn) + Dn + h*DHn;
                kv = kr[d];
                vv = kr[Dn + d];
            }
            Ks[d][j] = kv;
            Vs[j][d] = vv;
        }
        __syncthreads();
        if (qv) {
            float s = 0.f;
#pragma unroll 8
            for (int d = 0; d < 128; ++d) s += Qs[warp][d] * Ks[d][lane];
            s *= scale;
            if (lane >= jn) s = -1e30f;
            float smax = s;
#pragma unroll
            for (int off = 16; off; off >>= 1)
                smax = fmaxf(smax, __shfl_xor_sync(0xffffffffu, smax, off));
            float mnew = fmaxf(m, smax);
            float p = (lane < jn) ? __expf(s - mnew) : 0.f;
            float ps = p;
#pragma unroll
            for (int off = 16; off; off >>= 1)
                ps += __shfl_xor_sync(0xffffffffu, ps, off);
            float corr = __expf(m - mnew);
            lsum = lsum * corr + ps;
#pragma unroll
            for (int c = 0; c < 4; ++c) acc[c] *= corr;
            for (int j = 0; j < jn; ++j) {
                float pj = __shfl_sync(0xffffffffu, p, j);
#pragma unroll
                for (int c = 0; c < 4; ++c) acc[c] += pj * Vs[j][lane + 32*c];
            }
            m = mnew;
        }
    }
    if (qv) {
        float inv = 1.f / lsum;
        size_t rb = (size_t)(b*Sn + q) * Dn + h * DHn;
#pragma unroll
        for (int c = 0; c < 4; ++c)
            g_ctx_h[rb + lane + 32*c] = __float2half_rn(acc[c] * inv);
    }
}

// ---------------- block reduction helper ------------------------------------------
__device__ __forceinline__ float block_sum256(float v, float* red)
{
    int lane = threadIdx.x & 31, warp = threadIdx.x >> 5;
#pragma unroll
    for (int off = 16; off; off >>= 1) v += __shfl_xor_sync(0xffffffffu, v, off);
    if (lane == 0) red[warp] = v;
    __syncthreads();
    if (warp == 0) {
        float t = (lane < 8) ? red[lane] : 0.f;
#pragma unroll
        for (int off = 4; off; off >>= 1) t += __shfl_xor_sync(0xffffffffu, t, off);
        if (lane == 0) red[0] = t;
    }
    __syncthreads();
    float r = red[0];
    __syncthreads();
    return r;
}

// ---------------- fused residual-add + LayerNorm (+ optional fp16 out) ------------
__global__ void __launch_bounds__(256) add_ln_kernel(
    const float* __restrict__ X, const float* __restrict__ Y,
    const float* __restrict__ g, const float* __restrict__ be,
    float* __restrict__ out, __half* __restrict__ oh, int use_cnt)
{
    int r = blockIdx.x;
    if (use_cnt) { int b = r >> 11; if ((r & 2047) >= g_tcnt[b]) return; }
    __shared__ float red[8];
    int t = threadIdx.x;
    float4 xv = ((const float4*)(X + (size_t)r * Dn))[t];
    float4 yv = ((const float4*)(Y + (size_t)r * Dn))[t];
    float v0 = xv.x + yv.x, v1 = xv.y + yv.y, v2 = xv.z + yv.z, v3 = xv.w + yv.w;
    float mu = block_sum256(v0 + v1 + v2 + v3, red) * (1.0f / Dn);
    float d0 = v0 - mu, d1 = v1 - mu, d2 = v2 - mu, d3 = v3 - mu;
    float var = block_sum256(d0*d0 + d1*d1 + d2*d2 + d3*d3, red) * (1.0f / Dn);
    float inv = rsqrtf(var + 1e-5f);
    float4 gv = ((const float4*)g)[t];
    float4 bv = ((const float4*)be)[t];
    float4 o;
    o.x = d0 * inv * gv.x + bv.x;
    o.y = d1 * inv * gv.y + bv.y;
    o.z = d2 * inv * gv.z + bv.z;
    o.w = d3 * inv * gv.w + bv.w;
    ((float4*)(out + (size_t)r * Dn))[t] = o;
    if (oh) ((uint2*)(oh + (size_t)r * Dn))[t] = cvt4h(o);
}

// ---------------- cat init: cat = [x | x] (fp16), eff = 0.1 ------------------------
__global__ void init_cat_kernel(const float* __restrict__ x)
{
    int r = blockIdx.x, t = threadIdx.x;
    float4 v = ((const float4*)(x + (size_t)r * Dn))[t];
    uint2 h = cvt4h(v);
    uint2* ch = (uint2*)(g_cat_h + (size_t)r * 2 * Dn);
    ch[t] = h; ch[t + 256] = h;
    if (t == 0) g_eff[r] = 0.1f;
}

// ---------------- scatter x2 into cat[:, D:] (fp16) + gate --------------------------
__global__ void __launch_bounds__(256) scatter_kernel(
    const float* __restrict__ Wg, const float* __restrict__ bg)
{
    int b = blockIdx.y, i = blockIdx.x;
    if (i >= g_tcnt[b]) return;
    __shared__ float red[8];
    int dst = b * Sn + g_tidx[b * Sn + i];
    int t = threadIdx.x;
    float4 v = ((const float4*)(g_x2 + (size_t)(b*Sn + i) * Dn))[t];
    ((uint2*)(g_cat_h + (size_t)dst * 2 * Dn + Dn))[t] = cvt4h(v);
    float4 w = ((const float4*)Wg)[t];
    float p = v.x*w.x + v.y*w.y + v.z*w.z + v.w*w.w;
    float tot = block_sum256(p, red);
    if (t == 0) g_eff[dst] = 1.f / (1.f + __expf(-(tot + bg[0])));
}

// ---------------- mix: mixed = (1-eff)*x + eff*mixed_ctx (fp16 out) -----------------
__global__ void mix_kernel(const float* __restrict__ x)
{
    int r = blockIdx.x, t = threadIdx.x;
    float e = g_eff[r];
    float4 xv = ((const float4*)(x + (size_t)r * Dn))[t];
    float4 mc = ((const float4*)(g_mctx + (size_t)r * Dn))[t];
    float4 o;
    o.x = (1.f - e) * xv.x + e * mc.x;
    o.y = (1.f - e) * xv.y + e * mc.y;
    o.z = (1.f - e) * xv.z + e * mc.z;
    o.w = (1.f - e) * xv.w + e * mc.w;
    ((uint2*)(g_mix_h + (size_t)r * Dn))[t] = cvt4h(o);
}

// ---------------- launch ------------------------------------------------------------
#define SYM(p, s) cudaGetSymbolAddress((void**)&p, s)

extern "C" void kernel_launch(void* const* d_in, const int* in_sizes, int n_in,
                              void* d_out, int out_size)
{
    const float* x    = (const float*)d_in[0];
    const int*   ids  = (const int*)d_in[1];
    const int*   sot  = (const int*)d_in[2];
    const int*   eot  = (const int*)d_in[3];
    const float* Wqkv = (const float*)d_in[4];
    const float* bqkv = (const float*)d_in[5];
    const float* Wo   = (const float*)d_in[6];
    const float* bo   = (const float*)d_in[7];
    const float* ln1g = (const float*)d_in[8];
    const float* ln1b = (const float*)d_in[9];
    const float* W1   = (const float*)d_in[10];
    const float* b1   = (const float*)d_in[11];
    const float* W2   = (const float*)d_in[12];
    const float* b2   = (const float*)d_in[13];
    const float* ln2g = (const float*)d_in[14];
    const float* ln2b = (const float*)d_in[15];
    const float* Wg   = (const float*)d_in[16];
    const float* bg   = (const float*)d_in[17];
    const float* Wm   = (const float*)d_in[18];
    const float* bm   = (const float*)d_in[19];
    const float* Wout = (const float*)d_in[20];
    const float* bout = (const float*)d_in[21];
    float* out = (float*)d_out;

    float *pXc, *pqkv, *pattno, *px1, *pff, *px2, *pmctx;
    __half *pXch, *pctxh, *px1h, *phffh, *pcath, *pmixh;
    __half *pWqkvh, *pWoh, *pW1h, *pW2h, *pWmh, *pWouth;
    SYM(pXc, g_Xc); SYM(pqkv, g_qkv); SYM(pattno, g_attno); SYM(px1, g_x1);
    SYM(pff, g_ff); SYM(px2, g_x2); SYM(pmctx, g_mctx);
    SYM(pXch, g_Xc_h); SYM(pctxh, g_ctx_h); SYM(px1h, g_x1_h); SYM(phffh, g_hff_h);
    SYM(pcath, g_cat_h); SYM(pmixh, g_mix_h);
    SYM(pWqkvh, g_Wqkv_h); SYM(pWoh, g_Wo_h); SYM(pW1h, g_W1_h); SYM(pW2h, g_W2_h);
    SYM(pWmh, g_Wm_h); SYM(pWouth, g_Wout_h);

    cudaFuncSetAttribute(gemm_hs<false,false>, cudaFuncAttributeMaxDynamicSharedMemorySize, GSMEM);
    cudaFuncSetAttribute(gemm_hs<true,true>,   cudaFuncAttributeMaxDynamicSharedMemorySize, GSMEM);

    // 1. thought mask + compaction
    mask_kernel<<<Bn, 32>>>(ids, sot, eot);
    // 2. convert weights to fp16
    conv_kernel<<<512, 256>>>((const float4*)Wqkv, (uint2*)pWqkvh, 3*Dn*Dn/4);
    conv_kernel<<<256, 256>>>((const float4*)Wo,   (uint2*)pWoh,   Dn*Dn/4);
    conv_kernel<<<512, 256>>>((const float4*)W1,   (uint2*)pW1h,   DFFn*Dn/4);
    conv_kernel<<<512, 256>>>((const float4*)W2,   (uint2*)pW2h,   Dn*DFFn/4);
    conv_kernel<<<512, 256>>>((const float4*)Wm,   (uint2*)pWmh,   Dn*2*Dn/4);
    conv_kernel<<<2048, 256>>>((const float4*)Wout,(uint2*)pWouth, Vn*Dn/4);
    // 3. gather thought rows (fp32 + fp16)
    gather_kernel<<<dim3(Sn, Bn), 256>>>(x);
    // 4. QKV on compacted rows (N=3072, K=1024)
    gemm_hs<false,false><<<32*24, 256, GSMEM>>>(pXch, pWqkvh, bqkv, pqkv, nullptr, 3*Dn, Dn, 1);
    // 5. masked attention == dense attention over compacted keys -> ctx fp16
    attn_kernel<<<dim3(Sn/8, NHEADS, Bn), 256>>>();
    // 6. attention output projection
    gemm_hs<false,false><<<32*8, 256, GSMEM>>>(pctxh, pWoh, bo, pattno, nullptr, Dn, Dn, 1);
    // 7. LN1(x + attn) -> x1 fp32 + fp16
    add_ln_kernel<<<Rn, 256>>>(pXc, pattno, ln1g, ln1b, px1, px1h, 1);
    // 8. FFN up + relu -> hff fp16 directly (N=4096, K=1024)
    gemm_hs<true,true><<<32*32, 256, GSMEM>>>(px1h, pW1h, b1, nullptr, phffh, DFFn, Dn, 1);
    // 9. FFN down (N=1024, K=4096)
    gemm_hs<false,false><<<32*8, 256, GSMEM>>>(phffh, pW2h, b2, pff, nullptr, Dn, DFFn, 1);
    // 10. LN2(x1 + ff) -> x2 fp32
    add_ln_kernel<<<Rn, 256>>>(px1, pff, ln2g, ln2b, px2, nullptr, 1);
    // 11. cat = [x | x] fp16, eff = 0.1
    init_cat_kernel<<<Rn, 256>>>(x);
    // 12. scatter x2 into cat[:, D:] + gate
    scatter_kernel<<<dim3(Sn, Bn), 256>>>(Wg, bg);
    // 13. mixed_ctx = cat @ Wm^T + bm (dense, N=1024, K=2048)
    gemm_hs<false,false><<<32*8, 256, GSMEM>>>(pcath, pWmh, bm, pmctx, nullptr, Dn, 2*Dn, 0);
    // 14. mixed (fp16)
    mix_kernel<<<Rn, 256>>>(x);
    // 15. logits = mixed @ Wout^T + bout (dominant: N=32000, K=1024)
    gemm_hs<false,false><<<32*250, 256, GSMEM>>>(pmixh, pWouth, bout, out, nullptr, Vn, Dn, 0);

    (void)in_sizes; (void)n_in; (void)out_size;
}

// round 6
// speedup vs baseline: 5.9866x; 1.3415x over previous
#include <cuda_runtime.h>
#include <cuda_fp16.h>
#include <cstdint>

// ---------------- problem constants ----------------
#define Bn 2
#define Sn 2048
#define Dn 1024
#define Vn 32000
#define NHEADS 8
#define DHn 128
#define DFFn 4096
#define Rn (Bn*Sn)   // 4096 total rows

// ---------------- fp32 scratch ----------------
__device__ float g_Xc[Rn*Dn];
__device__ float g_qkv[Rn*3*Dn];
__device__ float g_attno[Rn*Dn];
__device__ float g_x1[Rn*Dn];
__device__ float g_ff[Rn*Dn];
__device__ float g_x2[Rn*Dn];
__device__ float g_mctx[Rn*Dn];
__device__ float g_eff[Rn];
__device__ int   g_tidx[Rn];
__device__ int   g_tcnt[Bn];

// ---------------- fp16 planes ---------------------------------
__device__ __align__(16) __half g_Xc_h[Rn*Dn];
__device__ __align__(16) __half g_ctx_h[Rn*Dn];
__device__ __align__(16) __half g_x1_h[Rn*Dn];
__device__ __align__(16) __half g_hff_h[Rn*DFFn];
__device__ __align__(16) __half g_cat_h[Rn*2*Dn];
__device__ __align__(16) __half g_mix_h[Rn*Dn];
__device__ __align__(16) __half g_Wqkv_h[3*Dn*Dn];
__device__ __align__(16) __half g_Wo_h[Dn*Dn];
__device__ __align__(16) __half g_W1_h[DFFn*Dn];
__device__ __align__(16) __half g_W2_h[Dn*DFFn];
__device__ __align__(16) __half g_Wm_h[Dn*2*Dn];
__device__ __align__(16) __half g_Wout_h[Vn*Dn];

// ---------------- helpers -------------------------------------------------------
__device__ __forceinline__ uint32_t smem_u32(const void* p) {
    uint32_t a;
    asm("{ .reg .u64 t; cvta.to.shared.u64 t, %1; cvt.u32.u64 %0, t; }" : "=r"(a) : "l"(p));
    return a;
}
__device__ __forceinline__ uint32_t pk2h(__half a, __half b) {
    return ((uint32_t)__half_as_ushort(b) << 16) | (uint32_t)__half_as_ushort(a);
}
__device__ __forceinline__ uint2 cvt4h(float4 v) {
    uint2 h;
    h.x = pk2h(__float2half_rn(v.x), __float2half_rn(v.y));
    h.y = pk2h(__float2half_rn(v.z), __float2half_rn(v.w));
    return h;
}
__device__ __forceinline__ void cpa16(uint32_t dst, const void* src) {
    asm volatile("cp.async.cg.shared.global [%0], [%1], 16;" :: "r"(dst), "l"(src));
}
__device__ __forceinline__ void cp_commit() {
    asm volatile("cp.async.commit_group;" ::: "memory");
}
template<int N>
__device__ __forceinline__ void cp_wait() {
    asm volatile("cp.async.wait_group %0;" :: "n"(N) : "memory");
}
__device__ __forceinline__ void ldm4(uint32_t addr, uint32_t* r) {
    asm volatile("ldmatrix.sync.aligned.m8n8.x4.shared.b16 {%0,%1,%2,%3}, [%4];"
                 : "=r"(r[0]), "=r"(r[1]), "=r"(r[2]), "=r"(r[3]) : "r"(addr));
}
__device__ __forceinline__ void mma_hf(float* d, const uint32_t* a, const uint32_t* b) {
    asm volatile("mma.sync.aligned.m16n8k16.row.col.f32.f16.f16.f32 "
                 "{%0,%1,%2,%3}, {%4,%5,%6,%7}, {%8,%9}, {%0,%1,%2,%3};"
                 : "+f"(d[0]), "+f"(d[1]), "+f"(d[2]), "+f"(d[3])
                 : "r"(a[0]), "r"(a[1]), "r"(a[2]), "r"(a[3]), "r"(b[0]), "r"(b[1]));
}

// ---------------- weight convert kernel (fp32 -> fp16) ----------------------------
__global__ void conv_kernel(const float4* __restrict__ in, uint2* __restrict__ out, int n4)
{
    for (int i = blockIdx.x * 256 + threadIdx.x; i < n4; i += gridDim.x * 256) {
        out[i] = cvt4h(in[i]);
    }
}

// ---------------- fp16 GEMM: C = A @ W^T + bias -----------------------------------
// A fp16 [M,K], W fp16 [N,K]. BM=128,BN=128,BK=32. 256 thr, 8 warps (4x2).
// 3-stage cp.async pipeline, 2 CTAs/SM.
#define TILEB 10240          // 128 rows * 80B padded stride
#define BUFB  (2*TILEB)      // A | W
#define GSMEM (3*BUFB)       // 61440 (3 stages)

template<bool RELU, bool SPLITOUT>
__global__ void __launch_bounds__(256, 2)
gemm_hs(const __half* __restrict__ A, const __half* __restrict__ W,
        const float* __restrict__ bias, float* __restrict__ C,
        __half* __restrict__ Ch,
        int N, int K, int use_cnt)
{
    int bid = blockIdx.x;
    int m0 = (bid & 31) << 7;
    int n0 = (bid >> 5) << 7;
    if (use_cnt) {
        int b = m0 >> 11;
        if ((m0 & 2047) >= g_tcnt[b]) return;
    }

    extern __shared__ char smraw[];
    uint32_t sb = smem_u32(smraw);
    int tid = threadIdx.x, lane = tid & 31, wid = tid >> 5;
    int mw = (wid & 3) << 5;   // warp m-origin in tile
    int nw = (wid >> 2) << 6;  // warp n-origin in tile

    // cp.async slots: 4 per thread (2 tiles x 2 rows)
    int lr = tid >> 2, seg = tid & 3;
    const __half* src[4];
    uint32_t dsto[4];
    src[0] = A + (size_t)(m0 + lr) * K + seg * 8;        dsto[0] = 0*TILEB + lr*80 + seg*16;
    src[1] = A + (size_t)(m0 + lr + 64) * K + seg * 8;   dsto[1] = 0*TILEB + (lr+64)*80 + seg*16;
    src[2] = W + (size_t)(n0 + lr) * K + seg * 8;        dsto[2] = 1*TILEB + lr*80 + seg*16;
    src[3] = W + (size_t)(n0 + lr + 64) * K + seg * 8;   dsto[3] = 1*TILEB + (lr+64)*80 + seg*16;

    // ldmatrix per-lane offsets
    int am = lane >> 3;
    int arow = ((am & 1) << 3) | (lane & 7);
    int akc = am >> 1;
    uint32_t offA[2][2];
    #pragma unroll
    for (int mt = 0; mt < 2; ++mt)
        #pragma unroll
        for (int ks = 0; ks < 2; ++ks)
            offA[mt][ks] = (uint32_t)((mw + mt*16 + arow) * 80 + (ks*2 + akc) * 16);
    int brow = ((am >> 1) << 3) | (lane & 7);
    int bkc = am & 1;
    uint32_t offB[4][2];
    #pragma unroll
    for (int jp = 0; jp < 4; ++jp)
        #pragma unroll
        for (int ks = 0; ks < 2; ++ks)
            offB[jp][ks] = (uint32_t)((nw + jp*16 + brow) * 80 + (ks*2 + bkc) * 16);

    float acc[2][8][4];
    #pragma unroll
    for (int mt = 0; mt < 2; ++mt)
        #pragma unroll
        for (int nt = 0; nt < 8; ++nt)
            #pragma unroll
            for (int i = 0; i < 4; ++i) acc[mt][nt][i] = 0.f;

    int NC = K >> 5;

    // prefetch chunks 0 and 1 into stages 0,1
    #pragma unroll
    for (int j = 0; j < 4; ++j) cpa16(sb + dsto[j], src[j]);
    cp_commit();
    #pragma unroll
    for (int j = 0; j < 4; ++j) cpa16(sb + BUFB + dsto[j], src[j] + 32);
    cp_commit();

    int slot = 0;      // slot of chunk c
    for (int c = 0; c < NC; ++c) {
        if (c + 1 < NC) cp_wait<1>(); else cp_wait<0>();
        __syncthreads();
        if (c + 2 < NC) {
            // stage slot for c+2 == (slot+2)%3; its old data (chunk c-1) was
            // consumed before the sync above.
            uint32_t nb = sb + (uint32_t)((slot + 2) % 3) * BUFB;
            const int ko = (c + 2) * 32;
            #pragma unroll
            for (int j = 0; j < 4; ++j) cpa16(nb + dsto[j], src[j] + ko);
            cp_commit();
        }
        uint32_t cb = sb + (uint32_t)slot * BUFB;
        #pragma unroll
        for (int ks = 0; ks < 2; ++ks) {
            uint32_t ah[2][4], w[4][4];
            ldm4(cb + offA[0][ks], ah[0]);
            ldm4(cb + offA[1][ks], ah[1]);
            #pragma unroll
            for (int jp = 0; jp < 4; ++jp)
                ldm4(cb + TILEB + offB[jp][ks], w[jp]);
            #pragma unroll
            for (int mt = 0; mt < 2; ++mt)
                #pragma unroll
                for (int nt = 0; nt < 8; ++nt) {
                    const uint32_t* bw = &w[nt >> 1][(nt & 1) * 2];
                    mma_hf(acc[mt][nt], ah[mt], bw);
                }
        }
        slot = (slot + 1) % 3;
    }

    // epilogue
    #pragma unroll
    for (int mt = 0; mt < 2; ++mt)
        #pragma unroll
        for (int nt = 0; nt < 8; ++nt) {
            float* a = acc[mt][nt];
            int col = n0 + nw + nt * 8 + (lane & 3) * 2;
            int r0  = m0 + mw + mt * 16 + (lane >> 2);
            float2 bv = *(const float2*)(bias + col);
            float x0 = a[0] + bv.x, y0 = a[1] + bv.y;
            float x1 = a[2] + bv.x, y1 = a[3] + bv.y;
            if (RELU) {
                x0 = fmaxf(x0, 0.f); y0 = fmaxf(y0, 0.f);
                x1 = fmaxf(x1, 0.f); y1 = fmaxf(y1, 0.f);
            }
            if (!SPLITOUT) {
                float2 v0 = {x0, y0}, v1 = {x1, y1};
                *(float2*)(C + (size_t)r0 * N + col) = v0;
                *(float2*)(C + (size_t)(r0 + 8) * N + col) = v1;
            } else {
                *(uint32_t*)(Ch + (size_t)r0 * N + col) =
                    pk2h(__float2half_rn(x0), __float2half_rn(y0));
                *(uint32_t*)(Ch + (size_t)(r0 + 8) * N + col) =
                    pk2h(__float2half_rn(x1), __float2half_rn(y1));
            }
        }
}

// ---------------- mask + compaction (1 warp per batch) ---------------------------
__global__ void mask_kernel(const int* __restrict__ ids,
                            const int* __restrict__ sotp,
                            const int* __restrict__ eotp)
{
    int b = blockIdx.x;
    int lane = threadIdx.x;
    int sot = *sotp, eot = *eotp;
    const int* row = ids + b * Sn;
    int base = lane * 64;

    unsigned a = 0u, bb = 1u, anyeot = 0u;
    for (int i = 0; i < 64; ++i) {
        int t = row[base + i];
        unsigned iso = (t == sot) ? 1u : 0u;
        unsigned ieo = (t == eot) ? 1u : 0u;
        a = iso | (a & (1u - ieo));
        bb = bb & (1u - ieo);
        anyeot |= ieo;
    }
    unsigned ai = a, bi = bb;
    for (int off = 1; off < 32; off <<= 1) {
        unsigned ap = __shfl_up_sync(0xffffffffu, ai, off);
        unsigned bp = __shfl_up_sync(0xffffffffu, bi, off);
        if (lane >= off) { ai = ai | (ap & bi); bi = bi & bp; }
    }
    unsigned s_in = __shfl_up_sync(0xffffffffu, ai, 1);
    if (lane == 0) s_in = 0u;

    unsigned sfx = anyeot;
    for (int off = 1; off < 32; off <<= 1) {
        unsigned v = __shfl_down_sync(0xffffffffu, sfx, off);
        if (lane + off < 32) sfx |= v;
    }
    unsigned after = __shfl_down_sync(0xffffffffu, sfx, 1);
    if (lane == 31) after = 0u;

    unsigned long long openbits = 0ull;
    unsigned s = s_in;
    for (int i = 0; i < 64; ++i) {
        int t = row[base + i];
        unsigned iso = (t == sot) ? 1u : 0u;
        unsigned ieo = (t == eot) ? 1u : 0u;
        unsigned o = iso | s;
        openbits |= ((unsigned long long)o) << i;
        s = iso | (s & (1u - ieo));
    }
    unsigned long long tbits = 0ull;
    unsigned seen = after;
    for (int i = 63; i >= 0; --i) {
        int t = row[base + i];
        if (t == eot) seen = 1u;
        if (((openbits >> i) & 1ull) && seen) tbits |= (1ull << i);
    }
    int c = __popcll(tbits);
    int pre = c;
    for (int off = 1; off < 32; off <<= 1) {
        int v = __shfl_up_sync(0xffffffffu, pre, off);
        if (lane >= off) pre += v;
    }
    int excl = pre - c;
    int total = __shfl_sync(0xffffffffu, pre, 31);
    if (lane == 31) g_tcnt[b] = total;
    int o = excl;
    for (int i = 0; i < 64; ++i) {
        if ((tbits >> i) & 1ull) g_tidx[b * Sn + (o++)] = base + i;
    }
}

// ---------------- gather thought rows: fp32 + fp16 --------------------------------
__global__ void gather_kernel(const float* __restrict__ x)
{
    int b = blockIdx.y, i = blockIdx.x;
    if (i >= g_tcnt[b]) return;
    int src = b * Sn + g_tidx[b * Sn + i];
    int t = threadIdx.x;
    float4 v = ((const float4*)(x + (size_t)src * Dn))[t];
    size_t rb = (size_t)(b * Sn + i) * Dn;
    ((float4*)(g_Xc + rb))[t] = v;
    ((uint2*)(g_Xc_h + rb))[t] = cvt4h(v);
}

// ---------------- attention over compacted thought rows ---------------------------
// 16 queries per block, 2 per warp (q and q+8). Online softmax, key tiles of 32.
__global__ void __launch_bounds__(256) attn_kernel()
{
    int b = blockIdx.z, h = blockIdx.y, qt = blockIdx.x;
    int nT = g_tcnt[b];
    if (qt * 16 >= nT) return;

    __shared__ float Ks[128][33];
    __shared__ float Vs[32][128];
    __shared__ float Qs[16][132];

    int tid = threadIdx.x, warp = tid >> 5, lane = tid & 31;
    int q0 = qt * 16 + warp;
    int q1 = q0 + 8;
    bool qv0 = q0 < nT, qv1 = q1 < nT;
    if (qv0) {
        const float* qr = g_qkv + (size_t)(b*Sn + q0) * (3*Dn) + h * DHn;
#pragma unroll
        for (int c = 0; c < 4; ++c) Qs[warp][lane + 32*c] = qr[lane + 32*c];
    }
    if (qv1) {
        const float* qr = g_qkv + (size_t)(b*Sn + q1) * (3*Dn) + h * DHn;
#pragma unroll
        for (int c = 0; c < 4; ++c) Qs[warp + 8][lane + 32*c] = qr[lane + 32*c];
    }

    float m0 = -1e30f, l0 = 0.f, m1 = -1e30f, l1 = 0.f;
    float acc0[4] = {0.f, 0.f, 0.f, 0.f};
    float acc1[4] = {0.f, 0.f, 0.f, 0.f};
    const float scale = 0.088388347648318447f;

    for (int j0 = 0; j0 < nT; j0 += 32) {
        int jn = min(32, nT - j0);
        __syncthreads();
        for (int idx = tid; idx < 32*128; idx += 256) {
            int j = idx >> 7, d = idx & 127;
            float kv = 0.f, vv = 0.f;
            if (j < jn) {
                const float* kr = g_qkv + (size_t)(b*Sn + j0 + j)*(3*Dn) + Dn + h*DHn;
                kv = kr[d];
                vv = kr[Dn + d];
            }
            Ks[d][j] = kv;
            Vs[j][d] = vv;
        }
        __syncthreads();

        float s0 = 0.f, s1 = 0.f;
#pragma unroll 8
        for (int d = 0; d < 128; ++d) {
            float kv = Ks[d][lane];
            s0 += Qs[warp][d] * kv;
            s1 += Qs[warp + 8][d] * kv;
        }
        s0 *= scale; s1 *= scale;
        if (lane >= jn) { s0 = -1e30f; s1 = -1e30f; }

        // query 0 softmax update
        float sm = s0;
#pragma unroll
        for (int off = 16; off; off >>= 1)
            sm = fmaxf(sm, __shfl_xor_sync(0xffffffffu, sm, off));
        float mn0 = fmaxf(m0, sm);
        float p0 = (lane < jn) ? __expf(s0 - mn0) : 0.f;
        float ps0 = p0;
#pragma unroll
        for (int off = 16; off; off >>= 1)
            ps0 += __shfl_xor_sync(0xffffffffu, ps0, off);
        float cr0 = __expf(m0 - mn0);
        l0 = l0 * cr0 + ps0;
        m0 = mn0;

        // query 1 softmax update
        sm = s1;
#pragma unroll
        for (int off = 16; off; off >>= 1)
            sm = fmaxf(sm, __shfl_xor_sync(0xffffffffu, sm, off));
        float mn1 = fmaxf(m1, sm);
        float p1 = (lane < jn) ? __expf(s1 - mn1) : 0.f;
        float ps1 = p1;
#pragma unroll
        for (int off = 16; off; off >>= 1)
            ps1 += __shfl_xor_sync(0xffffffffu, ps1, off);
        float cr1 = __expf(m1 - mn1);
        l1 = l1 * cr1 + ps1;
        m1 = mn1;

#pragma unroll
        for (int c = 0; c < 4; ++c) { acc0[c] *= cr0; acc1[c] *= cr1; }
        for (int j = 0; j < jn; ++j) {
            float pj0 = __shfl_sync(0xffffffffu, p0, j);
            float pj1 = __shfl_sync(0xffffffffu, p1, j);
#pragma unroll
            for (int c = 0; c < 4; ++c) {
                float vv = Vs[j][lane + 32*c];
                acc0[c] += pj0 * vv;
                acc1[c] += pj1 * vv;
            }
        }
    }
    if (qv0) {
        float inv = 1.f / l0;
        size_t rb = (size_t)(b*Sn + q0) * Dn + h * DHn;
#pragma unroll
        for (int c = 0; c < 4; ++c)
            g_ctx_h[rb + lane + 32*c] = __float2half_rn(acc0[c] * inv);
    }
    if (qv1) {
        float inv = 1.f / l1;
        size_t rb = (size_t)(b*Sn + q1) * Dn + h * DHn;
#pragma unroll
        for (int c = 0; c < 4; ++c)
            g_ctx_h[rb + lane + 32*c] = __float2half_rn(acc1[c] * inv);
    }
}

// ---------------- block reduction helper ------------------------------------------
__device__ __forceinline__ float block_sum256(float v, float* red)
{
    int lane = threadIdx.x & 31, warp = threadIdx.x >> 5;
#pragma unroll
    for (int off = 16; off; off >>= 1) v += __shfl_xor_sync(0xffffffffu, v, off);
    if (lane == 0) red[warp] = v;
    __syncthreads();
    if (warp == 0) {
        float t = (lane < 8) ? red[lane] : 0.f;
#pragma unroll
        for (int off = 4; off; off >>= 1) t += __shfl_xor_sync(0xffffffffu, t, off);
        if (lane == 0) red[0] = t;
    }
    __syncthreads();
    float r = red[0];
    __syncthreads();
    return r;
}

// ---------------- fused residual-add + LayerNorm (+ optional fp16 out) ------------
__global__ void __launch_bounds__(256) add_ln_kernel(
    const float* __restrict__ X, const float* __restrict__ Y,
    const float* __restrict__ g, const float* __restrict__ be,
    float* __restrict__ out, __half* __restrict__ oh, int use_cnt)
{
    int r = blockIdx.x;
    if (use_cnt) { int b = r >> 11; if ((r & 2047) >= g_tcnt[b]) return; }
    __shared__ float red[8];
    int t = threadIdx.x;
    float4 xv = ((const float4*)(X + (size_t)r * Dn))[t];
    float4 yv = ((const float4*)(Y + (size_t)r * Dn))[t];
    float v0 = xv.x + yv.x, v1 = xv.y + yv.y, v2 = xv.z + yv.z, v3 = xv.w + yv.w;
    float mu = block_sum256(v0 + v1 + v2 + v3, red) * (1.0f / Dn);
    float d0 = v0 - mu, d1 = v1 - mu, d2 = v2 - mu, d3 = v3 - mu;
    float var = block_sum256(d0*d0 + d1*d1 + d2*d2 + d3*d3, red) * (1.0f / Dn);
    float inv = rsqrtf(var + 1e-5f);
    float4 gv = ((const float4*)g)[t];
    float4 bv = ((const float4*)be)[t];
    float4 o;
    o.x = d0 * inv * gv.x + bv.x;
    o.y = d1 * inv * gv.y + bv.y;
    o.z = d2 * inv * gv.z + bv.z;
    o.w = d3 * inv * gv.w + bv.w;
    ((float4*)(out + (size_t)r * Dn))[t] = o;
    if (oh) ((uint2*)(oh + (size_t)r * Dn))[t] = cvt4h(o);
}

// ---------------- cat init: cat = [x | x] (fp16), eff = 0.1 ------------------------
__global__ void init_cat_kernel(const float* __restrict__ x)
{
    int r = blockIdx.x, t = threadIdx.x;
    float4 v = ((const float4*)(x + (size_t)r * Dn))[t];
    uint2 h = cvt4h(v);
    uint2* ch = (uint2*)(g_cat_h + (size_t)r * 2 * Dn);
    ch[t] = h; ch[t + 256] = h;
    if (t == 0) g_eff[r] = 0.1f;
}

// ---------------- scatter x2 into cat[:, D:] (fp16) + gate --------------------------
__global__ void __launch_bounds__(256) scatter_kernel(
    const float* __restrict__ Wg, const float* __restrict__ bg)
{
    int b = blockIdx.y, i = blockIdx.x;
    if (i >= g_tcnt[b]) return;
    __shared__ float red[8];
    int dst = b * Sn + g_tidx[b * Sn + i];
    int t = threadIdx.x;
    float4 v = ((const float4*)(g_x2 + (size_t)(b*Sn + i) * Dn))[t];
    ((uint2*)(g_cat_h + (size_t)dst * 2 * Dn + Dn))[t] = cvt4h(v);
    float4 w = ((const float4*)Wg)[t];
    float p = v.x*w.x + v.y*w.y + v.z*w.z + v.w*w.w;
    float tot = block_sum256(p, red);
    if (t == 0) g_eff[dst] = 1.f / (1.f + __expf(-(tot + bg[0])));
}

// ---------------- mix: mixed = (1-eff)*x + eff*mixed_ctx (fp16 out) -----------------
__global__ void mix_kernel(const float* __restrict__ x)
{
    int r = blockIdx.x, t = threadIdx.x;
    float e = g_eff[r];
    float4 xv = ((const float4*)(x + (size_t)r * Dn))[t];
    float4 mc = ((const float4*)(g_mctx + (size_t)r * Dn))[t];
    float4 o;
    o.x = (1.f - e) * xv.x + e * mc.x;
    o.y = (1.f - e) * xv.y + e * mc.y;
    o.z = (1.f - e) * xv.z + e * mc.z;
    o.w = (1.f - e) * xv.w + e * mc.w;
    ((uint2*)(g_mix_h + (size_t)r * Dn))[t] = cvt4h(o);
}

// ---------------- launch ------------------------------------------------------------
#define SYM(p, s) cudaGetSymbolAddress((void**)&p, s)

extern "C" void kernel_launch(void* const* d_in, const int* in_sizes, int n_in,
                              void* d_out, int out_size)
{
    const float* x    = (const float*)d_in[0];
    const int*   ids  = (const int*)d_in[1];
    const int*   sot  = (const int*)d_in[2];
    const int*   eot  = (const int*)d_in[3];
    const float* Wqkv = (const float*)d_in[4];
    const float* bqkv = (const float*)d_in[5];
    const float* Wo   = (const float*)d_in[6];
    const float* bo   = (const float*)d_in[7];
    const float* ln1g = (const float*)d_in[8];
    const float* ln1b = (const float*)d_in[9];
    const float* W1   = (const float*)d_in[10];
    const float* b1   = (const float*)d_in[11];
    const float* W2   = (const float*)d_in[12];
    const float* b2   = (const float*)d_in[13];
    const float* ln2g = (const float*)d_in[14];
    const float* ln2b = (const float*)d_in[15];
    const float* Wg   = (const float*)d_in[16];
    const float* bg   = (const float*)d_in[17];
    const float* Wm   = (const float*)d_in[18];
    const float* bm   = (const float*)d_in[19];
    const float* Wout = (const float*)d_in[20];
    const float* bout = (const float*)d_in[21];
    float* out = (float*)d_out;

    float *pXc, *pqkv, *pattno, *px1, *pff, *px2, *pmctx;
    __half *pXch, *pctxh, *px1h, *phffh, *pcath, *pmixh;
    __half *pWqkvh, *pWoh, *pW1h, *pW2h, *pWmh, *pWouth;
    SYM(pXc, g_Xc); SYM(pqkv, g_qkv); SYM(pattno, g_attno); SYM(px1, g_x1);
    SYM(pff, g_ff); SYM(px2, g_x2); SYM(pmctx, g_mctx);
    SYM(pXch, g_Xc_h); SYM(pctxh, g_ctx_h); SYM(px1h, g_x1_h); SYM(phffh, g_hff_h);
    SYM(pcath, g_cat_h); SYM(pmixh, g_mix_h);
    SYM(pWqkvh, g_Wqkv_h); SYM(pWoh, g_Wo_h); SYM(pW1h, g_W1_h); SYM(pW2h, g_W2_h);
    SYM(pWmh, g_Wm_h); SYM(pWouth, g_Wout_h);

    cudaFuncSetAttribute(gemm_hs<false,false>, cudaFuncAttributeMaxDynamicSharedMemorySize, GSMEM);
    cudaFuncSetAttribute(gemm_hs<true,true>,   cudaFuncAttributeMaxDynamicSharedMemorySize, GSMEM);

    // 1. thought mask + compaction
    mask_kernel<<<Bn, 32>>>(ids, sot, eot);
    // 2. convert weights to fp16
    conv_kernel<<<512, 256>>>((const float4*)Wqkv, (uint2*)pWqkvh, 3*Dn*Dn/4);
    conv_kernel<<<256, 256>>>((const float4*)Wo,   (uint2*)pWoh,   Dn*Dn/4);
    conv_kernel<<<512, 256>>>((const float4*)W1,   (uint2*)pW1h,   DFFn*Dn/4);
    conv_kernel<<<512, 256>>>((const float4*)W2,   (uint2*)pW2h,   Dn*DFFn/4);
    conv_kernel<<<512, 256>>>((const float4*)Wm,   (uint2*)pWmh,   Dn*2*Dn/4);
    conv_kernel<<<2048, 256>>>((const float4*)Wout,(uint2*)pWouth, Vn*Dn/4);
    // 3. gather thought rows (fp32 + fp16)
    gather_kernel<<<dim3(Sn, Bn), 256>>>(x);
    // 4. QKV on compacted rows (N=3072, K=1024)
    gemm_hs<false,false><<<32*24, 256, GSMEM>>>(pXch, pWqkvh, bqkv, pqkv, nullptr, 3*Dn, Dn, 1);
    // 5. masked attention == dense attention over compacted keys -> ctx fp16
    attn_kernel<<<dim3(Sn/16, NHEADS, Bn), 256>>>();
    // 6. attention output projection
    gemm_hs<false,false><<<32*8, 256, GSMEM>>>(pctxh, pWoh, bo, pattno, nullptr, Dn, Dn, 1);
    // 7. LN1(x + attn) -> x1 fp32 + fp16
    add_ln_kernel<<<Rn, 256>>>(pXc, pattno, ln1g, ln1b, px1, px1h, 1);
    // 8. FFN up + relu -> hff fp16 directly (N=4096, K=1024)
    gemm_hs<true,true><<<32*32, 256, GSMEM>>>(px1h, pW1h, b1, nullptr, phffh, DFFn, Dn, 1);
    // 9. FFN down (N=1024, K=4096)
    gemm_hs<false,false><<<32*8, 256, GSMEM>>>(phffh, pW2h, b2, pff, nullptr, Dn, DFFn, 1);
    // 10. LN2(x1 + ff) -> x2 fp32
    add_ln_kernel<<<Rn, 256>>>(px1, pff, ln2g, ln2b, px2, nullptr, 1);
    // 11. cat = [x | x] fp16, eff = 0.1
    init_cat_kernel<<<Rn, 256>>>(x);
    // 12. scatter x2 into cat[:, D:] + gate
    scatter_kernel<<<dim3(Sn, Bn), 256>>>(Wg, bg);
    // 13. mixed_ctx = cat @ Wm^T + bm (dense, N=1024, K=2048)
    gemm_hs<false,false><<<32*8, 256, GSMEM>>>(pcath, pWmh, bm, pmctx, nullptr, Dn, 2*Dn, 0);
    // 14. mixed (fp16)
    mix_kernel<<<Rn, 256>>>(x);
    // 15. logits = mixed @ Wout^T + bout (dominant: N=32000, K=1024)
    gemm_hs<false,false><<<32*250, 256, GSMEM>>>(pmixh, pWouth, bout, out, nullptr, Vn, Dn, 0);

    (void)in_sizes; (void)n_in; (void)out_size;
}

// round 7
// speedup vs baseline: 6.5767x; 1.0986x over previous
#include <cuda_runtime.h>
#include <cuda_fp16.h>
#include <cstdint>

// ---------------- problem constants ----------------
#define Bn 2
#define Sn 2048
#define Dn 1024
#define Vn 32000
#define NHEADS 8
#define DHn 128
#define DFFn 4096
#define Rn (Bn*Sn)   // 4096 total rows

// ---------------- fp32 scratch ----------------
__device__ float g_Xc[Rn*Dn];
__device__ float g_qkv[Rn*3*Dn];
__device__ float g_attno[Rn*Dn];
__device__ float g_x1[Rn*Dn];
__device__ float g_ff[Rn*Dn];
__device__ float g_x2[Rn*Dn];
__device__ float g_mctx[Rn*Dn];
__device__ float g_eff[Rn];
__device__ int   g_tidx[Rn];
__device__ int   g_tcnt[Bn];

// ---------------- fp16 planes ---------------------------------
__device__ __align__(16) __half g_Xc_h[Rn*Dn];
__device__ __align__(16) __half g_ctx_h[Rn*Dn];
__device__ __align__(16) __half g_x1_h[Rn*Dn];
__device__ __align__(16) __half g_hff_h[Rn*DFFn];
__device__ __align__(16) __half g_cat_h[Rn*2*Dn];
__device__ __align__(16) __half g_mix_h[Rn*Dn];
__device__ __align__(16) __half g_Wqkv_h[3*Dn*Dn];
__device__ __align__(16) __half g_Wo_h[Dn*Dn];
__device__ __align__(16) __half g_W1_h[DFFn*Dn];
__device__ __align__(16) __half g_W2_h[Dn*DFFn];
__device__ __align__(16) __half g_Wm_h[Dn*2*Dn];
__device__ __align__(16) __half g_Wout_h[Vn*Dn];

// ---------------- helpers -------------------------------------------------------
__device__ __forceinline__ uint32_t smem_u32(const void* p) {
    uint32_t a;
    asm("{ .reg .u64 t; cvta.to.shared.u64 t, %1; cvt.u32.u64 %0, t; }" : "=r"(a) : "l"(p));
    return a;
}
__device__ __forceinline__ uint32_t pk2h(__half a, __half b) {
    return ((uint32_t)__half_as_ushort(b) << 16) | (uint32_t)__half_as_ushort(a);
}
__device__ __forceinline__ uint2 cvt4h(float4 v) {
    uint2 h;
    h.x = pk2h(__float2half_rn(v.x), __float2half_rn(v.y));
    h.y = pk2h(__float2half_rn(v.z), __float2half_rn(v.w));
    return h;
}
__device__ __forceinline__ void cpa16(uint32_t dst, const void* src) {
    asm volatile("cp.async.cg.shared.global [%0], [%1], 16;" :: "r"(dst), "l"(src));
}
__device__ __forceinline__ void cp_commit() {
    asm volatile("cp.async.commit_group;" ::: "memory");
}
template<int N>
__device__ __forceinline__ void cp_wait() {
    asm volatile("cp.async.wait_group %0;" :: "n"(N) : "memory");
}
__device__ __forceinline__ void ldm4(uint32_t addr, uint32_t* r) {
    asm volatile("ldmatrix.sync.aligned.m8n8.x4.shared.b16 {%0,%1,%2,%3}, [%4];"
                 : "=r"(r[0]), "=r"(r[1]), "=r"(r[2]), "=r"(r[3]) : "r"(addr));
}
__device__ __forceinline__ void mma_hf(float* d, const uint32_t* a, const uint32_t* b) {
    asm volatile("mma.sync.aligned.m16n8k16.row.col.f32.f16.f16.f32 "
                 "{%0,%1,%2,%3}, {%4,%5,%6,%7}, {%8,%9}, {%0,%1,%2,%3};"
                 : "+f"(d[0]), "+f"(d[1]), "+f"(d[2]), "+f"(d[3])
                 : "r"(a[0]), "r"(a[1]), "r"(a[2]), "r"(a[3]), "r"(b[0]), "r"(b[1]));
}

// ---------------- weight convert kernel (fp32 -> fp16) ----------------------------
__global__ void conv_kernel(const float4* __restrict__ in, uint2* __restrict__ out, int n4)
{
    for (int i = blockIdx.x * 256 + threadIdx.x; i < n4; i += gridDim.x * 256) {
        out[i] = cvt4h(in[i]);
    }
}

// ---------------- fp16 GEMM: C = A @ W^T + bias -----------------------------------
// A fp16 [M,K], W fp16 [N,K]. BM=128,BN=128,BK=32. 256 thr, 8 warps (4x2).
// 5-stage cp.async pipeline (4 chunks ahead), 2 CTAs/SM.
#define TILEB 10240          // 128 rows * 80B padded stride
#define BUFB  (2*TILEB)      // A | W
#define NSTG  5
#define GSMEM (NSTG*BUFB)    // 102400

template<bool RELU, bool SPLITOUT>
__global__ void __launch_bounds__(256, 2)
gemm_hs(const __half* __restrict__ A, const __half* __restrict__ W,
        const float* __restrict__ bias, float* __restrict__ C,
        __half* __restrict__ Ch,
        int N, int K, int use_cnt)
{
    int bid = blockIdx.x;
    int m0 = (bid & 31) << 7;
    int n0 = (bid >> 5) << 7;
    if (use_cnt) {
        int b = m0 >> 11;
        if ((m0 & 2047) >= g_tcnt[b]) return;
    }

    extern __shared__ char smraw[];
    uint32_t sb = smem_u32(smraw);
    int tid = threadIdx.x, lane = tid & 31, wid = tid >> 5;
    int mw = (wid & 3) << 5;   // warp m-origin in tile
    int nw = (wid >> 2) << 6;  // warp n-origin in tile

    // cp.async slots: 4 per thread (2 tiles x 2 rows)
    int lr = tid >> 2, seg = tid & 3;
    const __half* src[4];
    uint32_t dsto[4];
    src[0] = A + (size_t)(m0 + lr) * K + seg * 8;        dsto[0] = 0*TILEB + lr*80 + seg*16;
    src[1] = A + (size_t)(m0 + lr + 64) * K + seg * 8;   dsto[1] = 0*TILEB + (lr+64)*80 + seg*16;
    src[2] = W + (size_t)(n0 + lr) * K + seg * 8;        dsto[2] = 1*TILEB + lr*80 + seg*16;
    src[3] = W + (size_t)(n0 + lr + 64) * K + seg * 8;   dsto[3] = 1*TILEB + (lr+64)*80 + seg*16;

    // ldmatrix per-lane offsets
    int am = lane >> 3;
    int arow = ((am & 1) << 3) | (lane & 7);
    int akc = am >> 1;
    uint32_t offA[2][2];
    #pragma unroll
    for (int mt = 0; mt < 2; ++mt)
        #pragma unroll
        for (int ks = 0; ks < 2; ++ks)
            offA[mt][ks] = (uint32_t)((mw + mt*16 + arow) * 80 + (ks*2 + akc) * 16);
    int brow = ((am >> 1) << 3) | (lane & 7);
    int bkc = am & 1;
    uint32_t offB[4][2];
    #pragma unroll
    for (int jp = 0; jp < 4; ++jp)
        #pragma unroll
        for (int ks = 0; ks < 2; ++ks)
            offB[jp][ks] = (uint32_t)((nw + jp*16 + brow) * 80 + (ks*2 + bkc) * 16);

    float acc[2][8][4];
    #pragma unroll
    for (int mt = 0; mt < 2; ++mt)
        #pragma unroll
        for (int nt = 0; nt < 8; ++nt)
            #pragma unroll
            for (int i = 0; i < 4; ++i) acc[mt][nt][i] = 0.f;

    int NC = K >> 5;   // K >= 1024, so NC >= 32 > 4

    // prefetch chunks 0..3 into stages 0..3 (one commit group per chunk)
    #pragma unroll
    for (int s = 0; s < 4; ++s) {
        uint32_t nb = sb + (uint32_t)s * BUFB;
        const int ko = s * 32;
        #pragma unroll
        for (int j = 0; j < 4; ++j) cpa16(nb + dsto[j], src[j] + ko);
        cp_commit();
    }

    int slot = 0;       // slot of chunk c (c % NSTG)
    int pslot = 4;      // slot of chunk c+4
    for (int c = 0; c < NC; ++c) {
        cp_wait<3>();        // chunk c's group complete (one group per iteration)
        __syncthreads();     // all warps done with chunk c-1; chunk c visible

        // issue chunk c+4 into pslot (held chunk c-1, now safe); empty commit at tail
        if (c + 4 < NC) {
            uint32_t nb = sb + (uint32_t)pslot * BUFB;
            const int ko = (c + 4) * 32;
            #pragma unroll
            for (int j = 0; j < 4; ++j) cpa16(nb + dsto[j], src[j] + ko);
        }
        cp_commit();

        uint32_t cb = sb + (uint32_t)slot * BUFB;
        #pragma unroll
        for (int ks = 0; ks < 2; ++ks) {
            uint32_t ah[2][4], w[4][4];
            ldm4(cb + offA[0][ks], ah[0]);
            ldm4(cb + offA[1][ks], ah[1]);
            #pragma unroll
            for (int jp = 0; jp < 4; ++jp)
                ldm4(cb + TILEB + offB[jp][ks], w[jp]);
            #pragma unroll
            for (int mt = 0; mt < 2; ++mt)
                #pragma unroll
                for (int nt = 0; nt < 8; ++nt) {
                    const uint32_t* bw = &w[nt >> 1][(nt & 1) * 2];
                    mma_hf(acc[mt][nt], ah[mt], bw);
                }
        }
        slot  = (slot  == NSTG-1) ? 0 : slot  + 1;
        pslot = (pslot == NSTG-1) ? 0 : pslot + 1;
    }

    // epilogue
    #pragma unroll
    for (int mt = 0; mt < 2; ++mt)
        #pragma unroll
        for (int nt = 0; nt < 8; ++nt) {
            float* a = acc[mt][nt];
            int col = n0 + nw + nt * 8 + (lane & 3) * 2;
            int r0  = m0 + mw + mt * 16 + (lane >> 2);
            float2 bv = *(const float2*)(bias + col);
            float x0 = a[0] + bv.x, y0 = a[1] + bv.y;
            float x1 = a[2] + bv.x, y1 = a[3] + bv.y;
            if (RELU) {
                x0 = fmaxf(x0, 0.f); y0 = fmaxf(y0, 0.f);
                x1 = fmaxf(x1, 0.f); y1 = fmaxf(y1, 0.f);
            }
            if (!SPLITOUT) {
                float2 v0 = {x0, y0}, v1 = {x1, y1};
                *(float2*)(C + (size_t)r0 * N + col) = v0;
                *(float2*)(C + (size_t)(r0 + 8) * N + col) = v1;
            } else {
                *(uint32_t*)(Ch + (size_t)r0 * N + col) =
                    pk2h(__float2half_rn(x0), __float2half_rn(y0));
                *(uint32_t*)(Ch + (size_t)(r0 + 8) * N + col) =
                    pk2h(__float2half_rn(x1), __float2half_rn(y1));
            }
        }
}

// ---------------- mask + compaction (1 warp per batch) ---------------------------
__global__ void mask_kernel(const int* __restrict__ ids,
                            const int* __restrict__ sotp,
                            const int* __restrict__ eotp)
{
    int b = blockIdx.x;
    int lane = threadIdx.x;
    int sot = *sotp, eot = *eotp;
    const int* row = ids + b * Sn;
    int base = lane * 64;

    unsigned a = 0u, bb = 1u, anyeot = 0u;
    for (int i = 0; i < 64; ++i) {
        int t = row[base + i];
        unsigned iso = (t == sot) ? 1u : 0u;
        unsigned ieo = (t == eot) ? 1u : 0u;
        a = iso | (a & (1u - ieo));
        bb = bb & (1u - ieo);
        anyeot |= ieo;
    }
    unsigned ai = a, bi = bb;
    for (int off = 1; off < 32; off <<= 1) {
        unsigned ap = __shfl_up_sync(0xffffffffu, ai, off);
        unsigned bp = __shfl_up_sync(0xffffffffu, bi, off);
        if (lane >= off) { ai = ai | (ap & bi); bi = bi & bp; }
    }
    unsigned s_in = __shfl_up_sync(0xffffffffu, ai, 1);
    if (lane == 0) s_in = 0u;

    unsigned sfx = anyeot;
    for (int off = 1; off < 32; off <<= 1) {
        unsigned v = __shfl_down_sync(0xffffffffu, sfx, off);
        if (lane + off < 32) sfx |= v;
    }
    unsigned after = __shfl_down_sync(0xffffffffu, sfx, 1);
    if (lane == 31) after = 0u;

    unsigned long long openbits = 0ull;
    unsigned s = s_in;
    for (int i = 0; i < 64; ++i) {
        int t = row[base + i];
        unsigned iso = (t == sot) ? 1u : 0u;
        unsigned ieo = (t == eot) ? 1u : 0u;
        unsigned o = iso | s;
        openbits |= ((unsigned long long)o) << i;
        s = iso | (s & (1u - ieo));
    }
    unsigned long long tbits = 0ull;
    unsigned seen = after;
    for (int i = 63; i >= 0; --i) {
        int t = row[base + i];
        if (t == eot) seen = 1u;
        if (((openbits >> i) & 1ull) && seen) tbits |= (1ull << i);
    }
    int c = __popcll(tbits);
    int pre = c;
    for (int off = 1; off < 32; off <<= 1) {
        int v = __shfl_up_sync(0xffffffffu, pre, off);
        if (lane >= off) pre += v;
    }
    int excl = pre - c;
    int total = __shfl_sync(0xffffffffu, pre, 31);
    if (lane == 31) g_tcnt[b] = total;
    int o = excl;
    for (int i = 0; i < 64; ++i) {
        if ((tbits >> i) & 1ull) g_tidx[b * Sn + (o++)] = base + i;
    }
}

// ---------------- gather thought rows: fp32 + fp16 --------------------------------
__global__ void gather_kernel(const float* __restrict__ x)
{
    int b = blockIdx.y, i = blockIdx.x;
    if (i >= g_tcnt[b]) return;
    int src = b * Sn + g_tidx[b * Sn + i];
    int t = threadIdx.x;
    float4 v = ((const float4*)(x + (size_t)src * Dn))[t];
    size_t rb = (size_t)(b * Sn + i) * Dn;
    ((float4*)(g_Xc + rb))[t] = v;
    ((uint2*)(g_Xc_h + rb))[t] = cvt4h(v);
}

// ---------------- attention over compacted thought rows ---------------------------
// 16 queries per block, 2 per warp (q and q+8). Online softmax, key tiles of 32.
__global__ void __launch_bounds__(256) attn_kernel()
{
    int b = blockIdx.z, h = blockIdx.y, qt = blockIdx.x;
    int nT = g_tcnt[b];
    if (qt * 16 >= nT) return;

    __shared__ float Ks[128][33];
    __shared__ float Vs[32][128];
    __shared__ float Qs[16][132];

    int tid = threadIdx.x, warp = tid >> 5, lane = tid & 31;
    int q0 = qt * 16 + warp;
    int q1 = q0 + 8;
    bool qv0 = q0 < nT, qv1 = q1 < nT;
    if (qv0) {
        const float* qr = g_qkv + (size_t)(b*Sn + q0) * (3*Dn) + h * DHn;
#pragma unroll
        for (int c = 0; c < 4; ++c) Qs[warp][lane + 32*c] = qr[lane + 32*c];
    }
    if (qv1) {
        const float* qr = g_qkv + (size_t)(b*Sn + q1) * (3*Dn) + h * DHn;
#pragma unroll
        for (int c = 0; c < 4; ++c) Qs[warp + 8][lane + 32*c] = qr[lane + 32*c];
    }

    float m0 = -1e30f, l0 = 0.f, m1 = -1e30f, l1 = 0.f;
    float acc0[4] = {0.f, 0.f, 0.f, 0.f};
    float acc1[4] = {0.f, 0.f, 0.f, 0.f};
    const float scale = 0.088388347648318447f;

    for (int j0 = 0; j0 < nT; j0 += 32) {
        int jn = min(32, nT - j0);
        __syncthreads();
        for (int idx = tid; idx < 32*128; idx += 256) {
            int j = idx >> 7, d = idx & 127;
            float kv = 0.f, vv = 0.f;
            if (j < jn) {
                const float* kr = g_qkv + (size_t)(b*Sn + j0 + j)*(3*Dn) + Dn + h*DHn;
                kv = kr[d];
                vv = kr[Dn + d];
            }
            Ks[d][j] = kv;
            Vs[j][d] = vv;
        }
        __syncthreads();

        float s0 = 0.f, s1 = 0.f;
#pragma unroll 8
        for (int d = 0; d < 128; ++d) {
            float kv = Ks[d][lane];
            s0 += Qs[warp][d] * kv;
            s1 += Qs[warp + 8][d] * kv;
        }
        s0 *= scale; s1 *= scale;
        if (lane >= jn) { s0 = -1e30f; s1 = -1e30f; }

        float sm = s0;
#pragma unroll
        for (int off = 16; off; off >>= 1)
            sm = fmaxf(sm, __shfl_xor_sync(0xffffffffu, sm, off));
        float mn0 = fmaxf(m0, sm);
        float p0 = (lane < jn) ? __expf(s0 - mn0) : 0.f;
        float ps0 = p0;
#pragma unroll
        for (int off = 16; off; off >>= 1)
            ps0 += __shfl_xor_sync(0xffffffffu, ps0, off);
        float cr0 = __expf(m0 - mn0);
        l0 = l0 * cr0 + ps0;
        m0 = mn0;

        sm = s1;
#pragma unroll
        for (int off = 16; off; off >>= 1)
            sm = fmaxf(sm, __shfl_xor_sync(0xffffffffu, sm, off));
        float mn1 = fmaxf(m1, sm);
        float p1 = (lane < jn) ? __expf(s1 - mn1) : 0.f;
        float ps1 = p1;
#pragma unroll
        for (int off = 16; off; off >>= 1)
            ps1 += __shfl_xor_sync(0xffffffffu, ps1, off);
        float cr1 = __expf(m1 - mn1);
        l1 = l1 * cr1 + ps1;
        m1 = mn1;

#pragma unroll
        for (int c = 0; c < 4; ++c) { acc0[c] *= cr0; acc1[c] *= cr1; }
        for (int j = 0; j < jn; ++j) {
            float pj0 = __shfl_sync(0xffffffffu, p0, j);
            float pj1 = __shfl_sync(0xffffffffu, p1, j);
#pragma unroll
            for (int c = 0; c < 4; ++c) {
                float vv = Vs[j][lane + 32*c];
                acc0[c] += pj0 * vv;
                acc1[c] += pj1 * vv;
            }
        }
    }
    if (qv0) {
        float inv = 1.f / l0;
        size_t rb = (size_t)(b*Sn + q0) * Dn + h * DHn;
#pragma unroll
        for (int c = 0; c < 4; ++c)
            g_ctx_h[rb + lane + 32*c] = __float2half_rn(acc0[c] * inv);
    }
    if (qv1) {
        float inv = 1.f / l1;
        size_t rb = (size_t)(b*Sn + q1) * Dn + h * DHn;
#pragma unroll
        for (int c = 0; c < 4; ++c)
            g_ctx_h[rb + lane + 32*c] = __float2half_rn(acc1[c] * inv);
    }
}

// ---------------- block reduction helper ------------------------------------------
__device__ __forceinline__ float block_sum256(float v, float* red)
{
    int lane = threadIdx.x & 31, warp = threadIdx.x >> 5;
#pragma unroll
    for (int off = 16; off; off >>= 1) v += __shfl_xor_sync(0xffffffffu, v, off);
    if (lane == 0) red[warp] = v;
    __syncthreads();
    if (warp == 0) {
        float t = (lane < 8) ? red[lane] : 0.f;
#pragma unroll
        for (int off = 4; off; off >>= 1) t += __shfl_xor_sync(0xffffffffu, t, off);
        if (lane == 0) red[0] = t;
    }
    __syncthreads();
    float r = red[0];
    __syncthreads();
    return r;
}

// ---------------- fused residual-add + LayerNorm (+ optional fp16 out) ------------
__global__ void __launch_bounds__(256) add_ln_kernel(
    const float* __restrict__ X, const float* __restrict__ Y,
    const float* __restrict__ g, const float* __restrict__ be,
    float* __restrict__ out, __half* __restrict__ oh, int use_cnt)
{
    int r = blockIdx.x;
    if (use_cnt) { int b = r >> 11; if ((r & 2047) >= g_tcnt[b]) return; }
    __shared__ float red[8];
    int t = threadIdx.x;
    float4 xv = ((const float4*)(X + (size_t)r * Dn))[t];
    float4 yv = ((const float4*)(Y + (size_t)r * Dn))[t];
    float v0 = xv.x + yv.x, v1 = xv.y + yv.y, v2 = xv.z + yv.z, v3 = xv.w + yv.w;
    float mu = block_sum256(v0 + v1 + v2 + v3, red) * (1.0f / Dn);
    float d0 = v0 - mu, d1 = v1 - mu, d2 = v2 - mu, d3 = v3 - mu;
    float var = block_sum256(d0*d0 + d1*d1 + d2*d2 + d3*d3, red) * (1.0f / Dn);
    float inv = rsqrtf(var + 1e-5f);
    float4 gv = ((const float4*)g)[t];
    float4 bv = ((const float4*)be)[t];
    float4 o;
    o.x = d0 * inv * gv.x + bv.x;
    o.y = d1 * inv * gv.y + bv.y;
    o.z = d2 * inv * gv.z + bv.z;
    o.w = d3 * inv * gv.w + bv.w;
    ((float4*)(out + (size_t)r * Dn))[t] = o;
    if (oh) ((uint2*)(oh + (size_t)r * Dn))[t] = cvt4h(o);
}

// ---------------- cat init: cat = [x | x] (fp16), eff = 0.1 ------------------------
__global__ void init_cat_kernel(const float* __restrict__ x)
{
    int r = blockIdx.x, t = threadIdx.x;
    float4 v = ((const float4*)(x + (size_t)r * Dn))[t];
    uint2 h = cvt4h(v);
    uint2* ch = (uint2*)(g_cat_h + (size_t)r * 2 * Dn);
    ch[t] = h; ch[t + 256] = h;
    if (t == 0) g_eff[r] = 0.1f;
}

// ---------------- scatter x2 into cat[:, D:] (fp16) + gate --------------------------
__global__ void __launch_bounds__(256) scatter_kernel(
    const float* __restrict__ Wg, const float* __restrict__ bg)
{
    int b = blockIdx.y, i = blockIdx.x;
    if (i >= g_tcnt[b]) return;
    __shared__ float red[8];
    int dst = b * Sn + g_tidx[b * Sn + i];
    int t = threadIdx.x;
    float4 v = ((const float4*)(g_x2 + (size_t)(b*Sn + i) * Dn))[t];
    ((uint2*)(g_cat_h + (size_t)dst * 2 * Dn + Dn))[t] = cvt4h(v);
    float4 w = ((const float4*)Wg)[t];
    float p = v.x*w.x + v.y*w.y + v.z*w.z + v.w*w.w;
    float tot = block_sum256(p, red);
    if (t == 0) g_eff[dst] = 1.f / (1.f + __expf(-(tot + bg[0])));
}

// ---------------- mix: mixed = (1-eff)*x + eff*mixed_ctx (fp16 out) -----------------
__global__ void mix_kernel(const float* __restrict__ x)
{
    int r = blockIdx.x, t = threadIdx.x;
    float e = g_eff[r];
    float4 xv = ((const float4*)(x + (size_t)r * Dn))[t];
    float4 mc = ((const float4*)(g_mctx + (size_t)r * Dn))[t];
    float4 o;
    o.x = (1.f - e) * xv.x + e * mc.x;
    o.y = (1.f - e) * xv.y + e * mc.y;
    o.z = (1.f - e) * xv.z + e * mc.z;
    o.w = (1.f - e) * xv.w + e * mc.w;
    ((uint2*)(g_mix_h + (size_t)r * Dn))[t] = cvt4h(o);
}

// ---------------- launch ------------------------------------------------------------
#define SYM(p, s) cudaGetSymbolAddress((void**)&p, s)

extern "C" void kernel_launch(void* const* d_in, const int* in_sizes, int n_in,
                              void* d_out, int out_size)
{
    const float* x    = (const float*)d_in[0];
    const int*   ids  = (const int*)d_in[1];
    const int*   sot  = (const int*)d_in[2];
    const int*   eot  = (const int*)d_in[3];
    const float* Wqkv = (const float*)d_in[4];
    const float* bqkv = (const float*)d_in[5];
    const float* Wo   = (const float*)d_in[6];
    const float* bo   = (const float*)d_in[7];
    const float* ln1g = (const float*)d_in[8];
    const float* ln1b = (const float*)d_in[9];
    const float* W1   = (const float*)d_in[10];
    const float* b1   = (const float*)d_in[11];
    const float* W2   = (const float*)d_in[12];
    const float* b2   = (const float*)d_in[13];
    const float* ln2g = (const float*)d_in[14];
    const float* ln2b = (const float*)d_in[15];
    const float* Wg   = (const float*)d_in[16];
    const float* bg   = (const float*)d_in[17];
    const float* Wm   = (const float*)d_in[18];
    const float* bm   = (const float*)d_in[19];
    const float* Wout = (const float*)d_in[20];
    const float* bout = (const float*)d_in[21];
    float* out = (float*)d_out;

    float *pXc, *pqkv, *pattno, *px1, *pff, *px2, *pmctx;
    __half *pXch, *pctxh, *px1h, *phffh, *pcath, *pmixh;
    __half *pWqkvh, *pWoh, *pW1h, *pW2h, *pWmh, *pWouth;
    SYM(pXc, g_Xc); SYM(pqkv, g_qkv); SYM(pattno, g_attno); SYM(px1, g_x1);
    SYM(pff, g_ff); SYM(px2, g_x2); SYM(pmctx, g_mctx);
    SYM(pXch, g_Xc_h); SYM(pctxh, g_ctx_h); SYM(px1h, g_x1_h); SYM(phffh, g_hff_h);
    SYM(pcath, g_cat_h); SYM(pmixh, g_mix_h);
    SYM(pWqkvh, g_Wqkv_h); SYM(pWoh, g_Wo_h); SYM(pW1h, g_W1_h); SYM(pW2h, g_W2_h);
    SYM(pWmh, g_Wm_h); SYM(pWouth, g_Wout_h);

    cudaFuncSetAttribute(gemm_hs<false,false>, cudaFuncAttributeMaxDynamicSharedMemorySize, GSMEM);
    cudaFuncSetAttribute(gemm_hs<true,true>,   cudaFuncAttributeMaxDynamicSharedMemorySize, GSMEM);

    // one-time stream/event setup (host-side objects; no device allocations)
    static cudaStream_t s1 = nullptr;
    static cudaEvent_t evF = nullptr, evW = nullptr, evR = nullptr;
    if (!s1) {
        cudaStreamCreateWithFlags(&s1, cudaStreamNonBlocking);
        cudaEventCreateWithFlags(&evF, cudaEventDisableTiming);
        cudaEventCreateWithFlags(&evW, cudaEventDisableTiming);
        cudaEventCreateWithFlags(&evR, cudaEventDisableTiming);
    }

    // ---- fork: weight conversions run on s1, overlapping mask/gather/QKV/attn ----
    cudaEventRecord(evF, 0);
    cudaStreamWaitEvent(s1, evF, 0);
    conv_kernel<<<512, 256, 0, s1>>>((const float4*)Wqkv, (uint2*)pWqkvh, 3*Dn*Dn/4);
    cudaEventRecord(evW, s1);   // QKV GEMM depends only on this conv
    conv_kernel<<<256, 256, 0, s1>>>((const float4*)Wo,   (uint2*)pWoh,   Dn*Dn/4);
    conv_kernel<<<512, 256, 0, s1>>>((const float4*)W1,   (uint2*)pW1h,   DFFn*Dn/4);
    conv_kernel<<<512, 256, 0, s1>>>((const float4*)W2,   (uint2*)pW2h,   Dn*DFFn/4);
    conv_kernel<<<512, 256, 0, s1>>>((const float4*)Wm,   (uint2*)pWmh,   Dn*2*Dn/4);
    conv_kernel<<<2048, 256, 0, s1>>>((const float4*)Wout,(uint2*)pWouth, Vn*Dn/4);
    cudaEventRecord(evR, s1);

    // ---- main chain on stream 0 ----
    mask_kernel<<<Bn, 32>>>(ids, sot, eot);
    gather_kernel<<<dim3(Sn, Bn), 256>>>(x);
    cudaStreamWaitEvent(0, evW, 0);
    // QKV on compacted rows (N=3072, K=1024)
    gemm_hs<false,false><<<32*24, 256, GSMEM>>>(pXch, pWqkvh, bqkv, pqkv, nullptr, 3*Dn, Dn, 1);
    // masked attention == dense attention over compacted keys -> ctx fp16
    attn_kernel<<<dim3(Sn/16, NHEADS, Bn), 256>>>();
    cudaStreamWaitEvent(0, evR, 0);   // join remaining convs before their uses
    // attention output projection
    gemm_hs<false,false><<<32*8, 256, GSMEM>>>(pctxh, pWoh, bo, pattno, nullptr, Dn, Dn, 1);
    // LN1(x + attn) -> x1 fp32 + fp16
    add_ln_kernel<<<Rn, 256>>>(pXc, pattno, ln1g, ln1b, px1, px1h, 1);
    // FFN up + relu -> hff fp16 directly (N=4096, K=1024)
    gemm_hs<true,true><<<32*32, 256, GSMEM>>>(px1h, pW1h, b1, nullptr, phffh, DFFn, Dn, 1);
    // FFN down (N=1024, K=4096)
    gemm_hs<false,false><<<32*8, 256, GSMEM>>>(phffh, pW2h, b2, pff, nullptr, Dn, DFFn, 1);
    // LN2(x1 + ff) -> x2 fp32
    add_ln_kernel<<<Rn, 256>>>(px1, pff, ln2g, ln2b, px2, nullptr, 1);
    // cat = [x | x] fp16, eff = 0.1
    init_cat_kernel<<<Rn, 256>>>(x);
    // scatter x2 into cat[:, D:] + gate
    scatter_kernel<<<dim3(Sn, Bn), 256>>>(Wg, bg);
    // mixed_ctx = cat @ Wm^T + bm (dense, N=1024, K=2048)
    gemm_hs<false,false><<<32*8, 256, GSMEM>>>(pcath, pWmh, bm, pmctx, nullptr, Dn, 2*Dn, 0);
    // mixed (fp16)
    mix_kernel<<<Rn, 256>>>(x);
    // logits = mixed @ Wout^T + bout (dominant: N=32000, K=1024)
    gemm_hs<false,false><<<32*250, 256, GSMEM>>>(pmixh, pWouth, bout, out, nullptr, Vn, Dn, 0);

    (void)in_sizes; (void)n_in; (void)out_size;
}

// round 8
// speedup vs baseline: 6.6071x; 1.0046x over previous
#include <cuda_runtime.h>
#include <cuda_fp16.h>
#include <cstdint>

// ---------------- problem constants ----------------
#define Bn 2
#define Sn 2048
#define Dn 1024
#define Vn 32000
#define NHEADS 8
#define DHn 128
#define DFFn 4096
#define Rn (Bn*Sn)   // 4096 total rows

// ---------------- fp32 scratch ----------------
__device__ float g_Xc[Rn*Dn];
__device__ float g_qkv[Rn*3*Dn];
__device__ float g_attno[Rn*Dn];
__device__ float g_x1[Rn*Dn];
__device__ float g_ff[Rn*Dn];
__device__ float g_x2[Rn*Dn];
__device__ float g_eff[Rn];
__device__ int   g_tidx[Rn];
__device__ int   g_tcnt[Bn];

// ---------------- fp16 planes ---------------------------------
__device__ __align__(16) __half g_Xc_h[Rn*Dn];
__device__ __align__(16) __half g_ctx_h[Rn*Dn];
__device__ __align__(16) __half g_x1_h[Rn*Dn];
__device__ __align__(16) __half g_hff_h[Rn*DFFn];
__device__ __align__(16) __half g_cat_h[Rn*2*Dn];
__device__ __align__(16) __half g_mix_h[Rn*Dn];
__device__ __align__(16) __half g_Wqkv_h[3*Dn*Dn];
__device__ __align__(16) __half g_Wo_h[Dn*Dn];
__device__ __align__(16) __half g_W1_h[DFFn*Dn];
__device__ __align__(16) __half g_W2_h[Dn*DFFn];
__device__ __align__(16) __half g_Wm_h[Dn*2*Dn];
__device__ __align__(16) __half g_Wout_h[Vn*Dn];

// ---------------- helpers -------------------------------------------------------
__device__ __forceinline__ uint32_t smem_u32(const void* p) {
    uint32_t a;
    asm("{ .reg .u64 t; cvta.to.shared.u64 t, %1; cvt.u32.u64 %0, t; }" : "=r"(a) : "l"(p));
    return a;
}
__device__ __forceinline__ uint32_t pk2h(__half a, __half b) {
    return ((uint32_t)__half_as_ushort(b) << 16) | (uint32_t)__half_as_ushort(a);
}
__device__ __forceinline__ uint2 cvt4h(float4 v) {
    uint2 h;
    h.x = pk2h(__float2half_rn(v.x), __float2half_rn(v.y));
    h.y = pk2h(__float2half_rn(v.z), __float2half_rn(v.w));
    return h;
}
__device__ __forceinline__ void cpa16(uint32_t dst, const void* src) {
    asm volatile("cp.async.cg.shared.global [%0], [%1], 16;" :: "r"(dst), "l"(src));
}
__device__ __forceinline__ void cp_commit() {
    asm volatile("cp.async.commit_group;" ::: "memory");
}
template<int N>
__device__ __forceinline__ void cp_wait() {
    asm volatile("cp.async.wait_group %0;" :: "n"(N) : "memory");
}
__device__ __forceinline__ void ldm4(uint32_t addr, uint32_t* r) {
    asm volatile("ldmatrix.sync.aligned.m8n8.x4.shared.b16 {%0,%1,%2,%3}, [%4];"
                 : "=r"(r[0]), "=r"(r[1]), "=r"(r[2]), "=r"(r[3]) : "r"(addr));
}
__device__ __forceinline__ void mma_hf(float* d, const uint32_t* a, const uint32_t* b) {
    asm volatile("mma.sync.aligned.m16n8k16.row.col.f32.f16.f16.f32 "
                 "{%0,%1,%2,%3}, {%4,%5,%6,%7}, {%8,%9}, {%0,%1,%2,%3};"
                 : "+f"(d[0]), "+f"(d[1]), "+f"(d[2]), "+f"(d[3])
                 : "r"(a[0]), "r"(a[1]), "r"(a[2]), "r"(a[3]), "r"(b[0]), "r"(b[1]));
}

// ---------------- weight convert kernel (fp32 -> fp16) ----------------------------
__global__ void conv_kernel(const float4* __restrict__ in, uint2* __restrict__ out, int n4)
{
    for (int i = blockIdx.x * 256 + threadIdx.x; i < n4; i += gridDim.x * 256) {
        out[i] = cvt4h(in[i]);
    }
}

// ---------------- fp16 GEMM: C = A @ W^T + bias -----------------------------------
// A fp16 [M,K], W fp16 [N,K]. BM=128,BN=128,BK=32. 256 thr, 8 warps (4x2).
// 5-stage cp.async pipeline (4 chunks ahead), 2 CTAs/SM.
// MIXOUT: write fp16 ((1-eff)*Xin + eff*(acc+bias)) to Ch instead.
#define TILEB 10240          // 128 rows * 80B padded stride
#define BUFB  (2*TILEB)      // A | W
#define NSTG  5
#define GSMEM (NSTG*BUFB)    // 102400

template<bool RELU, bool SPLITOUT, bool MIXOUT>
__global__ void __launch_bounds__(256, 2)
gemm_hs(const __half* __restrict__ A, const __half* __restrict__ W,
        const float* __restrict__ bias, float* __restrict__ C,
        __half* __restrict__ Ch,
        const float* __restrict__ Xin,
        int N, int K, int use_cnt)
{
    int bid = blockIdx.x;
    int m0 = (bid & 31) << 7;
    int n0 = (bid >> 5) << 7;
    if (use_cnt) {
        int b = m0 >> 11;
        if ((m0 & 2047) >= g_tcnt[b]) return;
    }

    extern __shared__ char smraw[];
    uint32_t sb = smem_u32(smraw);
    int tid = threadIdx.x, lane = tid & 31, wid = tid >> 5;
    int mw = (wid & 3) << 5;   // warp m-origin in tile
    int nw = (wid >> 2) << 6;  // warp n-origin in tile

    // cp.async slots: 4 per thread (2 tiles x 2 rows)
    int lr = tid >> 2, seg = tid & 3;
    const __half* src[4];
    uint32_t dsto[4];
    src[0] = A + (size_t)(m0 + lr) * K + seg * 8;        dsto[0] = 0*TILEB + lr*80 + seg*16;
    src[1] = A + (size_t)(m0 + lr + 64) * K + seg * 8;   dsto[1] = 0*TILEB + (lr+64)*80 + seg*16;
    src[2] = W + (size_t)(n0 + lr) * K + seg * 8;        dsto[2] = 1*TILEB + lr*80 + seg*16;
    src[3] = W + (size_t)(n0 + lr + 64) * K + seg * 8;   dsto[3] = 1*TILEB + (lr+64)*80 + seg*16;

    // ldmatrix per-lane offsets
    int am = lane >> 3;
    int arow = ((am & 1) << 3) | (lane & 7);
    int akc = am >> 1;
    uint32_t offA[2][2];
    #pragma unroll
    for (int mt = 0; mt < 2; ++mt)
        #pragma unroll
        for (int ks = 0; ks < 2; ++ks)
            offA[mt][ks] = (uint32_t)((mw + mt*16 + arow) * 80 + (ks*2 + akc) * 16);
    int brow = ((am >> 1) << 3) | (lane & 7);
    int bkc = am & 1;
    uint32_t offB[4][2];
    #pragma unroll
    for (int jp = 0; jp < 4; ++jp)
        #pragma unroll
        for (int ks = 0; ks < 2; ++ks)
            offB[jp][ks] = (uint32_t)((nw + jp*16 + brow) * 80 + (ks*2 + bkc) * 16);

    float acc[2][8][4];
    #pragma unroll
    for (int mt = 0; mt < 2; ++mt)
        #pragma unroll
        for (int nt = 0; nt < 8; ++nt)
            #pragma unroll
            for (int i = 0; i < 4; ++i) acc[mt][nt][i] = 0.f;

    int NC = K >> 5;   // K >= 1024 => NC >= 32 > 4

    // prefetch chunks 0..3 into stages 0..3 (one commit group per chunk)
    #pragma unroll
    for (int s = 0; s < 4; ++s) {
        uint32_t nb = sb + (uint32_t)s * BUFB;
        const int ko = s * 32;
        #pragma unroll
        for (int j = 0; j < 4; ++j) cpa16(nb + dsto[j], src[j] + ko);
        cp_commit();
    }

    int slot = 0;       // slot of chunk c (c % NSTG)
    int pslot = 4;      // slot of chunk c+4
    for (int c = 0; c < NC; ++c) {
        cp_wait<3>();        // chunk c's group complete (one group per iteration)
        __syncthreads();     // all warps done with chunk c-1; chunk c visible

        if (c + 4 < NC) {
            uint32_t nb = sb + (uint32_t)pslot * BUFB;
            const int ko = (c + 4) * 32;
            #pragma unroll
            for (int j = 0; j < 4; ++j) cpa16(nb + dsto[j], src[j] + ko);
        }
        cp_commit();

        uint32_t cb = sb + (uint32_t)slot * BUFB;
        #pragma unroll
        for (int ks = 0; ks < 2; ++ks) {
            uint32_t ah[2][4], w[4][4];
            ldm4(cb + offA[0][ks], ah[0]);
            ldm4(cb + offA[1][ks], ah[1]);
            #pragma unroll
            for (int jp = 0; jp < 4; ++jp)
                ldm4(cb + TILEB + offB[jp][ks], w[jp]);
            #pragma unroll
            for (int mt = 0; mt < 2; ++mt)
                #pragma unroll
                for (int nt = 0; nt < 8; ++nt) {
                    const uint32_t* bw = &w[nt >> 1][(nt & 1) * 2];
                    mma_hf(acc[mt][nt], ah[mt], bw);
                }
        }
        slot  = (slot  == NSTG-1) ? 0 : slot  + 1;
        pslot = (pslot == NSTG-1) ? 0 : pslot + 1;
    }

    // epilogue
    #pragma unroll
    for (int mt = 0; mt < 2; ++mt)
        #pragma unroll
        for (int nt = 0; nt < 8; ++nt) {
            float* a = acc[mt][nt];
            int col = n0 + nw + nt * 8 + (lane & 3) * 2;
            int r0  = m0 + mw + mt * 16 + (lane >> 2);
            float2 bv = *(const float2*)(bias + col);
            float x0 = a[0] + bv.x, y0 = a[1] + bv.y;
            float x1 = a[2] + bv.x, y1 = a[3] + bv.y;
            if (RELU) {
                x0 = fmaxf(x0, 0.f); y0 = fmaxf(y0, 0.f);
                x1 = fmaxf(x1, 0.f); y1 = fmaxf(y1, 0.f);
            }
            if (MIXOUT) {
                float e0 = g_eff[r0], e1 = g_eff[r0 + 8];
                float2 xa = *(const float2*)(Xin + (size_t)r0 * N + col);
                float2 xb = *(const float2*)(Xin + (size_t)(r0 + 8) * N + col);
                x0 = (1.f - e0) * xa.x + e0 * x0;
                y0 = (1.f - e0) * xa.y + e0 * y0;
                x1 = (1.f - e1) * xb.x + e1 * x1;
                y1 = (1.f - e1) * xb.y + e1 * y1;
                *(uint32_t*)(Ch + (size_t)r0 * N + col) =
                    pk2h(__float2half_rn(x0), __float2half_rn(y0));
                *(uint32_t*)(Ch + (size_t)(r0 + 8) * N + col) =
                    pk2h(__float2half_rn(x1), __float2half_rn(y1));
            } else if (SPLITOUT) {
                *(uint32_t*)(Ch + (size_t)r0 * N + col) =
                    pk2h(__float2half_rn(x0), __float2half_rn(y0));
                *(uint32_t*)(Ch + (size_t)(r0 + 8) * N + col) =
                    pk2h(__float2half_rn(x1), __float2half_rn(y1));
            } else {
                float2 v0 = {x0, y0}, v1 = {x1, y1};
                *(float2*)(C + (size_t)r0 * N + col) = v0;
                *(float2*)(C + (size_t)(r0 + 8) * N + col) = v1;
            }
        }
}

// ---------------- mask + compaction (1 warp per batch) ---------------------------
__global__ void mask_kernel(const int* __restrict__ ids,
                            const int* __restrict__ sotp,
                            const int* __restrict__ eotp)
{
    int b = blockIdx.x;
    int lane = threadIdx.x;
    int sot = *sotp, eot = *eotp;
    const int* row = ids + b * Sn;
    int base = lane * 64;

    unsigned a = 0u, bb = 1u, anyeot = 0u;
    for (int i = 0; i < 64; ++i) {
        int t = row[base + i];
        unsigned iso = (t == sot) ? 1u : 0u;
        unsigned ieo = (t == eot) ? 1u : 0u;
        a = iso | (a & (1u - ieo));
        bb = bb & (1u - ieo);
        anyeot |= ieo;
    }
    unsigned ai = a, bi = bb;
    for (int off = 1; off < 32; off <<= 1) {
        unsigned ap = __shfl_up_sync(0xffffffffu, ai, off);
        unsigned bp = __shfl_up_sync(0xffffffffu, bi, off);
        if (lane >= off) { ai = ai | (ap & bi); bi = bi & bp; }
    }
    unsigned s_in = __shfl_up_sync(0xffffffffu, ai, 1);
    if (lane == 0) s_in = 0u;

    unsigned sfx = anyeot;
    for (int off = 1; off < 32; off <<= 1) {
        unsigned v = __shfl_down_sync(0xffffffffu, sfx, off);
        if (lane + off < 32) sfx |= v;
    }
    unsigned after = __shfl_down_sync(0xffffffffu, sfx, 1);
    if (lane == 31) after = 0u;

    unsigned long long openbits = 0ull;
    unsigned s = s_in;
    for (int i = 0; i < 64; ++i) {
        int t = row[base + i];
        unsigned iso = (t == sot) ? 1u : 0u;
        unsigned ieo = (t == eot) ? 1u : 0u;
        unsigned o = iso | s;
        openbits |= ((unsigned long long)o) << i;
        s = iso | (s & (1u - ieo));
    }
    unsigned long long tbits = 0ull;
    unsigned seen = after;
    for (int i = 63; i >= 0; --i) {
        int t = row[base + i];
        if (t == eot) seen = 1u;
        if (((openbits >> i) & 1ull) && seen) tbits |= (1ull << i);
    }
    int c = __popcll(tbits);
    int pre = c;
    for (int off = 1; off < 32; off <<= 1) {
        int v = __shfl_up_sync(0xffffffffu, pre, off);
        if (lane >= off) pre += v;
    }
    int excl = pre - c;
    int total = __shfl_sync(0xffffffffu, pre, 31);
    if (lane == 31) g_tcnt[b] = total;
    int o = excl;
    for (int i = 0; i < 64; ++i) {
        if ((tbits >> i) & 1ull) g_tidx[b * Sn + (o++)] = base + i;
    }
}

// ---------------- gather thought rows: fp32 + fp16 --------------------------------
__global__ void gather_kernel(const float* __restrict__ x)
{
    int b = blockIdx.y, i = blockIdx.x;
    if (i >= g_tcnt[b]) return;
    int src = b * Sn + g_tidx[b * Sn + i];
    int t = threadIdx.x;
    float4 v = ((const float4*)(x + (size_t)src * Dn))[t];
    size_t rb = (size_t)(b * Sn + i) * Dn;
    ((float4*)(g_Xc + rb))[t] = v;
    ((uint2*)(g_Xc_h + rb))[t] = cvt4h(v);
}

// ---------------- attention over compacted thought rows ---------------------------
// 32 queries per block, 4 per warp (q, q+8, q+16, q+24). Online softmax, tiles of 32.
__global__ void __launch_bounds__(256) attn_kernel()
{
    int b = blockIdx.z, h = blockIdx.y, qt = blockIdx.x;
    int nT = g_tcnt[b];
    if (qt * 32 >= nT) return;

    __shared__ float Ks[128][33];
    __shared__ float Vs[32][128];
    __shared__ float Qs[32][132];

    int tid = threadIdx.x, warp = tid >> 5, lane = tid & 31;
    int qb[4]; bool qv[4];
    #pragma unroll
    for (int qq = 0; qq < 4; ++qq) {
        qb[qq] = qt * 32 + warp + 8 * qq;
        qv[qq] = qb[qq] < nT;
        if (qv[qq]) {
            const float* qr = g_qkv + (size_t)(b*Sn + qb[qq]) * (3*Dn) + h * DHn;
            #pragma unroll
            for (int c = 0; c < 4; ++c) Qs[warp + 8*qq][lane + 32*c] = qr[lane + 32*c];
        }
    }

    float mx[4], ls[4], acc[4][4];
    #pragma unroll
    for (int qq = 0; qq < 4; ++qq) {
        mx[qq] = -1e30f; ls[qq] = 0.f;
        #pragma unroll
        for (int c = 0; c < 4; ++c) acc[qq][c] = 0.f;
    }
    const float scale = 0.088388347648318447f;

    for (int j0 = 0; j0 < nT; j0 += 32) {
        int jn = min(32, nT - j0);
        __syncthreads();
        for (int idx = tid; idx < 32*128; idx += 256) {
            int j = idx >> 7, d = idx & 127;
            float kv = 0.f, vv = 0.f;
            if (j < jn) {
                const float* kr = g_qkv + (size_t)(b*Sn + j0 + j)*(3*Dn) + Dn + h*DHn;
                kv = kr[d];
                vv = kr[Dn + d];
            }
            Ks[d][j] = kv;
            Vs[j][d] = vv;
        }
        __syncthreads();

        float s[4] = {0.f, 0.f, 0.f, 0.f};
#pragma unroll 4
        for (int d = 0; d < 128; ++d) {
            float kv = Ks[d][lane];
            #pragma unroll
            for (int qq = 0; qq < 4; ++qq) s[qq] += Qs[warp + 8*qq][d] * kv;
        }
        float p[4], cr[4];
        #pragma unroll
        for (int qq = 0; qq < 4; ++qq) {
            float sq = s[qq] * scale;
            if (lane >= jn) sq = -1e30f;
            float sm = sq;
            #pragma unroll
            for (int off = 16; off; off >>= 1)
                sm = fmaxf(sm, __shfl_xor_sync(0xffffffffu, sm, off));
            float mn = fmaxf(mx[qq], sm);
            p[qq] = (lane < jn) ? __expf(sq - mn) : 0.f;
            float ps = p[qq];
            #pragma unroll
            for (int off = 16; off; off >>= 1)
                ps += __shfl_xor_sync(0xffffffffu, ps, off);
            cr[qq] = __expf(mx[qq] - mn);
            ls[qq] = ls[qq] * cr[qq] + ps;
            mx[qq] = mn;
        }
        #pragma unroll
        for (int qq = 0; qq < 4; ++qq)
            #pragma unroll
            for (int c = 0; c < 4; ++c) acc[qq][c] *= cr[qq];
        for (int j = 0; j < jn; ++j) {
            float pj[4];
            #pragma unroll
            for (int qq = 0; qq < 4; ++qq)
                pj[qq] = __shfl_sync(0xffffffffu, p[qq], j);
            #pragma unroll
            for (int c = 0; c < 4; ++c) {
                float vv = Vs[j][lane + 32*c];
                #pragma unroll
                for (int qq = 0; qq < 4; ++qq) acc[qq][c] += pj[qq] * vv;
            }
        }
    }
    #pragma unroll
    for (int qq = 0; qq < 4; ++qq) {
        if (qv[qq]) {
            float inv = 1.f / ls[qq];
            size_t rb = (size_t)(b*Sn + qb[qq]) * Dn + h * DHn;
            #pragma unroll
            for (int c = 0; c < 4; ++c)
                g_ctx_h[rb + lane + 32*c] = __float2half_rn(acc[qq][c] * inv);
        }
    }
}

// ---------------- block reduction helper ------------------------------------------
__device__ __forceinline__ float block_sum256(float v, float* red)
{
    int lane = threadIdx.x & 31, warp = threadIdx.x >> 5;
#pragma unroll
    for (int off = 16; off; off >>= 1) v += __shfl_xor_sync(0xffffffffu, v, off);
    if (lane == 0) red[warp] = v;
    __syncthreads();
    if (warp == 0) {
        float t = (lane < 8) ? red[lane] : 0.f;
#pragma unroll
        for (int off = 4; off; off >>= 1) t += __shfl_xor_sync(0xffffffffu, t, off);
        if (lane == 0) red[0] = t;
    }
    __syncthreads();
    float r = red[0];
    __syncthreads();
    return r;
}

// ---------------- fused residual-add + LayerNorm (+ optional fp16 out) ------------
__global__ void __launch_bounds__(256) add_ln_kernel(
    const float* __restrict__ X, const float* __restrict__ Y,
    const float* __restrict__ g, const float* __restrict__ be,
    float* __restrict__ out, __half* __restrict__ oh, int use_cnt)
{
    int r = blockIdx.x;
    if (use_cnt) { int b = r >> 11; if ((r & 2047) >= g_tcnt[b]) return; }
    __shared__ float red[8];
    int t = threadIdx.x;
    float4 xv = ((const float4*)(X + (size_t)r * Dn))[t];
    float4 yv = ((const float4*)(Y + (size_t)r * Dn))[t];
    float v0 = xv.x + yv.x, v1 = xv.y + yv.y, v2 = xv.z + yv.z, v3 = xv.w + yv.w;
    float mu = block_sum256(v0 + v1 + v2 + v3, red) * (1.0f / Dn);
    float d0 = v0 - mu, d1 = v1 - mu, d2 = v2 - mu, d3 = v3 - mu;
    float var = block_sum256(d0*d0 + d1*d1 + d2*d2 + d3*d3, red) * (1.0f / Dn);
    float inv = rsqrtf(var + 1e-5f);
    float4 gv = ((const float4*)g)[t];
    float4 bv = ((const float4*)be)[t];
    float4 o;
    o.x = d0 * inv * gv.x + bv.x;
    o.y = d1 * inv * gv.y + bv.y;
    o.z = d2 * inv * gv.z + bv.z;
    o.w = d3 * inv * gv.w + bv.w;
    ((float4*)(out + (size_t)r * Dn))[t] = o;
    if (oh) ((uint2*)(oh + (size_t)r * Dn))[t] = cvt4h(o);
}

// ---------------- cat init: cat = [x | x] (fp16), eff = 0.1 ------------------------
__global__ void init_cat_kernel(const float* __restrict__ x)
{
    int r = blockIdx.x, t = threadIdx.x;
    float4 v = ((const float4*)(x + (size_t)r * Dn))[t];
    uint2 h = cvt4h(v);
    uint2* ch = (uint2*)(g_cat_h + (size_t)r * 2 * Dn);
    ch[t] = h; ch[t + 256] = h;
    if (t == 0) g_eff[r] = 0.1f;
}

// ---------------- scatter x2 into cat[:, D:] (fp16) + gate --------------------------
__global__ void __launch_bounds__(256) scatter_kernel(
    const float* __restrict__ Wg, const float* __restrict__ bg)
{
    int b = blockIdx.y, i = blockIdx.x;
    if (i >= g_tcnt[b]) return;
    __shared__ float red[8];
    int dst = b * Sn + g_tidx[b * Sn + i];
    int t = threadIdx.x;
    float4 v = ((const float4*)(g_x2 + (size_t)(b*Sn + i) * Dn))[t];
    ((uint2*)(g_cat_h + (size_t)dst * 2 * Dn + Dn))[t] = cvt4h(v);
    float4 w = ((const float4*)Wg)[t];
    float p = v.x*w.x + v.y*w.y + v.z*w.z + v.w*w.w;
    float tot = block_sum256(p, red);
    if (t == 0) g_eff[dst] = 1.f / (1.f + __expf(-(tot + bg[0])));
}

// ---------------- launch ------------------------------------------------------------
#define SYM(p, s) cudaGetSymbolAddress((void**)&p, s)

extern "C" void kernel_launch(void* const* d_in, const int* in_sizes, int n_in,
                              void* d_out, int out_size)
{
    const float* x    = (const float*)d_in[0];
    const int*   ids  = (const int*)d_in[1];
    const int*   sot  = (const int*)d_in[2];
    const int*   eot  = (const int*)d_in[3];
    const float* Wqkv = (const float*)d_in[4];
    const float* bqkv = (const float*)d_in[5];
    const float* Wo   = (const float*)d_in[6];
    const float* bo   = (const float*)d_in[7];
    const float* ln1g = (const float*)d_in[8];
    const float* ln1b = (const float*)d_in[9];
    const float* W1   = (const float*)d_in[10];
    const float* b1   = (const float*)d_in[11];
    const float* W2   = (const float*)d_in[12];
    const float* b2   = (const float*)d_in[13];
    const float* ln2g = (const float*)d_in[14];
    const float* ln2b = (const float*)d_in[15];
    const float* Wg   = (const float*)d_in[16];
    const float* bg   = (const float*)d_in[17];
    const float* Wm   = (const float*)d_in[18];
    const float* bm   = (const float*)d_in[19];
    const float* Wout = (const float*)d_in[20];
    const float* bout = (const float*)d_in[21];
    float* out = (float*)d_out;

    float *pXc, *pqkv, *pattno, *px1, *pff, *px2;
    __half *pXch, *pctxh, *px1h, *phffh, *pcath, *pmixh;
    __half *pWqkvh, *pWoh, *pW1h, *pW2h, *pWmh, *pWouth;
    SYM(pXc, g_Xc); SYM(pqkv, g_qkv); SYM(pattno, g_attno); SYM(px1, g_x1);
    SYM(pff, g_ff); SYM(px2, g_x2);
    SYM(pXch, g_Xc_h); SYM(pctxh, g_ctx_h); SYM(px1h, g_x1_h); SYM(phffh, g_hff_h);
    SYM(pcath, g_cat_h); SYM(pmixh, g_mix_h);
    SYM(pWqkvh, g_Wqkv_h); SYM(pWoh, g_Wo_h); SYM(pW1h, g_W1_h); SYM(pW2h, g_W2_h);
    SYM(pWmh, g_Wm_h); SYM(pWouth, g_Wout_h);

    cudaFuncSetAttribute(gemm_hs<false,false,false>, cudaFuncAttributeMaxDynamicSharedMemorySize, GSMEM);
    cudaFuncSetAttribute(gemm_hs<true,true,false>,   cudaFuncAttributeMaxDynamicSharedMemorySize, GSMEM);
    cudaFuncSetAttribute(gemm_hs<false,false,true>,  cudaFuncAttributeMaxDynamicSharedMemorySize, GSMEM);

    // one-time stream/event setup (host-side objects; no device allocations)
    static cudaStream_t s1 = nullptr;
    static cudaEvent_t evF = nullptr, evW = nullptr, evR = nullptr;
    if (!s1) {
        cudaStreamCreateWithFlags(&s1, cudaStreamNonBlocking);
        cudaEventCreateWithFlags(&evF, cudaEventDisableTiming);
        cudaEventCreateWithFlags(&evW, cudaEventDisableTiming);
        cudaEventCreateWithFlags(&evR, cudaEventDisableTiming);
    }

    // ---- fork: weight conversions + init_cat on s1, overlap with encoder chain ----
    cudaEventRecord(evF, 0);
    cudaStreamWaitEvent(s1, evF, 0);
    conv_kernel<<<512, 256, 0, s1>>>((const float4*)Wqkv, (uint2*)pWqkvh, 3*Dn*Dn/4);
    cudaEventRecord(evW, s1);   // QKV GEMM depends only on this conv
    conv_kernel<<<256, 256, 0, s1>>>((const float4*)Wo,   (uint2*)pWoh,   Dn*Dn/4);
    conv_kernel<<<512, 256, 0, s1>>>((const float4*)W1,   (uint2*)pW1h,   DFFn*Dn/4);
    conv_kernel<<<512, 256, 0, s1>>>((const float4*)W2,   (uint2*)pW2h,   Dn*DFFn/4);
    conv_kernel<<<512, 256, 0, s1>>>((const float4*)Wm,   (uint2*)pWmh,   Dn*2*Dn/4);
    conv_kernel<<<2048, 256, 0, s1>>>((const float4*)Wout,(uint2*)pWouth, Vn*Dn/4);
    init_cat_kernel<<<Rn, 256, 0, s1>>>(x);
    cudaEventRecord(evR, s1);

    // ---- main chain on stream 0 ----
    mask_kernel<<<Bn, 32>>>(ids, sot, eot);
    gather_kernel<<<dim3(Sn, Bn), 256>>>(x);
    cudaStreamWaitEvent(0, evW, 0);
    // QKV on compacted rows (N=3072, K=1024)
    gemm_hs<false,false,false><<<32*24, 256, GSMEM>>>(pXch, pWqkvh, bqkv, pqkv, nullptr, nullptr, 3*Dn, Dn, 1);
    // masked attention == dense attention over compacted keys -> ctx fp16
    attn_kernel<<<dim3(Sn/32, NHEADS, Bn), 256>>>();
    cudaStreamWaitEvent(0, evR, 0);   // join convs + init_cat before their uses
    // attention output projection
    gemm_hs<false,false,false><<<32*8, 256, GSMEM>>>(pctxh, pWoh, bo, pattno, nullptr, nullptr, Dn, Dn, 1);
    // LN1(x + attn) -> x1 fp32 + fp16
    add_ln_kernel<<<Rn, 256>>>(pXc, pattno, ln1g, ln1b, px1, px1h, 1);
    // FFN up + relu -> hff fp16 directly (N=4096, K=1024)
    gemm_hs<true,true,false><<<32*32, 256, GSMEM>>>(px1h, pW1h, b1, nullptr, phffh, nullptr, DFFn, Dn, 1);
    // FFN down (N=1024, K=4096)
    gemm_hs<false,false,false><<<32*8, 256, GSMEM>>>(phffh, pW2h, b2, pff, nullptr, nullptr, Dn, DFFn, 1);
    // LN2(x1 + ff) -> x2 fp32
    add_ln_kernel<<<Rn, 256>>>(px1, pff, ln2g, ln2b, px2, nullptr, 1);
    // scatter x2 into cat[:, D:] + gate (init_cat done via evR join)
    scatter_kernel<<<dim3(Sn, Bn), 256>>>(Wg, bg);
    // mixed = (1-eff)*x + eff*(cat @ Wm^T + bm)  — fused mix epilogue, fp16 out
    gemm_hs<false,false,true><<<32*8, 256, GSMEM>>>(pcath, pWmh, bm, nullptr, pmixh, x, Dn, 2*Dn, 0);
    // logits = mixed @ Wout^T + bout (dominant: N=32000, K=1024)
    gemm_hs<false,false,false><<<32*250, 256, GSMEM>>>(pmixh, pWouth, bout, out, nullptr, nullptr, Vn, Dn, 0);

    (void)in_sizes; (void)n_in; (void)out_size;
}

// round 9
// speedup vs baseline: 6.7922x; 1.0280x over previous
#include <cuda_runtime.h>
#include <cuda_fp16.h>
#include <cstdint>

// ---------------- problem constants ----------------
#define Bn 2
#define Sn 2048
#define Dn 1024
#define Vn 32000
#define NHEADS 8
#define DHn 128
#define DFFn 4096
#define Rn (Bn*Sn)   // 4096 total rows

// ---------------- fp32 scratch ----------------
__device__ float g_Xc[Rn*Dn];
__device__ float g_qkv[Rn*3*Dn];
__device__ float g_attno[Rn*Dn];
__device__ float g_x1[Rn*Dn];
__device__ float g_ff[Rn*Dn];
__device__ float g_x2[Rn*Dn];
__device__ float g_eff[Rn];
__device__ int   g_tidx[Rn];
__device__ int   g_tcnt[Bn];

// ---------------- fp16 planes ---------------------------------
__device__ __align__(16) __half g_Xc_h[Rn*Dn];
__device__ __align__(16) __half g_ctx_h[Rn*Dn];
__device__ __align__(16) __half g_x1_h[Rn*Dn];
__device__ __align__(16) __half g_hff_h[Rn*DFFn];
__device__ __align__(16) __half g_cat_h[Rn*2*Dn];
__device__ __align__(16) __half g_mix_h[Rn*Dn];
__device__ __align__(16) __half g_Wqkv_h[3*Dn*Dn];
__device__ __align__(16) __half g_Wo_h[Dn*Dn];
__device__ __align__(16) __half g_W1_h[DFFn*Dn];
__device__ __align__(16) __half g_W2_h[Dn*DFFn];
__device__ __align__(16) __half g_Wm_h[Dn*2*Dn];
__device__ __align__(16) __half g_Wout_h[Vn*Dn];

// ---------------- helpers -------------------------------------------------------
__device__ __forceinline__ uint32_t smem_u32(const void* p) {
    uint32_t a;
    asm("{ .reg .u64 t; cvta.to.shared.u64 t, %1; cvt.u32.u64 %0, t; }" : "=r"(a) : "l"(p));
    return a;
}
__device__ __forceinline__ uint32_t pk2h(__half a, __half b) {
    return ((uint32_t)__half_as_ushort(b) << 16) | (uint32_t)__half_as_ushort(a);
}
__device__ __forceinline__ uint2 cvt4h(float4 v) {
    uint2 h;
    h.x = pk2h(__float2half_rn(v.x), __float2half_rn(v.y));
    h.y = pk2h(__float2half_rn(v.z), __float2half_rn(v.w));
    return h;
}
__device__ __forceinline__ void cpa16(uint32_t dst, const void* src) {
    asm volatile("cp.async.cg.shared.global [%0], [%1], 16;" :: "r"(dst), "l"(src));
}
__device__ __forceinline__ void cp_commit() {
    asm volatile("cp.async.commit_group;" ::: "memory");
}
template<int N>
__device__ __forceinline__ void cp_wait() {
    asm volatile("cp.async.wait_group %0;" :: "n"(N) : "memory");
}
__device__ __forceinline__ void ldm4(uint32_t addr, uint32_t* r) {
    asm volatile("ldmatrix.sync.aligned.m8n8.x4.shared.b16 {%0,%1,%2,%3}, [%4];"
                 : "=r"(r[0]), "=r"(r[1]), "=r"(r[2]), "=r"(r[3]) : "r"(addr));
}
__device__ __forceinline__ void mma_hf(float* d, const uint32_t* a, const uint32_t* b) {
    asm volatile("mma.sync.aligned.m16n8k16.row.col.f32.f16.f16.f32 "
                 "{%0,%1,%2,%3}, {%4,%5,%6,%7}, {%8,%9}, {%0,%1,%2,%3};"
                 : "+f"(d[0]), "+f"(d[1]), "+f"(d[2]), "+f"(d[3])
                 : "r"(a[0]), "r"(a[1]), "r"(a[2]), "r"(a[3]), "r"(b[0]), "r"(b[1]));
}

// ---------------- weight convert kernel (fp32 -> fp16) ----------------------------
__global__ void conv_kernel(const float4* __restrict__ in, uint2* __restrict__ out, int n4)
{
    for (int i = blockIdx.x * 256 + threadIdx.x; i < n4; i += gridDim.x * 256) {
        out[i] = cvt4h(in[i]);
    }
}

// ---------------- fp16 GEMM: C = A @ W^T + bias -----------------------------------
// A fp16 [M,K], W fp16 [N,K]. BM=128,BN=128,BK=64. 256 thr, 8 warps (4x2).
// 3-stage cp.async pipeline (2 chunks ahead), 2 CTAs/SM.
// MIXOUT: write fp16 ((1-eff)*Xin + eff*(acc+bias)) to Ch instead.
#define ROWB  144            // 128B data + 16B pad per row (conflict-free: 36 words)
#define TILEB (128*ROWB)     // 18432
#define BUFB  (2*TILEB)      // A | W = 36864
#define NSTG  3
#define GSMEM (NSTG*BUFB)    // 110592

template<bool RELU, bool SPLITOUT, bool MIXOUT>
__global__ void __launch_bounds__(256, 2)
gemm_hs(const __half* __restrict__ A, const __half* __restrict__ W,
        const float* __restrict__ bias, float* __restrict__ C,
        __half* __restrict__ Ch,
        const float* __restrict__ Xin,
        int N, int K, int use_cnt)
{
    int bid = blockIdx.x;
    int m0 = (bid & 31) << 7;
    int n0 = (bid >> 5) << 7;
    if (use_cnt) {
        int b = m0 >> 11;
        if ((m0 & 2047) >= g_tcnt[b]) return;
    }

    extern __shared__ char smraw[];
    uint32_t sb = smem_u32(smraw);
    int tid = threadIdx.x, lane = tid & 31, wid = tid >> 5;
    int mw = (wid & 3) << 5;   // warp m-origin in tile
    int nw = (wid >> 2) << 6;  // warp n-origin in tile

    // cp.async slots: 8 per thread (A: 4 slots covering 128 rows x 64 K-halfs; W: 4)
    int lr = tid >> 3, seg = tid & 7;     // 32 rows per batch of 256 threads, 8 segs/row
    const __half* srcA[4];
    const __half* srcW[4];
    uint32_t dstA[4], dstW[4];
    #pragma unroll
    for (int j = 0; j < 4; ++j) {
        int row = lr + 32 * j;            // 0..127
        srcA[j] = A + (size_t)(m0 + row) * K + seg * 8;
        srcW[j] = W + (size_t)(n0 + row) * K + seg * 8;
        dstA[j] = (uint32_t)(row * ROWB + seg * 16);
        dstW[j] = (uint32_t)(TILEB + row * ROWB + seg * 16);
    }

    // ldmatrix per-lane offsets (4 ks-steps of K16 per 64-chunk)
    int am = lane >> 3;
    int arow = ((am & 1) << 3) | (lane & 7);
    int akc = am >> 1;
    uint32_t offA[2][4];
    #pragma unroll
    for (int mt = 0; mt < 2; ++mt)
        #pragma unroll
        for (int ks = 0; ks < 4; ++ks)
            offA[mt][ks] = (uint32_t)((mw + mt*16 + arow) * ROWB + (ks*2 + akc) * 16);
    int brow = ((am >> 1) << 3) | (lane & 7);
    int bkc = am & 1;
    uint32_t offB[4][4];
    #pragma unroll
    for (int jp = 0; jp < 4; ++jp)
        #pragma unroll
        for (int ks = 0; ks < 4; ++ks)
            offB[jp][ks] = (uint32_t)((nw + jp*16 + brow) * ROWB + (ks*2 + bkc) * 16);

    float acc[2][8][4];
    #pragma unroll
    for (int mt = 0; mt < 2; ++mt)
        #pragma unroll
        for (int nt = 0; nt < 8; ++nt)
            #pragma unroll
            for (int i = 0; i < 4; ++i) acc[mt][nt][i] = 0.f;

    int NC = K >> 6;   // K >= 1024 => NC >= 16 > 2

    // prefetch chunks 0..1 into stages 0..1 (one commit group per chunk)
    #pragma unroll
    for (int s = 0; s < 2; ++s) {
        uint32_t nb = sb + (uint32_t)s * BUFB;
        const int ko = s * 64;
        #pragma unroll
        for (int j = 0; j < 4; ++j) {
            cpa16(nb + dstA[j], srcA[j] + ko);
            cpa16(nb + dstW[j], srcW[j] + ko);
        }
        cp_commit();
    }

    int slot = 0;       // slot of chunk c (c % NSTG)
    int pslot = 2;      // slot of chunk c+2
    for (int c = 0; c < NC; ++c) {
        cp_wait<1>();        // chunk c's group complete (one group per iteration)
        __syncthreads();     // all warps done with chunk c-1; chunk c visible

        if (c + 2 < NC) {
            uint32_t nb = sb + (uint32_t)pslot * BUFB;
            const int ko = (c + 2) * 64;
            #pragma unroll
            for (int j = 0; j < 4; ++j) {
                cpa16(nb + dstA[j], srcA[j] + ko);
                cpa16(nb + dstW[j], srcW[j] + ko);
            }
        }
        cp_commit();

        uint32_t cb = sb + (uint32_t)slot * BUFB;
        #pragma unroll
        for (int ks = 0; ks < 4; ++ks) {
            uint32_t ah[2][4], w[4][4];
            ldm4(cb + offA[0][ks], ah[0]);
            ldm4(cb + offA[1][ks], ah[1]);
            #pragma unroll
            for (int jp = 0; jp < 4; ++jp)
                ldm4(cb + TILEB + offB[jp][ks], w[jp]);
            #pragma unroll
            for (int mt = 0; mt < 2; ++mt)
                #pragma unroll
                for (int nt = 0; nt < 8; ++nt) {
                    const uint32_t* bw = &w[nt >> 1][(nt & 1) * 2];
                    mma_hf(acc[mt][nt], ah[mt], bw);
                }
        }
        slot  = (slot  == NSTG-1) ? 0 : slot  + 1;
        pslot = (pslot == NSTG-1) ? 0 : pslot + 1;
    }

    // epilogue
    #pragma unroll
    for (int mt = 0; mt < 2; ++mt)
        #pragma unroll
        for (int nt = 0; nt < 8; ++nt) {
            float* a = acc[mt][nt];
            int col = n0 + nw + nt * 8 + (lane & 3) * 2;
            int r0  = m0 + mw + mt * 16 + (lane >> 2);
            float2 bv = *(const float2*)(bias + col);
            float x0 = a[0] + bv.x, y0 = a[1] + bv.y;
            float x1 = a[2] + bv.x, y1 = a[3] + bv.y;
            if (RELU) {
                x0 = fmaxf(x0, 0.f); y0 = fmaxf(y0, 0.f);
                x1 = fmaxf(x1, 0.f); y1 = fmaxf(y1, 0.f);
            }
            if (MIXOUT) {
                float e0 = g_eff[r0], e1 = g_eff[r0 + 8];
                float2 xa = *(const float2*)(Xin + (size_t)r0 * N + col);
                float2 xb = *(const float2*)(Xin + (size_t)(r0 + 8) * N + col);
                x0 = (1.f - e0) * xa.x + e0 * x0;
                y0 = (1.f - e0) * xa.y + e0 * y0;
                x1 = (1.f - e1) * xb.x + e1 * x1;
                y1 = (1.f - e1) * xb.y + e1 * y1;
                *(uint32_t*)(Ch + (size_t)r0 * N + col) =
                    pk2h(__float2half_rn(x0), __float2half_rn(y0));
                *(uint32_t*)(Ch + (size_t)(r0 + 8) * N + col) =
                    pk2h(__float2half_rn(x1), __float2half_rn(y1));
            } else if (SPLITOUT) {
                *(uint32_t*)(Ch + (size_t)r0 * N + col) =
                    pk2h(__float2half_rn(x0), __float2half_rn(y0));
                *(uint32_t*)(Ch + (size_t)(r0 + 8) * N + col) =
                    pk2h(__float2half_rn(x1), __float2half_rn(y1));
            } else {
                float2 v0 = {x0, y0}, v1 = {x1, y1};
                *(float2*)(C + (size_t)r0 * N + col) = v0;
                *(float2*)(C + (size_t)(r0 + 8) * N + col) = v1;
            }
        }
}

// ---------------- mask + compaction (1 warp per batch) ---------------------------
__global__ void mask_kernel(const int* __restrict__ ids,
                            const int* __restrict__ sotp,
                            const int* __restrict__ eotp)
{
    int b = blockIdx.x;
    int lane = threadIdx.x;
    int sot = *sotp, eot = *eotp;
    const int* row = ids + b * Sn;
    int base = lane * 64;

    unsigned a = 0u, bb = 1u, anyeot = 0u;
    for (int i = 0; i < 64; ++i) {
        int t = row[base + i];
        unsigned iso = (t == sot) ? 1u : 0u;
        unsigned ieo = (t == eot) ? 1u : 0u;
        a = iso | (a & (1u - ieo));
        bb = bb & (1u - ieo);
        anyeot |= ieo;
    }
    unsigned ai = a, bi = bb;
    for (int off = 1; off < 32; off <<= 1) {
        unsigned ap = __shfl_up_sync(0xffffffffu, ai, off);
        unsigned bp = __shfl_up_sync(0xffffffffu, bi, off);
        if (lane >= off) { ai = ai | (ap & bi); bi = bi & bp; }
    }
    unsigned s_in = __shfl_up_sync(0xffffffffu, ai, 1);
    if (lane == 0) s_in = 0u;

    unsigned sfx = anyeot;
    for (int off = 1; off < 32; off <<= 1) {
        unsigned v = __shfl_down_sync(0xffffffffu, sfx, off);
        if (lane + off < 32) sfx |= v;
    }
    unsigned after = __shfl_down_sync(0xffffffffu, sfx, 1);
    if (lane == 31) after = 0u;

    unsigned long long openbits = 0ull;
    unsigned s = s_in;
    for (int i = 0; i < 64; ++i) {
        int t = row[base + i];
        unsigned iso = (t == sot) ? 1u : 0u;
        unsigned ieo = (t == eot) ? 1u : 0u;
        unsigned o = iso | s;
        openbits |= ((unsigned long long)o) << i;
        s = iso | (s & (1u - ieo));
    }
    unsigned long long tbits = 0ull;
    unsigned seen = after;
    for (int i = 63; i >= 0; --i) {
        int t = row[base + i];
        if (t == eot) seen = 1u;
        if (((openbits >> i) & 1ull) && seen) tbits |= (1ull << i);
    }
    int c = __popcll(tbits);
    int pre = c;
    for (int off = 1; off < 32; off <<= 1) {
        int v = __shfl_up_sync(0xffffffffu, pre, off);
        if (lane >= off) pre += v;
    }
    int excl = pre - c;
    int total = __shfl_sync(0xffffffffu, pre, 31);
    if (lane == 31) g_tcnt[b] = total;
    int o = excl;
    for (int i = 0; i < 64; ++i) {
        if ((tbits >> i) & 1ull) g_tidx[b * Sn + (o++)] = base + i;
    }
}

// ---------------- gather thought rows: fp32 + fp16 --------------------------------
__global__ void gather_kernel(const float* __restrict__ x)
{
    int b = blockIdx.y, i = blockIdx.x;
    if (i >= g_tcnt[b]) return;
    int src = b * Sn + g_tidx[b * Sn + i];
    int t = threadIdx.x;
    float4 v = ((const float4*)(x + (size_t)src * Dn))[t];
    size_t rb = (size_t)(b * Sn + i) * Dn;
    ((float4*)(g_Xc + rb))[t] = v;
    ((uint2*)(g_Xc_h + rb))[t] = cvt4h(v);
}

// ---------------- attention over compacted thought rows ---------------------------
// 32 queries per block, 4 per warp (q, q+8, q+16, q+24). Online softmax, tiles of 32.
__global__ void __launch_bounds__(256) attn_kernel()
{
    int b = blockIdx.z, h = blockIdx.y, qt = blockIdx.x;
    int nT = g_tcnt[b];
    if (qt * 32 >= nT) return;

    __shared__ float Ks[128][33];
    __shared__ float Vs[32][128];
    __shared__ float Qs[32][132];

    int tid = threadIdx.x, warp = tid >> 5, lane = tid & 31;
    int qb[4]; bool qv[4];
    #pragma unroll
    for (int qq = 0; qq < 4; ++qq) {
        qb[qq] = qt * 32 + warp + 8 * qq;
        qv[qq] = qb[qq] < nT;
        if (qv[qq]) {
            const float* qr = g_qkv + (size_t)(b*Sn + qb[qq]) * (3*Dn) + h * DHn;
            #pragma unroll
            for (int c = 0; c < 4; ++c) Qs[warp + 8*qq][lane + 32*c] = qr[lane + 32*c];
        }
    }

    float mx[4], ls[4], acc[4][4];
    #pragma unroll
    for (int qq = 0; qq < 4; ++qq) {
        mx[qq] = -1e30f; ls[qq] = 0.f;
        #pragma unroll
        for (int c = 0; c < 4; ++c) acc[qq][c] = 0.f;
    }
    const float scale = 0.088388347648318447f;

    for (int j0 = 0; j0 < nT; j0 += 32) {
        int jn = min(32, nT - j0);
        __syncthreads();
        for (int idx = tid; idx < 32*128; idx += 256) {
            int j = idx >> 7, d = idx & 127;
            float kv = 0.f, vv = 0.f;
            if (j < jn) {
                const float* kr = g_qkv + (size_t)(b*Sn + j0 + j)*(3*Dn) + Dn + h*DHn;
                kv = kr[d];
                vv = kr[Dn + d];
            }
            Ks[d][j] = kv;
            Vs[j][d] = vv;
        }
        __syncthreads();

        float s[4] = {0.f, 0.f, 0.f, 0.f};
#pragma unroll 4
        for (int d = 0; d < 128; ++d) {
            float kv = Ks[d][lane];
            #pragma unroll
            for (int qq = 0; qq < 4; ++qq) s[qq] += Qs[warp + 8*qq][d] * kv;
        }
        float p[4], cr[4];
        #pragma unroll
        for (int qq = 0; qq < 4; ++qq) {
            float sq = s[qq] * scale;
            if (lane >= jn) sq = -1e30f;
            float sm = sq;
            #pragma unroll
            for (int off = 16; off; off >>= 1)
                sm = fmaxf(sm, __shfl_xor_sync(0xffffffffu, sm, off));
            float mn = fmaxf(mx[qq], sm);
            p[qq] = (lane < jn) ? __expf(sq - mn) : 0.f;
            float ps = p[qq];
            #pragma unroll
            for (int off = 16; off; off >>= 1)
                ps += __shfl_xor_sync(0xffffffffu, ps, off);
            cr[qq] = __expf(mx[qq] - mn);
            ls[qq] = ls[qq] * cr[qq] + ps;
            mx[qq] = mn;
        }
        #pragma unroll
        for (int qq = 0; qq < 4; ++qq)
            #pragma unroll
            for (int c = 0; c < 4; ++c) acc[qq][c] *= cr[qq];
        for (int j = 0; j < jn; ++j) {
            float pj[4];
            #pragma unroll
            for (int qq = 0; qq < 4; ++qq)
                pj[qq] = __shfl_sync(0xffffffffu, p[qq], j);
            #pragma unroll
            for (int c = 0; c < 4; ++c) {
                float vv = Vs[j][lane + 32*c];
                #pragma unroll
                for (int qq = 0; qq < 4; ++qq) acc[qq][c] += pj[qq] * vv;
            }
        }
    }
    #pragma unroll
    for (int qq = 0; qq < 4; ++qq) {
        if (qv[qq]) {
            float inv = 1.f / ls[qq];
            size_t rb = (size_t)(b*Sn + qb[qq]) * Dn + h * DHn;
            #pragma unroll
            for (int c = 0; c < 4; ++c)
                g_ctx_h[rb + lane + 32*c] = __float2half_rn(acc[qq][c] * inv);
        }
    }
}

// ---------------- block reduction helper ------------------------------------------
__device__ __forceinline__ float block_sum256(float v, float* red)
{
    int lane = threadIdx.x & 31, warp = threadIdx.x >> 5;
#pragma unroll
    for (int off = 16; off; off >>= 1) v += __shfl_xor_sync(0xffffffffu, v, off);
    if (lane == 0) red[warp] = v;
    __syncthreads();
    if (warp == 0) {
        float t = (lane < 8) ? red[lane] : 0.f;
#pragma unroll
        for (int off = 4; off; off >>= 1) t += __shfl_xor_sync(0xffffffffu, t, off);
        if (lane == 0) red[0] = t;
    }
    __syncthreads();
    float r = red[0];
    __syncthreads();
    return r;
}

// ---------------- fused residual-add + LayerNorm (+ optional fp16 out) ------------
__global__ void __launch_bounds__(256) add_ln_kernel(
    const float* __restrict__ X, const float* __restrict__ Y,
    const float* __restrict__ g, const float* __restrict__ be,
    float* __restrict__ out, __half* __restrict__ oh, int use_cnt)
{
    int r = blockIdx.x;
    if (use_cnt) { int b = r >> 11; if ((r & 2047) >= g_tcnt[b]) return; }
    __shared__ float red[8];
    int t = threadIdx.x;
    float4 xv = ((const float4*)(X + (size_t)r * Dn))[t];
    float4 yv = ((const float4*)(Y + (size_t)r * Dn))[t];
    float v0 = xv.x + yv.x, v1 = xv.y + yv.y, v2 = xv.z + yv.z, v3 = xv.w + yv.w;
    float mu = block_sum256(v0 + v1 + v2 + v3, red) * (1.0f / Dn);
    float d0 = v0 - mu, d1 = v1 - mu, d2 = v2 - mu, d3 = v3 - mu;
    float var = block_sum256(d0*d0 + d1*d1 + d2*d2 + d3*d3, red) * (1.0f / Dn);
    float inv = rsqrtf(var + 1e-5f);
    float4 gv = ((const float4*)g)[t];
    float4 bv = ((const float4*)be)[t];
    float4 o;
    o.x = d0 * inv * gv.x + bv.x;
    o.y = d1 * inv * gv.y + bv.y;
    o.z = d2 * inv * gv.z + bv.z;
    o.w = d3 * inv * gv.w + bv.w;
    ((float4*)(out + (size_t)r * Dn))[t] = o;
    if (oh) ((uint2*)(oh + (size_t)r * Dn))[t] = cvt4h(o);
}

// ---------------- cat init: cat = [x | x] (fp16), eff = 0.1 ------------------------
__global__ void init_cat_kernel(const float* __restrict__ x)
{
    int r = blockIdx.x, t = threadIdx.x;
    float4 v = ((const float4*)(x + (size_t)r * Dn))[t];
    uint2 h = cvt4h(v);
    uint2* ch = (uint2*)(g_cat_h + (size_t)r * 2 * Dn);
    ch[t] = h; ch[t + 256] = h;
    if (t == 0) g_eff[r] = 0.1f;
}

// ---------------- scatter x2 into cat[:, D:] (fp16) + gate --------------------------
__global__ void __launch_bounds__(256) scatter_kernel(
    const float* __restrict__ Wg, const float* __restrict__ bg)
{
    int b = blockIdx.y, i = blockIdx.x;
    if (i >= g_tcnt[b]) return;
    __shared__ float red[8];
    int dst = b * Sn + g_tidx[b * Sn + i];
    int t = threadIdx.x;
    float4 v = ((const float4*)(g_x2 + (size_t)(b*Sn + i) * Dn))[t];
    ((uint2*)(g_cat_h + (size_t)dst * 2 * Dn + Dn))[t] = cvt4h(v);
    float4 w = ((const float4*)Wg)[t];
    float p = v.x*w.x + v.y*w.y + v.z*w.z + v.w*w.w;
    float tot = block_sum256(p, red);
    if (t == 0) g_eff[dst] = 1.f / (1.f + __expf(-(tot + bg[0])));
}

// ---------------- launch ------------------------------------------------------------
#define SYM(p, s) cudaGetSymbolAddress((void**)&p, s)

extern "C" void kernel_launch(void* const* d_in, const int* in_sizes, int n_in,
                              void* d_out, int out_size)
{
    const float* x    = (const float*)d_in[0];
    const int*   ids  = (const int*)d_in[1];
    const int*   sot  = (const int*)d_in[2];
    const int*   eot  = (const int*)d_in[3];
    const float* Wqkv = (const float*)d_in[4];
    const float* bqkv = (const float*)d_in[5];
    const float* Wo   = (const float*)d_in[6];
    const float* bo   = (const float*)d_in[7];
    const float* ln1g = (const float*)d_in[8];
    const float* ln1b = (const float*)d_in[9];
    const float* W1   = (const float*)d_in[10];
    const float* b1   = (const float*)d_in[11];
    const float* W2   = (const float*)d_in[12];
    const float* b2   = (const float*)d_in[13];
    const float* ln2g = (const float*)d_in[14];
    const float* ln2b = (const float*)d_in[15];
    const float* Wg   = (const float*)d_in[16];
    const float* bg   = (const float*)d_in[17];
    const float* Wm   = (const float*)d_in[18];
    const float* bm   = (const float*)d_in[19];
    const float* Wout = (const float*)d_in[20];
    const float* bout = (const float*)d_in[21];
    float* out = (float*)d_out;

    float *pXc, *pqkv, *pattno, *px1, *pff, *px2;
    __half *pXch, *pctxh, *px1h, *phffh, *pcath, *pmixh;
    __half *pWqkvh, *pWoh, *pW1h, *pW2h, *pWmh, *pWouth;
    SYM(pXc, g_Xc); SYM(pqkv, g_qkv); SYM(pattno, g_attno); SYM(px1, g_x1);
    SYM(pff, g_ff); SYM(px2, g_x2);
    SYM(pXch, g_Xc_h); SYM(pctxh, g_ctx_h); SYM(px1h, g_x1_h); SYM(phffh, g_hff_h);
    SYM(pcath, g_cat_h); SYM(pmixh, g_mix_h);
    SYM(pWqkvh, g_Wqkv_h); SYM(pWoh, g_Wo_h); SYM(pW1h, g_W1_h); SYM(pW2h, g_W2_h);
    SYM(pWmh, g_Wm_h); SYM(pWouth, g_Wout_h);

    cudaFuncSetAttribute(gemm_hs<false,false,false>, cudaFuncAttributeMaxDynamicSharedMemorySize, GSMEM);
    cudaFuncSetAttribute(gemm_hs<true,true,false>,   cudaFuncAttributeMaxDynamicSharedMemorySize, GSMEM);
    cudaFuncSetAttribute(gemm_hs<false,false,true>,  cudaFuncAttributeMaxDynamicSharedMemorySize, GSMEM);

    // one-time stream/event setup (host-side objects; no device allocations)
    static cudaStream_t s1 = nullptr;
    static cudaEvent_t evF = nullptr, evW = nullptr, evR = nullptr;
    if (!s1) {
        cudaStreamCreateWithFlags(&s1, cudaStreamNonBlocking);
        cudaEventCreateWithFlags(&evF, cudaEventDisableTiming);
        cudaEventCreateWithFlags(&evW, cudaEventDisableTiming);
        cudaEventCreateWithFlags(&evR, cudaEventDisableTiming);
    }

    // ---- fork: weight conversions + init_cat on s1, overlap with encoder chain ----
    cudaEventRecord(evF, 0);
    cudaStreamWaitEvent(s1, evF, 0);
    conv_kernel<<<512, 256, 0, s1>>>((const float4*)Wqkv, (uint2*)pWqkvh, 3*Dn*Dn/4);
    cudaEventRecord(evW, s1);   // QKV GEMM depends only on this conv
    conv_kernel<<<256, 256, 0, s1>>>((const float4*)Wo,   (uint2*)pWoh,   Dn*Dn/4);
    conv_kernel<<<512, 256, 0, s1>>>((const float4*)W1,   (uint2*)pW1h,   DFFn*Dn/4);
    conv_kernel<<<512, 256, 0, s1>>>((const float4*)W2,   (uint2*)pW2h,   Dn*DFFn/4);
    conv_kernel<<<512, 256, 0, s1>>>((const float4*)Wm,   (uint2*)pWmh,   Dn*2*Dn/4);
    conv_kernel<<<2048, 256, 0, s1>>>((const float4*)Wout,(uint2*)pWouth, Vn*Dn/4);
    init_cat_kernel<<<Rn, 256, 0, s1>>>(x);
    cudaEventRecord(evR, s1);

    // ---- main chain on stream 0 ----
    mask_kernel<<<Bn, 32>>>(ids, sot, eot);
    gather_kernel<<<dim3(Sn, Bn), 256>>>(x);
    cudaStreamWaitEvent(0, evW, 0);
    // QKV on compacted rows (N=3072, K=1024)
    gemm_hs<false,false,false><<<32*24, 256, GSMEM>>>(pXch, pWqkvh, bqkv, pqkv, nullptr, nullptr, 3*Dn, Dn, 1);
    // masked attention == dense attention over compacted keys -> ctx fp16
    attn_kernel<<<dim3(Sn/32, NHEADS, Bn), 256>>>();
    cudaStreamWaitEvent(0, evR, 0);   // join convs + init_cat before their uses
    // attention output projection
    gemm_hs<false,false,false><<<32*8, 256, GSMEM>>>(pctxh, pWoh, bo, pattno, nullptr, nullptr, Dn, Dn, 1);
    // LN1(x + attn) -> x1 fp32 + fp16
    add_ln_kernel<<<Rn, 256>>>(pXc, pattno, ln1g, ln1b, px1, px1h, 1);
    // FFN up + relu -> hff fp16 directly (N=4096, K=1024)
    gemm_hs<true,true,false><<<32*32, 256, GSMEM>>>(px1h, pW1h, b1, nullptr, phffh, nullptr, DFFn, Dn, 1);
    // FFN down (N=1024, K=4096)
    gemm_hs<false,false,false><<<32*8, 256, GSMEM>>>(phffh, pW2h, b2, pff, nullptr, nullptr, Dn, DFFn, 1);
    // LN2(x1 + ff) -> x2 fp32
    add_ln_kernel<<<Rn, 256>>>(px1, pff, ln2g, ln2b, px2, nullptr, 1);
    // scatter x2 into cat[:, D:] + gate (init_cat done via evR join)
    scatter_kernel<<<dim3(Sn, Bn), 256>>>(Wg, bg);
    // mixed = (1-eff)*x + eff*(cat @ Wm^T + bm)  — fused mix epilogue, fp16 out
    gemm_hs<false,false,true><<<32*8, 256, GSMEM>>>(pcath, pWmh, bm, nullptr, pmixh, x, Dn, 2*Dn, 0);
    // logits = mixed @ Wout^T + bout (dominant: N=32000, K=1024)
    gemm_hs<false,false,false><<<32*250, 256, GSMEM>>>(pmixh, pWouth, bout, out, nullptr, nullptr, Vn, Dn, 0);

    (void)in_sizes; (void)n_in; (void)out_size;
}

// round 10
// speedup vs baseline: 6.8653x; 1.0108x over previous
#include <cuda_runtime.h>
#include <cuda_fp16.h>
#include <cstdint>

// ---------------- problem constants ----------------
#define Bn 2
#define Sn 2048
#define Dn 1024
#define Vn 32000
#define NHEADS 8
#define DHn 128
#define DFFn 4096
#define Rn (Bn*Sn)   // 4096 total rows

// ---------------- fp32 scratch ----------------
__device__ float g_Xc[Rn*Dn];
__device__ float g_qkv[Rn*3*Dn];
__device__ float g_attno[Rn*Dn];
__device__ float g_x1[Rn*Dn];
__device__ float g_ff[Rn*Dn];
__device__ float g_x2[Rn*Dn];
__device__ float g_eff[Rn];
__device__ int   g_tidx[Rn];
__device__ int   g_tcnt[Bn];

// ---------------- fp16 planes ---------------------------------
__device__ __align__(16) __half g_Xc_h[Rn*Dn];
__device__ __align__(16) __half g_ctx_h[Rn*Dn];
__device__ __align__(16) __half g_x1_h[Rn*Dn];
__device__ __align__(16) __half g_hff_h[Rn*DFFn];
__device__ __align__(16) __half g_cat_h[Rn*2*Dn];
__device__ __align__(16) __half g_mix_h[Rn*Dn];
__device__ __align__(16) __half g_Wqkv_h[3*Dn*Dn];
__device__ __align__(16) __half g_Wo_h[Dn*Dn];
__device__ __align__(16) __half g_W1_h[DFFn*Dn];
__device__ __align__(16) __half g_W2_h[Dn*DFFn];
__device__ __align__(16) __half g_Wm_h[Dn*2*Dn];
__device__ __align__(16) __half g_Wout_h[Vn*Dn];

// ---------------- helpers -------------------------------------------------------
__device__ __forceinline__ uint32_t smem_u32(const void* p) {
    uint32_t a;
    asm("{ .reg .u64 t; cvta.to.shared.u64 t, %1; cvt.u32.u64 %0, t; }" : "=r"(a) : "l"(p));
    return a;
}
__device__ __forceinline__ uint32_t pk2h(__half a, __half b) {
    return ((uint32_t)__half_as_ushort(b) << 16) | (uint32_t)__half_as_ushort(a);
}
__device__ __forceinline__ uint2 cvt4h(float4 v) {
    uint2 h;
    h.x = pk2h(__float2half_rn(v.x), __float2half_rn(v.y));
    h.y = pk2h(__float2half_rn(v.z), __float2half_rn(v.w));
    return h;
}
__device__ __forceinline__ void cpa16(uint32_t dst, const void* src) {
    asm volatile("cp.async.cg.shared.global [%0], [%1], 16;" :: "r"(dst), "l"(src));
}
__device__ __forceinline__ void cp_commit() {
    asm volatile("cp.async.commit_group;" ::: "memory");
}
template<int N>
__device__ __forceinline__ void cp_wait() {
    asm volatile("cp.async.wait_group %0;" :: "n"(N) : "memory");
}
__device__ __forceinline__ void ldm4(uint32_t addr, uint32_t* r) {
    asm volatile("ldmatrix.sync.aligned.m8n8.x4.shared.b16 {%0,%1,%2,%3}, [%4];"
                 : "=r"(r[0]), "=r"(r[1]), "=r"(r[2]), "=r"(r[3]) : "r"(addr));
}
__device__ __forceinline__ void mma_hf(float* d, const uint32_t* a, const uint32_t* b) {
    asm volatile("mma.sync.aligned.m16n8k16.row.col.f32.f16.f16.f32 "
                 "{%0,%1,%2,%3}, {%4,%5,%6,%7}, {%8,%9}, {%0,%1,%2,%3};"
                 : "+f"(d[0]), "+f"(d[1]), "+f"(d[2]), "+f"(d[3])
                 : "r"(a[0]), "r"(a[1]), "r"(a[2]), "r"(a[3]), "r"(b[0]), "r"(b[1]));
}

// ---------------- weight convert kernel (fp32 -> fp16) ----------------------------
__global__ void conv_kernel(const float4* __restrict__ in, uint2* __restrict__ out, int n4)
{
    for (int i = blockIdx.x * 256 + threadIdx.x; i < n4; i += gridDim.x * 256) {
        out[i] = cvt4h(in[i]);
    }
}

// ---------------- fp16 GEMM: C = A @ W^T + bias -----------------------------------
// A fp16 [M,K], W fp16 [N,K]. BM=128,BN=128,BK=64. 256 thr, 8 warps (4x2).
// 3-stage cp.async pipeline, 2 CTAs/SM. m0 = ((bid & ((1<<mshift)-1)) + moff)*128.
#define ROWB  144            // 128B data + 16B pad per row (conflict-free)
#define TILEB (128*ROWB)     // 18432
#define BUFB  (2*TILEB)      // A | W = 36864
#define NSTG  3
#define GSMEM (NSTG*BUFB)    // 110592

template<bool RELU, bool SPLITOUT, bool MIXOUT>
__global__ void __launch_bounds__(256, 2)
gemm_hs(const __half* __restrict__ A, const __half* __restrict__ W,
        const float* __restrict__ bias, float* __restrict__ C,
        __half* __restrict__ Ch,
        const float* __restrict__ Xin,
        int N, int K, int use_cnt, int mshift, int moff)
{
    int bid = blockIdx.x;
    int m0 = ((bid & ((1 << mshift) - 1)) + moff) << 7;
    int n0 = (bid >> mshift) << 7;
    if (use_cnt) {
        int b = m0 >> 11;
        if ((m0 & 2047) >= g_tcnt[b]) return;
    }

    extern __shared__ char smraw[];
    uint32_t sb = smem_u32(smraw);
    int tid = threadIdx.x, lane = tid & 31, wid = tid >> 5;
    int mw = (wid & 3) << 5;   // warp m-origin in tile
    int nw = (wid >> 2) << 6;  // warp n-origin in tile

    // cp.async slots: 8 per thread (A: 4, W: 4)
    int lr = tid >> 3, seg = tid & 7;
    const __half* srcA[4];
    const __half* srcW[4];
    uint32_t dstA[4], dstW[4];
    #pragma unroll
    for (int j = 0; j < 4; ++j) {
        int row = lr + 32 * j;
        srcA[j] = A + (size_t)(m0 + row) * K + seg * 8;
        srcW[j] = W + (size_t)(n0 + row) * K + seg * 8;
        dstA[j] = (uint32_t)(row * ROWB + seg * 16);
        dstW[j] = (uint32_t)(TILEB + row * ROWB + seg * 16);
    }

    // ldmatrix per-lane offsets (4 ks-steps of K16 per 64-chunk)
    int am = lane >> 3;
    int arow = ((am & 1) << 3) | (lane & 7);
    int akc = am >> 1;
    uint32_t offA[2][4];
    #pragma unroll
    for (int mt = 0; mt < 2; ++mt)
        #pragma unroll
        for (int ks = 0; ks < 4; ++ks)
            offA[mt][ks] = (uint32_t)((mw + mt*16 + arow) * ROWB + (ks*2 + akc) * 16);
    int brow = ((am >> 1) << 3) | (lane & 7);
    int bkc = am & 1;
    uint32_t offB[4][4];
    #pragma unroll
    for (int jp = 0; jp < 4; ++jp)
        #pragma unroll
        for (int ks = 0; ks < 4; ++ks)
            offB[jp][ks] = (uint32_t)((nw + jp*16 + brow) * ROWB + (ks*2 + bkc) * 16);

    float acc[2][8][4];
    #pragma unroll
    for (int mt = 0; mt < 2; ++mt)
        #pragma unroll
        for (int nt = 0; nt < 8; ++nt)
            #pragma unroll
            for (int i = 0; i < 4; ++i) acc[mt][nt][i] = 0.f;

    int NC = K >> 6;

    #pragma unroll
    for (int s = 0; s < 2; ++s) {
        uint32_t nb = sb + (uint32_t)s * BUFB;
        const int ko = s * 64;
        #pragma unroll
        for (int j = 0; j < 4; ++j) {
            cpa16(nb + dstA[j], srcA[j] + ko);
            cpa16(nb + dstW[j], srcW[j] + ko);
        }
        cp_commit();
    }

    int slot = 0, pslot = 2;
    for (int c = 0; c < NC; ++c) {
        cp_wait<1>();
        __syncthreads();

        if (c + 2 < NC) {
            uint32_t nb = sb + (uint32_t)pslot * BUFB;
            const int ko = (c + 2) * 64;
            #pragma unroll
            for (int j = 0; j < 4; ++j) {
                cpa16(nb + dstA[j], srcA[j] + ko);
                cpa16(nb + dstW[j], srcW[j] + ko);
            }
        }
        cp_commit();

        uint32_t cb = sb + (uint32_t)slot * BUFB;
        #pragma unroll
        for (int ks = 0; ks < 4; ++ks) {
            uint32_t ah[2][4], w[4][4];
            ldm4(cb + offA[0][ks], ah[0]);
            ldm4(cb + offA[1][ks], ah[1]);
            #pragma unroll
            for (int jp = 0; jp < 4; ++jp)
                ldm4(cb + TILEB + offB[jp][ks], w[jp]);
            #pragma unroll
            for (int mt = 0; mt < 2; ++mt)
                #pragma unroll
                for (int nt = 0; nt < 8; ++nt) {
                    const uint32_t* bw = &w[nt >> 1][(nt & 1) * 2];
                    mma_hf(acc[mt][nt], ah[mt], bw);
                }
        }
        slot  = (slot  == NSTG-1) ? 0 : slot  + 1;
        pslot = (pslot == NSTG-1) ? 0 : pslot + 1;
    }

    #pragma unroll
    for (int mt = 0; mt < 2; ++mt)
        #pragma unroll
        for (int nt = 0; nt < 8; ++nt) {
            float* a = acc[mt][nt];
            int col = n0 + nw + nt * 8 + (lane & 3) * 2;
            int r0  = m0 + mw + mt * 16 + (lane >> 2);
            float2 bv = *(const float2*)(bias + col);
            float x0 = a[0] + bv.x, y0 = a[1] + bv.y;
            float x1 = a[2] + bv.x, y1 = a[3] + bv.y;
            if (RELU) {
                x0 = fmaxf(x0, 0.f); y0 = fmaxf(y0, 0.f);
                x1 = fmaxf(x1, 0.f); y1 = fmaxf(y1, 0.f);
            }
            if (MIXOUT) {
                float e0 = g_eff[r0], e1 = g_eff[r0 + 8];
                float2 xa = *(const float2*)(Xin + (size_t)r0 * N + col);
                float2 xb = *(const float2*)(Xin + (size_t)(r0 + 8) * N + col);
                x0 = (1.f - e0) * xa.x + e0 * x0;
                y0 = (1.f - e0) * xa.y + e0 * y0;
                x1 = (1.f - e1) * xb.x + e1 * x1;
                y1 = (1.f - e1) * xb.y + e1 * y1;
                *(uint32_t*)(Ch + (size_t)r0 * N + col) =
                    pk2h(__float2half_rn(x0), __float2half_rn(y0));
                *(uint32_t*)(Ch + (size_t)(r0 + 8) * N + col) =
                    pk2h(__float2half_rn(x1), __float2half_rn(y1));
            } else if (SPLITOUT) {
                *(uint32_t*)(Ch + (size_t)r0 * N + col) =
                    pk2h(__float2half_rn(x0), __float2half_rn(y0));
                *(uint32_t*)(Ch + (size_t)(r0 + 8) * N + col) =
                    pk2h(__float2half_rn(x1), __float2half_rn(y1));
            } else {
                float2 v0 = {x0, y0}, v1 = {x1, y1};
                *(float2*)(C + (size_t)r0 * N + col) = v0;
                *(float2*)(C + (size_t)(r0 + 8) * N + col) = v1;
            }
        }
}

// ---------------- mask + compaction (1 warp per batch) ---------------------------
__global__ void mask_kernel(const int* __restrict__ ids,
                            const int* __restrict__ sotp,
                            const int* __restrict__ eotp)
{
    int b = blockIdx.x;
    int lane = threadIdx.x;
    int sot = *sotp, eot = *eotp;
    const int* row = ids + b * Sn;
    int base = lane * 64;

    unsigned a = 0u, bb = 1u, anyeot = 0u;
    for (int i = 0; i < 64; ++i) {
        int t = row[base + i];
        unsigned iso = (t == sot) ? 1u : 0u;
        unsigned ieo = (t == eot) ? 1u : 0u;
        a = iso | (a & (1u - ieo));
        bb = bb & (1u - ieo);
        anyeot |= ieo;
    }
    unsigned ai = a, bi = bb;
    for (int off = 1; off < 32; off <<= 1) {
        unsigned ap = __shfl_up_sync(0xffffffffu, ai, off);
        unsigned bp = __shfl_up_sync(0xffffffffu, bi, off);
        if (lane >= off) { ai = ai | (ap & bi); bi = bi & bp; }
    }
    unsigned s_in = __shfl_up_sync(0xffffffffu, ai, 1);
    if (lane == 0) s_in = 0u;

    unsigned sfx = anyeot;
    for (int off = 1; off < 32; off <<= 1) {
        unsigned v = __shfl_down_sync(0xffffffffu, sfx, off);
        if (lane + off < 32) sfx |= v;
    }
    unsigned after = __shfl_down_sync(0xffffffffu, sfx, 1);
    if (lane == 31) after = 0u;

    unsigned long long openbits = 0ull;
    unsigned s = s_in;
    for (int i = 0; i < 64; ++i) {
        int t = row[base + i];
        unsigned iso = (t == sot) ? 1u : 0u;
        unsigned ieo = (t == eot) ? 1u : 0u;
        unsigned o = iso | s;
        openbits |= ((unsigned long long)o) << i;
        s = iso | (s & (1u - ieo));
    }
    unsigned long long tbits = 0ull;
    unsigned seen = after;
    for (int i = 63; i >= 0; --i) {
        int t = row[base + i];
        if (t == eot) seen = 1u;
        if (((openbits >> i) & 1ull) && seen) tbits |= (1ull << i);
    }
    int c = __popcll(tbits);
    int pre = c;
    for (int off = 1; off < 32; off <<= 1) {
        int v = __shfl_up_sync(0xffffffffu, pre, off);
        if (lane >= off) pre += v;
    }
    int excl = pre - c;
    int total = __shfl_sync(0xffffffffu, pre, 31);
    if (lane == 31) g_tcnt[b] = total;
    int o = excl;
    for (int i = 0; i < 64; ++i) {
        if ((tbits >> i) & 1ull) g_tidx[b * Sn + (o++)] = base + i;
    }
}

// ---------------- gather thought rows: fp32 + fp16 --------------------------------
__global__ void gather_kernel(const float* __restrict__ x)
{
    int b = blockIdx.y, i = blockIdx.x;
    if (i >= g_tcnt[b]) return;
    int src = b * Sn + g_tidx[b * Sn + i];
    int t = threadIdx.x;
    float4 v = ((const float4*)(x + (size_t)src * Dn))[t];
    size_t rb = (size_t)(b * Sn + i) * Dn;
    ((float4*)(g_Xc + rb))[t] = v;
    ((uint2*)(g_Xc_h + rb))[t] = cvt4h(v);
}

// ---------------- attention over compacted thought rows (per batch) ---------------
__global__ void __launch_bounds__(256) attn_kernel(int b)
{
    int h = blockIdx.y, qt = blockIdx.x;
    int nT = g_tcnt[b];
    if (qt * 32 >= nT) return;

    __shared__ float Ks[128][33];
    __shared__ float Vs[32][128];
    __shared__ float Qs[32][132];

    int tid = threadIdx.x, warp = tid >> 5, lane = tid & 31;
    int qb[4]; bool qv[4];
    #pragma unroll
    for (int qq = 0; qq < 4; ++qq) {
        qb[qq] = qt * 32 + warp + 8 * qq;
        qv[qq] = qb[qq] < nT;
        if (qv[qq]) {
            const float* qr = g_qkv + (size_t)(b*Sn + qb[qq]) * (3*Dn) + h * DHn;
            #pragma unroll
            for (int c = 0; c < 4; ++c) Qs[warp + 8*qq][lane + 32*c] = qr[lane + 32*c];
        }
    }

    float mx[4], ls[4], acc[4][4];
    #pragma unroll
    for (int qq = 0; qq < 4; ++qq) {
        mx[qq] = -1e30f; ls[qq] = 0.f;
        #pragma unroll
        for (int c = 0; c < 4; ++c) acc[qq][c] = 0.f;
    }
    const float scale = 0.088388347648318447f;

    for (int j0 = 0; j0 < nT; j0 += 32) {
        int jn = min(32, nT - j0);
        __syncthreads();
        for (int idx = tid; idx < 32*128; idx += 256) {
            int j = idx >> 7, d = idx & 127;
            float kv = 0.f, vv = 0.f;
            if (j < jn) {
                const float* kr = g_qkv + (size_t)(b*Sn + j0 + j)*(3*Dn) + Dn + h*DHn;
                kv = kr[d];
                vv = kr[Dn + d];
            }
            Ks[d][j] = kv;
            Vs[j][d] = vv;
        }
        __syncthreads();

        float s[4] = {0.f, 0.f, 0.f, 0.f};
#pragma unroll 4
        for (int d = 0; d < 128; ++d) {
            float kv = Ks[d][lane];
            #pragma unroll
            for (int qq = 0; qq < 4; ++qq) s[qq] += Qs[warp + 8*qq][d] * kv;
        }
        float p[4], cr[4];
        #pragma unroll
        for (int qq = 0; qq < 4; ++qq) {
            float sq = s[qq] * scale;
            if (lane >= jn) sq = -1e30f;
            float sm = sq;
            #pragma unroll
            for (int off = 16; off; off >>= 1)
                sm = fmaxf(sm, __shfl_xor_sync(0xffffffffu, sm, off));
            float mn = fmaxf(mx[qq], sm);
            p[qq] = (lane < jn) ? __expf(sq - mn) : 0.f;
            float ps = p[qq];
            #pragma unroll
            for (int off = 16; off; off >>= 1)
                ps += __shfl_xor_sync(0xffffffffu, ps, off);
            cr[qq] = __expf(mx[qq] - mn);
            ls[qq] = ls[qq] * cr[qq] + ps;
            mx[qq] = mn;
        }
        #pragma unroll
        for (int qq = 0; qq < 4; ++qq)
            #pragma unroll
            for (int c = 0; c < 4; ++c) acc[qq][c] *= cr[qq];
        for (int j = 0; j < jn; ++j) {
            float pj[4];
            #pragma unroll
            for (int qq = 0; qq < 4; ++qq)
                pj[qq] = __shfl_sync(0xffffffffu, p[qq], j);
            #pragma unroll
            for (int c = 0; c < 4; ++c) {
                float vv = Vs[j][lane + 32*c];
                #pragma unroll
                for (int qq = 0; qq < 4; ++qq) acc[qq][c] += pj[qq] * vv;
            }
        }
    }
    #pragma unroll
    for (int qq = 0; qq < 4; ++qq) {
        if (qv[qq]) {
            float inv = 1.f / ls[qq];
            size_t rb = (size_t)(b*Sn + qb[qq]) * Dn + h * DHn;
            #pragma unroll
            for (int c = 0; c < 4; ++c)
                g_ctx_h[rb + lane + 32*c] = __float2half_rn(acc[qq][c] * inv);
        }
    }
}

// ---------------- block reduction helper ------------------------------------------
__device__ __forceinline__ float block_sum256(float v, float* red)
{
    int lane = threadIdx.x & 31, warp = threadIdx.x >> 5;
#pragma unroll
    for (int off = 16; off; off >>= 1) v += __shfl_xor_sync(0xffffffffu, v, off);
    if (lane == 0) red[warp] = v;
    __syncthreads();
    if (warp == 0) {
        float t = (lane < 8) ? red[lane] : 0.f;
#pragma unroll
        for (int off = 4; off; off >>= 1) t += __shfl_xor_sync(0xffffffffu, t, off);
        if (lane == 0) red[0] = t;
    }
    __syncthreads();
    float r = red[0];
    __syncthreads();
    return r;
}

// ---------------- fused residual-add + LayerNorm (per-batch via roff) -------------
__global__ void __launch_bounds__(256) add_ln_kernel(
    const float* __restrict__ X, const float* __restrict__ Y,
    const float* __restrict__ g, const float* __restrict__ be,
    float* __restrict__ out, __half* __restrict__ oh, int use_cnt, int roff)
{
    int r = blockIdx.x + roff;
    if (use_cnt) { int b = r >> 11; if ((r & 2047) >= g_tcnt[b]) return; }
    __shared__ float red[8];
    int t = threadIdx.x;
    float4 xv = ((const float4*)(X + (size_t)r * Dn))[t];
    float4 yv = ((const float4*)(Y + (size_t)r * Dn))[t];
    float v0 = xv.x + yv.x, v1 = xv.y + yv.y, v2 = xv.z + yv.z, v3 = xv.w + yv.w;
    float mu = block_sum256(v0 + v1 + v2 + v3, red) * (1.0f / Dn);
    float d0 = v0 - mu, d1 = v1 - mu, d2 = v2 - mu, d3 = v3 - mu;
    float var = block_sum256(d0*d0 + d1*d1 + d2*d2 + d3*d3, red) * (1.0f / Dn);
    float inv = rsqrtf(var + 1e-5f);
    float4 gv = ((const float4*)g)[t];
    float4 bv = ((const float4*)be)[t];
    float4 o;
    o.x = d0 * inv * gv.x + bv.x;
    o.y = d1 * inv * gv.y + bv.y;
    o.z = d2 * inv * gv.z + bv.z;
    o.w = d3 * inv * gv.w + bv.w;
    ((float4*)(out + (size_t)r * Dn))[t] = o;
    if (oh) ((uint2*)(oh + (size_t)r * Dn))[t] = cvt4h(o);
}

// ---------------- cat init: cat = [x | x] (fp16), eff = 0.1 ------------------------
__global__ void init_cat_kernel(const float* __restrict__ x)
{
    int r = blockIdx.x, t = threadIdx.x;
    float4 v = ((const float4*)(x + (size_t)r * Dn))[t];
    uint2 h = cvt4h(v);
    uint2* ch = (uint2*)(g_cat_h + (size_t)r * 2 * Dn);
    ch[t] = h; ch[t + 256] = h;
    if (t == 0) g_eff[r] = 0.1f;
}

// ---------------- scatter x2 into cat[:, D:] (fp16) + gate (per batch) ------------
__global__ void __launch_bounds__(256) scatter_kernel(
    const float* __restrict__ Wg, const float* __restrict__ bg, int b)
{
    int i = blockIdx.x;
    if (i >= g_tcnt[b]) return;
    __shared__ float red[8];
    int dst = b * Sn + g_tidx[b * Sn + i];
    int t = threadIdx.x;
    float4 v = ((const float4*)(g_x2 + (size_t)(b*Sn + i) * Dn))[t];
    ((uint2*)(g_cat_h + (size_t)dst * 2 * Dn + Dn))[t] = cvt4h(v);
    float4 w = ((const float4*)Wg)[t];
    float p = v.x*w.x + v.y*w.y + v.z*w.z + v.w*w.w;
    float tot = block_sum256(p, red);
    if (t == 0) g_eff[dst] = 1.f / (1.f + __expf(-(tot + bg[0])));
}

// ---------------- launch ------------------------------------------------------------
#define SYM(p, s) cudaGetSymbolAddress((void**)&p, s)

extern "C" void kernel_launch(void* const* d_in, const int* in_sizes, int n_in,
                              void* d_out, int out_size)
{
    const float* x    = (const float*)d_in[0];
    const int*   ids  = (const int*)d_in[1];
    const int*   sot  = (const int*)d_in[2];
    const int*   eot  = (const int*)d_in[3];
    const float* Wqkv = (const float*)d_in[4];
    const float* bqkv = (const float*)d_in[5];
    const float* Wo   = (const float*)d_in[6];
    const float* bo   = (const float*)d_in[7];
    const float* ln1g = (const float*)d_in[8];
    const float* ln1b = (const float*)d_in[9];
    const float* W1   = (const float*)d_in[10];
    const float* b1   = (const float*)d_in[11];
    const float* W2   = (const float*)d_in[12];
    const float* b2   = (const float*)d_in[13];
    const float* ln2g = (const float*)d_in[14];
    const float* ln2b = (const float*)d_in[15];
    const float* Wg   = (const float*)d_in[16];
    const float* bg   = (const float*)d_in[17];
    const float* Wm   = (const float*)d_in[18];
    const float* bm   = (const float*)d_in[19];
    const float* Wout = (const float*)d_in[20];
    const float* bout = (const float*)d_in[21];
    float* out = (float*)d_out;

    float *pXc, *pqkv, *pattno, *px1, *pff, *px2;
    __half *pXch, *pctxh, *px1h, *phffh, *pcath, *pmixh;
    __half *pWqkvh, *pWoh, *pW1h, *pW2h, *pWmh, *pWouth;
    SYM(pXc, g_Xc); SYM(pqkv, g_qkv); SYM(pattno, g_attno); SYM(px1, g_x1);
    SYM(pff, g_ff); SYM(px2, g_x2);
    SYM(pXch, g_Xc_h); SYM(pctxh, g_ctx_h); SYM(px1h, g_x1_h); SYM(phffh, g_hff_h);
    SYM(pcath, g_cat_h); SYM(pmixh, g_mix_h);
    SYM(pWqkvh, g_Wqkv_h); SYM(pWoh, g_Wo_h); SYM(pW1h, g_W1_h); SYM(pW2h, g_W2_h);
    SYM(pWmh, g_Wm_h); SYM(pWouth, g_Wout_h);

    cudaFuncSetAttribute(gemm_hs<false,false,false>, cudaFuncAttributeMaxDynamicSharedMemorySize, GSMEM);
    cudaFuncSetAttribute(gemm_hs<true,true,false>,   cudaFuncAttributeMaxDynamicSharedMemorySize, GSMEM);
    cudaFuncSetAttribute(gemm_hs<false,false,true>,  cudaFuncAttributeMaxDynamicSharedMemorySize, GSMEM);

    // one-time stream/event setup (host-side objects; no device allocations)
    static cudaStream_t s1 = nullptr;
    static cudaEvent_t evF = nullptr, evW = nullptr, evR = nullptr, evG = nullptr, evD = nullptr;
    if (!s1) {
        cudaStreamCreateWithFlags(&s1, cudaStreamNonBlocking);
        cudaEventCreateWithFlags(&evF, cudaEventDisableTiming);
        cudaEventCreateWithFlags(&evW, cudaEventDisableTiming);
        cudaEventCreateWithFlags(&evR, cudaEventDisableTiming);
        cudaEventCreateWithFlags(&evG, cudaEventDisableTiming);
        cudaEventCreateWithFlags(&evD, cudaEventDisableTiming);
    }

    // per-batch chain helper (mshift=4, moff=16*b)
    auto chain = [&](cudaStream_t st, int b) {
        int mo = 16 * b;
        // QKV (N=3072, K=1024)
        gemm_hs<false,false,false><<<16*24, 256, GSMEM, st>>>(pXch, pWqkvh, bqkv, pqkv, nullptr, nullptr, 3*Dn, Dn, 1, 4, mo);
        // attention
        attn_kernel<<<dim3(Sn/32, NHEADS), 256, 0, st>>>(b);
        // Wo projection
        gemm_hs<false,false,false><<<16*8, 256, GSMEM, st>>>(pctxh, pWoh, bo, pattno, nullptr, nullptr, Dn, Dn, 1, 4, mo);
        // LN1
        add_ln_kernel<<<Sn, 256, 0, st>>>(pXc, pattno, ln1g, ln1b, px1, px1h, 1, b*Sn);
        // FFN up + relu
        gemm_hs<true,true,false><<<16*32, 256, GSMEM, st>>>(px1h, pW1h, b1, nullptr, phffh, nullptr, DFFn, Dn, 1, 4, mo);
        // FFN down
        gemm_hs<false,false,false><<<16*8, 256, GSMEM, st>>>(phffh, pW2h, b2, pff, nullptr, nullptr, Dn, DFFn, 1, 4, mo);
        // LN2
        add_ln_kernel<<<Sn, 256, 0, st>>>(px1, pff, ln2g, ln2b, px2, nullptr, 1, b*Sn);
        // scatter + gate
        scatter_kernel<<<Sn, 256, 0, st>>>(Wg, bg, b);
        // mixed = (1-eff)*x + eff*(cat @ Wm^T + bm)
        gemm_hs<false,false,true><<<16*8, 256, GSMEM, st>>>(pcath, pWmh, bm, nullptr, pmixh, x, Dn, 2*Dn, 0, 4, mo);
        // logits for this batch's rows
        gemm_hs<false,false,false><<<16*250, 256, GSMEM, st>>>(pmixh, pWouth, bout, out, nullptr, nullptr, Vn, Dn, 0, 4, mo);
    };

    // ---- fork: convs + init_cat on s1 ----
    cudaEventRecord(evF, 0);
    cudaStreamWaitEvent(s1, evF, 0);
    conv_kernel<<<512, 256, 0, s1>>>((const float4*)Wqkv, (uint2*)pWqkvh, 3*Dn*Dn/4);
    cudaEventRecord(evW, s1);   // batch0 QKV depends only on this conv
    conv_kernel<<<256, 256, 0, s1>>>((const float4*)Wo,   (uint2*)pWoh,   Dn*Dn/4);
    conv_kernel<<<512, 256, 0, s1>>>((const float4*)W1,   (uint2*)pW1h,   DFFn*Dn/4);
    conv_kernel<<<512, 256, 0, s1>>>((const float4*)W2,   (uint2*)pW2h,   Dn*DFFn/4);
    conv_kernel<<<512, 256, 0, s1>>>((const float4*)Wm,   (uint2*)pWmh,   Dn*2*Dn/4);
    conv_kernel<<<2048, 256, 0, s1>>>((const float4*)Wout,(uint2*)pWouth, Vn*Dn/4);
    init_cat_kernel<<<Rn, 256, 0, s1>>>(x);
    cudaEventRecord(evR, s1);   // all weights + init_cat ready

    // ---- stream 0: mask + gather, then batch-0 chain ----
    mask_kernel<<<Bn, 32>>>(ids, sot, eot);
    gather_kernel<<<dim3(Sn, Bn), 256>>>(x);
    cudaEventRecord(evG, 0);

    // ---- s1: batch-1 chain (after its own convs + gather) ----
    cudaStreamWaitEvent(s1, evG, 0);
    chain(s1, 1);
    cudaEventRecord(evD, s1);

    // ---- stream 0: batch-0 chain ----
    cudaStreamWaitEvent(0, evW, 0);   // Wqkv converted
    // note: Wo/W1/W2/Wm/Wout + init_cat needed later in chain; join evR first
    cudaStreamWaitEvent(0, evR, 0);
    chain(0, 0);
    cudaStreamWaitEvent(0, evD, 0);   // join batch-1 chain

    (void)in_sizes; (void)n_in; (void)out_size;
}